// round 1
// baseline (speedup 1.0000x reference)
#include <cuda_runtime.h>
#include <math.h>

#define TOKENS   2048
#define DMODEL   1024
#define HIDDEN   2048
#define NEXP     8
#define VOCABSZ  32000
#define NASSIGN  (TOKENS * 2)
#define LN_EPS   1e-5f

// ---------------- scratch (device globals; no allocation allowed) ----------
__device__ float g_h  [TOKENS  * DMODEL];   // gathered embeddings
__device__ float g_xn [TOKENS  * DMODEL];   // layernorm output
__device__ float g_a  [NASSIGN * HIDDEN];   // expert hidden activations (per slot)
__device__ float g_y  [NASSIGN * DMODEL];   // expert outputs (per slot)
__device__ float g_w  [NASSIGN];            // gate weights per (token,k)
__device__ int   g_eidx[NASSIGN];           // expert index per (token,k)
__device__ int   g_slot[NASSIGN];           // slot per (token,k)
__device__ int   g_tokOfSlot[NASSIGN];      // token per slot
__device__ int   g_cnt[NEXP];
__device__ int   g_off[NEXP + 1];
__device__ int   g_cur[NEXP];

// ---------------- tiny kernels ---------------------------------------------
__global__ void reset_kernel() {
    int i = threadIdx.x;
    if (i < NEXP) g_cnt[i] = 0;
}

// one block per token: gather embedding row, compute gate logits, softmax,
// top-2, histogram counts.
__global__ void gather_gate_kernel(const int* __restrict__ x,
                                   const float* __restrict__ embed,
                                   const float* __restrict__ Wg,
                                   const float* __restrict__ bg) {
    int t   = blockIdx.x;
    int tid = threadIdx.x;
    int row = x[t];

    const float4* src = (const float4*)(embed + (size_t)row * DMODEL);
    float4 v = src[tid];                       // 256 thr * 4 = 1024 floats
    ((float4*)(g_h + (size_t)t * DMODEL))[tid] = v;

    float p[NEXP];
#pragma unroll
    for (int e = 0; e < NEXP; e++) p[e] = 0.f;
    float hv[4] = {v.x, v.y, v.z, v.w};
    int d0 = tid * 4;
#pragma unroll
    for (int j = 0; j < 4; j++) {
        const float* wgr = Wg + (size_t)(d0 + j) * NEXP;
#pragma unroll
        for (int e = 0; e < NEXP; e++) p[e] += hv[j] * wgr[e];
    }
#pragma unroll
    for (int e = 0; e < NEXP; e++)
        for (int o = 16; o > 0; o >>= 1)
            p[e] += __shfl_xor_sync(0xffffffffu, p[e], o);

    __shared__ float red[8][NEXP];
    int warp = tid >> 5, lane = tid & 31;
    if (lane == 0)
#pragma unroll
        for (int e = 0; e < NEXP; e++) red[warp][e] = p[e];
    __syncthreads();

    if (tid == 0) {
        float g[NEXP];
#pragma unroll
        for (int e = 0; e < NEXP; e++) {
            g[e] = bg[e];
#pragma unroll
            for (int w = 0; w < 8; w++) g[e] += red[w][e];
        }
        float mx = g[0];
#pragma unroll
        for (int e = 1; e < NEXP; e++) mx = fmaxf(mx, g[e]);
        float s = 0.f, pr[NEXP];
#pragma unroll
        for (int e = 0; e < NEXP; e++) { pr[e] = expf(g[e] - mx); s += pr[e]; }
        float inv = 1.f / s;
#pragma unroll
        for (int e = 0; e < NEXP; e++) pr[e] *= inv;

        int i0 = 0;
#pragma unroll
        for (int e = 1; e < NEXP; e++) if (pr[e] > pr[i0]) i0 = e;
        int i1 = (i0 == 0) ? 1 : 0;
#pragma unroll
        for (int e = 0; e < NEXP; e++)
            if (e != i0 && pr[e] > pr[i1]) i1 = e;

        g_w[2 * t]     = pr[i0];  g_eidx[2 * t]     = i0;
        g_w[2 * t + 1] = pr[i1];  g_eidx[2 * t + 1] = i1;
        atomicAdd(&g_cnt[i0], 1);
        atomicAdd(&g_cnt[i1], 1);
    }
}

__global__ void scan_kernel() {
    g_off[0] = 0;
    for (int e = 0; e < NEXP; e++) {
        g_off[e + 1] = g_off[e] + g_cnt[e];
        g_cur[e] = 0;
    }
}

__global__ void assign_kernel() {
    int t = blockIdx.x * blockDim.x + threadIdx.x;
    if (t >= TOKENS) return;
#pragma unroll
    for (int k = 0; k < 2; k++) {
        int e = g_eidx[2 * t + k];
        int pos = atomicAdd(&g_cur[e], 1);   // order nondet, result order-free
        int slot = g_off[e] + pos;
        g_slot[2 * t + k] = slot;
        g_tokOfSlot[slot] = t;
    }
}

// combine top-2 expert outputs + LayerNorm, one block per token
__global__ void combine_ln_kernel(const float* __restrict__ gamma,
                                  const float* __restrict__ beta) {
    int t = blockIdx.x, tid = threadIdx.x;
    int s0 = g_slot[2 * t], s1 = g_slot[2 * t + 1];
    float w0 = g_w[2 * t], w1 = g_w[2 * t + 1];

    float4 a = ((const float4*)(g_y + (size_t)s0 * DMODEL))[tid];
    float4 b = ((const float4*)(g_y + (size_t)s1 * DMODEL))[tid];
    float4 c;
    c.x = w0 * a.x + w1 * b.x;  c.y = w0 * a.y + w1 * b.y;
    c.z = w0 * a.z + w1 * b.z;  c.w = w0 * a.w + w1 * b.w;

    float sum = c.x + c.y + c.z + c.w;
    float ssq = c.x*c.x + c.y*c.y + c.z*c.z + c.w*c.w;
    for (int o = 16; o > 0; o >>= 1) {
        sum += __shfl_xor_sync(0xffffffffu, sum, o);
        ssq += __shfl_xor_sync(0xffffffffu, ssq, o);
    }
    __shared__ float rs[8], rq[8];
    __shared__ float s_mu, s_rstd;
    int warp = tid >> 5, lane = tid & 31;
    if (lane == 0) { rs[warp] = sum; rq[warp] = ssq; }
    __syncthreads();
    if (tid == 0) {
        float S = 0.f, Q = 0.f;
#pragma unroll
        for (int w = 0; w < 8; w++) { S += rs[w]; Q += rq[w]; }
        float mu = S / (float)DMODEL;
        float var = Q / (float)DMODEL - mu * mu;
        s_mu = mu;
        s_rstd = rsqrtf(var + LN_EPS);
    }
    __syncthreads();
    float mu = s_mu, rstd = s_rstd;
    float4 g4 = ((const float4*)gamma)[tid];
    float4 b4 = ((const float4*)beta)[tid];
    float4 o;
    o.x = (c.x - mu) * rstd * g4.x + b4.x;
    o.y = (c.y - mu) * rstd * g4.y + b4.y;
    o.z = (c.z - mu) * rstd * g4.z + b4.z;
    o.w = (c.w - mu) * rstd * g4.w + b4.w;
    ((float4*)(g_xn + (size_t)t * DMODEL))[tid] = o;
}

// ---------------- 128x128x8 fp32 SGEMM, 256 thr, 8x8 per thread ------------
// A: [M,K] row-major (rows optionally gathered via g_tokOfSlot)
// B: [K,N] row-major;  C: [M,N] row-major;  bias per column; optional ReLU.
// GROUPED: blockIdx.z = expert; rows = g_off[e]..g_off[e+1]
template <int K, int N, bool GROUPED, bool GATHER, bool RELU>
__global__ void sgemm128(const float* __restrict__ A,
                         const float* __restrict__ Ball,
                         const float* __restrict__ biasAll,
                         float* __restrict__ C,
                         int Mtotal) {
    __shared__ float As[8][128];
    __shared__ float Bs[8][128];

    int e = GROUPED ? blockIdx.z : 0;
    int rowOff = GROUPED ? g_off[e] : 0;
    int cnt = GROUPED ? (g_off[e + 1] - rowOff) : Mtotal;
    int rowBlock = blockIdx.y * 128;
    if (rowBlock >= cnt) return;
    int colBlock = blockIdx.x * 128;

    const float* B = Ball + (GROUPED ? (size_t)e * K * N : (size_t)0);
    const float* bias = biasAll + (GROUPED ? (size_t)e * N : (size_t)0);

    int tid = threadIdx.x;
    // A-tile loader mapping
    int lr = tid >> 1;                 // 0..127
    int kq = (tid & 1) * 4;            // 0 or 4
    bool avalid = (rowBlock + lr) < cnt;
    const float* arow;
    if (GATHER) {
        int tok = avalid ? g_tokOfSlot[rowOff + rowBlock + lr] : 0;
        arow = A + (size_t)tok * K;
    } else {
        arow = A + (size_t)(rowOff + rowBlock + (avalid ? lr : 0)) * K;
    }
    // B-tile loader mapping
    int bkr = tid >> 5;                // 0..7
    int bn = (tid & 31) * 4;           // 0..124
    const float* bptr = B + (size_t)bkr * N + colBlock + bn;

    float acc[8][8];
#pragma unroll
    for (int i = 0; i < 8; i++)
#pragma unroll
        for (int j = 0; j < 8; j++) acc[i][j] = 0.f;

    int ty = tid >> 4, tx = tid & 15;

    for (int kt = 0; kt < K; kt += 8) {
        float4 va = avalid ? *(const float4*)(arow + kt + kq)
                           : make_float4(0.f, 0.f, 0.f, 0.f);
        As[kq + 0][lr] = va.x;
        As[kq + 1][lr] = va.y;
        As[kq + 2][lr] = va.z;
        As[kq + 3][lr] = va.w;
        float4 vb = *(const float4*)(bptr + (size_t)kt * N);
        *(float4*)&Bs[bkr][bn] = vb;
        __syncthreads();
#pragma unroll
        for (int kk = 0; kk < 8; kk++) {
            float4 a0 = *(const float4*)&As[kk][ty * 8];
            float4 a1 = *(const float4*)&As[kk][ty * 8 + 4];
            float4 b0 = *(const float4*)&Bs[kk][tx * 8];
            float4 b1 = *(const float4*)&Bs[kk][tx * 8 + 4];
            float av[8] = {a0.x, a0.y, a0.z, a0.w, a1.x, a1.y, a1.z, a1.w};
            float bv[8] = {b0.x, b0.y, b0.z, b0.w, b1.x, b1.y, b1.z, b1.w};
#pragma unroll
            for (int i = 0; i < 8; i++)
#pragma unroll
                for (int j = 0; j < 8; j++)
                    acc[i][j] += av[i] * bv[j];
        }
        __syncthreads();
    }

    float bb[8];
#pragma unroll
    for (int j = 0; j < 8; j++) bb[j] = bias[colBlock + tx * 8 + j];

#pragma unroll
    for (int i = 0; i < 8; i++) {
        int r = rowBlock + ty * 8 + i;
        if (r < cnt) {
            float* crow = C + (size_t)(rowOff + r) * N + colBlock + tx * 8;
            float v[8];
#pragma unroll
            for (int j = 0; j < 8; j++) {
                float t = acc[i][j] + bb[j];
                v[j] = RELU ? fmaxf(t, 0.f) : t;
            }
            *(float4*)(crow)     = make_float4(v[0], v[1], v[2], v[3]);
            *(float4*)(crow + 4) = make_float4(v[4], v[5], v[6], v[7]);
        }
    }
}

// ---------------- launch ----------------------------------------------------
extern "C" void kernel_launch(void* const* d_in, const int* in_sizes, int n_in,
                              void* d_out, int out_size) {
    const int*   x     = (const int*)  d_in[0];
    const float* embed = (const float*)d_in[1];
    const float* Wg    = (const float*)d_in[2];
    const float* bg    = (const float*)d_in[3];
    const float* W1    = (const float*)d_in[4];
    const float* b1    = (const float*)d_in[5];
    const float* W2    = (const float*)d_in[6];
    const float* b2    = (const float*)d_in[7];
    const float* gamma = (const float*)d_in[8];
    const float* beta  = (const float*)d_in[9];
    const float* Wh    = (const float*)d_in[10];
    const float* bh    = (const float*)d_in[11];
    float* out = (float*)d_out;

    float *p_h, *p_a, *p_y, *p_xn;
    cudaGetSymbolAddress((void**)&p_h,  g_h);
    cudaGetSymbolAddress((void**)&p_a,  g_a);
    cudaGetSymbolAddress((void**)&p_y,  g_y);
    cudaGetSymbolAddress((void**)&p_xn, g_xn);

    reset_kernel<<<1, 32>>>();
    gather_gate_kernel<<<TOKENS, 256>>>(x, embed, Wg, bg);
    scan_kernel<<<1, 1>>>();
    assign_kernel<<<(TOKENS + 255) / 256, 256>>>();

    // FFN layer 1: per-expert [cnt,1024] x [1024,2048], relu, A gathered
    sgemm128<DMODEL, HIDDEN, true, true, true>
        <<<dim3(HIDDEN / 128, 16, NEXP), 256>>>(p_h, W1, b1, p_a, 0);
    // FFN layer 2: per-expert [cnt,2048] x [2048,1024]
    sgemm128<HIDDEN, DMODEL, true, false, false>
        <<<dim3(DMODEL / 128, 16, NEXP), 256>>>(p_a, W2, b2, p_y, 0);

    combine_ln_kernel<<<TOKENS, 256>>>(gamma, beta);

    // Head: [2048,1024] x [1024,32000]
    sgemm128<DMODEL, VOCABSZ, false, false, false>
        <<<dim3(VOCABSZ / 128, TOKENS / 128, 1), 256>>>(p_xn, Wh, bh, out, TOKENS);
}

// round 3
// speedup vs baseline: 2.5237x; 2.5237x over previous
#include <cuda_runtime.h>
#include <cstdint>
#include <math.h>

#define TOKENS   2048
#define DMODEL   1024
#define HIDDEN   2048
#define NEXP     8
#define VOCABSZ  32000
#define NASSIGN  (TOKENS * 2)
#define LN_EPS   1e-5f

#define MT 128
#define NT 256
#define KCH 32

// ---------------- scratch (device globals; no allocation allowed) ----------
__device__ float g_h  [TOKENS  * DMODEL];
__device__ float g_xn [TOKENS  * DMODEL];
__device__ float g_a  [NASSIGN * HIDDEN];
__device__ float g_y  [NASSIGN * DMODEL];
__device__ float g_w  [NASSIGN];
__device__ int   g_eidx[NASSIGN];
__device__ int   g_slot[NASSIGN];
__device__ int   g_tokOfSlot[NASSIGN];
__device__ int   g_cnt[NEXP];
__device__ int   g_off[NEXP + 1];
__device__ int   g_cur[NEXP];

// ---------------- helpers ----------------------------------------------------
__device__ __forceinline__ uint32_t f2tf(float x) {
    uint32_t r;
    asm("cvt.rna.tf32.f32 %0, %1;" : "=r"(r) : "f"(x));
    return r;
}

__device__ __forceinline__ void mma_tf32(float c[4], const uint32_t a[4],
                                         const uint32_t b[2]) {
    asm volatile(
        "mma.sync.aligned.m16n8k8.row.col.f32.tf32.tf32.f32 "
        "{%0,%1,%2,%3}, {%4,%5,%6,%7}, {%8,%9}, {%0,%1,%2,%3};"
        : "+f"(c[0]), "+f"(c[1]), "+f"(c[2]), "+f"(c[3])
        : "r"(a[0]), "r"(a[1]), "r"(a[2]), "r"(a[3]), "r"(b[0]), "r"(b[1]));
}

// ---------------- tiny kernels ---------------------------------------------
__global__ void reset_kernel() {
    int i = threadIdx.x;
    if (i < NEXP) g_cnt[i] = 0;
}

__global__ void gather_gate_kernel(const int* __restrict__ x,
                                   const float* __restrict__ embed,
                                   const float* __restrict__ Wg,
                                   const float* __restrict__ bg) {
    int t   = blockIdx.x;
    int tid = threadIdx.x;
    int row = x[t];

    const float4* src = (const float4*)(embed + (size_t)row * DMODEL);
    float4 v = src[tid];
    ((float4*)(g_h + (size_t)t * DMODEL))[tid] = v;

    float p[NEXP];
#pragma unroll
    for (int e = 0; e < NEXP; e++) p[e] = 0.f;
    float hv[4] = {v.x, v.y, v.z, v.w};
    int d0 = tid * 4;
#pragma unroll
    for (int j = 0; j < 4; j++) {
        const float* wgr = Wg + (size_t)(d0 + j) * NEXP;
#pragma unroll
        for (int e = 0; e < NEXP; e++) p[e] += hv[j] * wgr[e];
    }
#pragma unroll
    for (int e = 0; e < NEXP; e++)
        for (int o = 16; o > 0; o >>= 1)
            p[e] += __shfl_xor_sync(0xffffffffu, p[e], o);

    __shared__ float red[8][NEXP];
    int warp = tid >> 5, lane = tid & 31;
    if (lane == 0)
#pragma unroll
        for (int e = 0; e < NEXP; e++) red[warp][e] = p[e];
    __syncthreads();

    if (tid == 0) {
        float g[NEXP];
#pragma unroll
        for (int e = 0; e < NEXP; e++) {
            g[e] = bg[e];
#pragma unroll
            for (int w = 0; w < 8; w++) g[e] += red[w][e];
        }
        float mx = g[0];
#pragma unroll
        for (int e = 1; e < NEXP; e++) mx = fmaxf(mx, g[e]);
        float s = 0.f, pr[NEXP];
#pragma unroll
        for (int e = 0; e < NEXP; e++) { pr[e] = expf(g[e] - mx); s += pr[e]; }
        float inv = 1.f / s;
#pragma unroll
        for (int e = 0; e < NEXP; e++) pr[e] *= inv;

        int i0 = 0;
#pragma unroll
        for (int e = 1; e < NEXP; e++) if (pr[e] > pr[i0]) i0 = e;
        int i1 = (i0 == 0) ? 1 : 0;
#pragma unroll
        for (int e = 0; e < NEXP; e++)
            if (e != i0 && pr[e] > pr[i1]) i1 = e;

        g_w[2 * t]     = pr[i0];  g_eidx[2 * t]     = i0;
        g_w[2 * t + 1] = pr[i1];  g_eidx[2 * t + 1] = i1;
        atomicAdd(&g_cnt[i0], 1);
        atomicAdd(&g_cnt[i1], 1);
    }
}

__global__ void scan_kernel() {
    g_off[0] = 0;
    for (int e = 0; e < NEXP; e++) {
        g_off[e + 1] = g_off[e] + g_cnt[e];
        g_cur[e] = 0;
    }
}

__global__ void assign_kernel() {
    int t = blockIdx.x * blockDim.x + threadIdx.x;
    if (t >= TOKENS) return;
#pragma unroll
    for (int k = 0; k < 2; k++) {
        int e = g_eidx[2 * t + k];
        int pos = atomicAdd(&g_cur[e], 1);
        int slot = g_off[e] + pos;
        g_slot[2 * t + k] = slot;
        g_tokOfSlot[slot] = t;
    }
}

__global__ void combine_ln_kernel(const float* __restrict__ gamma,
                                  const float* __restrict__ beta) {
    int t = blockIdx.x, tid = threadIdx.x;
    int s0 = g_slot[2 * t], s1 = g_slot[2 * t + 1];
    float w0 = g_w[2 * t], w1 = g_w[2 * t + 1];

    float4 a = ((const float4*)(g_y + (size_t)s0 * DMODEL))[tid];
    float4 b = ((const float4*)(g_y + (size_t)s1 * DMODEL))[tid];
    float4 c;
    c.x = w0 * a.x + w1 * b.x;  c.y = w0 * a.y + w1 * b.y;
    c.z = w0 * a.z + w1 * b.z;  c.w = w0 * a.w + w1 * b.w;

    float sum = c.x + c.y + c.z + c.w;
    float ssq = c.x*c.x + c.y*c.y + c.z*c.z + c.w*c.w;
    for (int o = 16; o > 0; o >>= 1) {
        sum += __shfl_xor_sync(0xffffffffu, sum, o);
        ssq += __shfl_xor_sync(0xffffffffu, ssq, o);
    }
    __shared__ float rs[8], rq[8];
    __shared__ float s_mu, s_rstd;
    int warp = tid >> 5, lane = tid & 31;
    if (lane == 0) { rs[warp] = sum; rq[warp] = ssq; }
    __syncthreads();
    if (tid == 0) {
        float S = 0.f, Q = 0.f;
#pragma unroll
        for (int w = 0; w < 8; w++) { S += rs[w]; Q += rq[w]; }
        float mu = S / (float)DMODEL;
        float var = Q / (float)DMODEL - mu * mu;
        s_mu = mu;
        s_rstd = rsqrtf(var + LN_EPS);
    }
    __syncthreads();
    float mu = s_mu, rstd = s_rstd;
    float4 g4 = ((const float4*)gamma)[tid];
    float4 b4 = ((const float4*)beta)[tid];
    float4 o;
    o.x = (c.x - mu) * rstd * g4.x + b4.x;
    o.y = (c.y - mu) * rstd * g4.y + b4.y;
    o.z = (c.z - mu) * rstd * g4.z + b4.z;
    o.w = (c.w - mu) * rstd * g4.w + b4.w;
    ((float4*)(g_xn + (size_t)t * DMODEL))[tid] = o;
}

// ---------------- tf32 mma.sync GEMM: 128x256 tile, 256 thr, 8 warps --------
// A [M,K] fp32 row-major (optional row gather); B [K,N] fp32 row-major;
// C [M,N] fp32; bias; optional ReLU. tf32 conversion (cvt.rna) at SMEM store.
// SMEM A: [kk(4)][m(128)][k8(8)], k8 swizzled by m:  k' = k ^ (4*((m>>2)&1))
// SMEM B: [k(32)][n(256)], n swizzled by k:          n' = n ^ ((k&3)<<3)
template <int K, int N, bool GROUPED, bool GATHER, bool RELU>
__global__ void __launch_bounds__(256, 1)
tgemm(const float* __restrict__ A, const float* __restrict__ Ball,
      const float* __restrict__ biasAll, float* __restrict__ C, int Mtotal) {
    extern __shared__ float sm[];
    float* Abuf[2] = { sm,        sm + 4096 };
    float* Bbuf[2] = { sm + 8192, sm + 16384 };

    int e = GROUPED ? blockIdx.z : 0;
    int rowOff = GROUPED ? g_off[e] : 0;
    int cnt = GROUPED ? (g_off[e + 1] - rowOff) : Mtotal;
    int mTile = GROUPED ? blockIdx.y : blockIdx.x;
    int nTile = GROUPED ? blockIdx.x : blockIdx.y;
    int rowBlock = mTile * MT;
    if (rowBlock >= cnt) return;
    int colBlock = nTile * NT;

    const float* B = Ball + (GROUPED ? (size_t)e * K * N : (size_t)0);
    const float* bias = biasAll + (GROUPED ? (size_t)e * N : (size_t)0);

    int tid = threadIdx.x;
    int wid = tid >> 5, lane = tid & 31;
    int wm = wid >> 2, wn = wid & 3;
    int wmOff = wm * 64, wnOff = wn * 64;
    int g = lane >> 2, tg = lane & 3;

    // A loader: row r = tid>>1, k-half = (tid&1)*16
    int r = tid >> 1;
    int khalf = (tid & 1) * 16;
    bool avalid = (rowBlock + r) < cnt;
    const float* arow;
    if (GATHER) {
        int tok = avalid ? g_tokOfSlot[rowOff + rowBlock + r] : 0;
        arow = A + (size_t)tok * K;
    } else {
        arow = A + (size_t)(rowOff + rowBlock + (avalid ? r : 0)) * K;
    }
    // precomputed A sts indices (float offsets)
    int aswz = ((r >> 2) & 1) * 4;
    // B loader base
    const float* bbase = B + colBlock;

    float acc[4][8][4];
#pragma unroll
    for (int i = 0; i < 4; i++)
#pragma unroll
        for (int j = 0; j < 8; j++)
#pragma unroll
            for (int q = 0; q < 4; q++) acc[i][j][q] = 0.f;

    float4 va[4];
    float4 vb[8];

    auto ldg_chunk = [&](int c) {
        const float* ap = arow + c * KCH + khalf;
#pragma unroll
        for (int j = 0; j < 4; j++)
            va[j] = avalid ? *(const float4*)(ap + j * 4)
                           : make_float4(0.f, 0.f, 0.f, 0.f);
#pragma unroll
        for (int i = 0; i < 8; i++) {
            int pos = i * 256 + tid;          // float4 units within 32x256
            int kq = pos >> 6;
            int n4 = (pos & 63) * 4;
            vb[i] = *(const float4*)(bbase + (size_t)(c * KCH + kq) * N + n4);
        }
    };
    auto sts_chunk = [&](int s) {
        float* As = Abuf[s];
        float* Bs = Bbuf[s];
#pragma unroll
        for (int j = 0; j < 4; j++) {
            int k_in = khalf + j * 4;
            int idx = (k_in >> 3) * 1024 + r * 8 + ((k_in & 7) ^ aswz);
            uint4 t;
            t.x = f2tf(va[j].x); t.y = f2tf(va[j].y);
            t.z = f2tf(va[j].z); t.w = f2tf(va[j].w);
            *(uint4*)(As + idx) = t;
        }
#pragma unroll
        for (int i = 0; i < 8; i++) {
            int pos = i * 256 + tid;
            int kq = pos >> 6;
            int n = (pos & 63) * 4;
            int idx = kq * 256 + (n ^ ((kq & 3) << 3));
            uint4 t;
            t.x = f2tf(vb[i].x); t.y = f2tf(vb[i].y);
            t.z = f2tf(vb[i].z); t.w = f2tf(vb[i].w);
            *(uint4*)(Bs + idx) = t;
        }
    };
    auto mma_chunk = [&](int s) {
        const uint32_t* As = (const uint32_t*)Abuf[s];
        const uint32_t* Bs = (const uint32_t*)Bbuf[s];
#pragma unroll
        for (int ks = 0; ks < 4; ks++) {
            const uint32_t* aB = As + ks * 1024;
            const uint32_t* bB = Bs + ks * 8 * 256;
            uint32_t af[4][4];
#pragma unroll
            for (int mb = 0; mb < 4; mb++) {
                int m = wmOff + mb * 16 + g;
                int swz = ((m >> 2) & 1) * 4;
                int base = m * 8;
                af[mb][0] = aB[base + (tg ^ swz)];
                af[mb][1] = aB[base + 64 + (tg ^ swz)];
                af[mb][2] = aB[base + ((tg + 4) ^ swz)];
                af[mb][3] = aB[base + 64 + ((tg + 4) ^ swz)];
            }
            uint32_t bf[8][2];
#pragma unroll
            for (int nb = 0; nb < 8; nb++) {
                int n = wnOff + nb * 8 + g;
                int nsw = n ^ (tg << 3);
                bf[nb][0] = bB[tg * 256 + nsw];
                bf[nb][1] = bB[(tg + 4) * 256 + nsw];
            }
#pragma unroll
            for (int mb = 0; mb < 4; mb++)
#pragma unroll
                for (int nb = 0; nb < 8; nb++)
                    mma_tf32(acc[mb][nb], af[mb], bf[nb]);
        }
    };

    const int NCH = K / KCH;
    ldg_chunk(0);
    sts_chunk(0);
    __syncthreads();
    for (int c = 0; c < NCH; c++) {
        int s = c & 1;
        if (c + 1 < NCH) ldg_chunk(c + 1);
        mma_chunk(s);
        __syncthreads();
        if (c + 1 < NCH) {
            sts_chunk(s ^ 1);
            __syncthreads();
        }
    }

    // epilogue
#pragma unroll
    for (int nb = 0; nb < 8; nb++) {
        int col = colBlock + wnOff + nb * 8 + 2 * tg;
        float2 bv = *(const float2*)(bias + col);
#pragma unroll
        for (int mb = 0; mb < 4; mb++) {
            int mr = wmOff + mb * 16 + g;
            if (rowBlock + mr < cnt) {
                float2 o;
                o.x = acc[mb][nb][0] + bv.x;
                o.y = acc[mb][nb][1] + bv.y;
                if (RELU) { o.x = fmaxf(o.x, 0.f); o.y = fmaxf(o.y, 0.f); }
                *(float2*)(C + (size_t)(rowOff + rowBlock + mr) * N + col) = o;
            }
            if (rowBlock + mr + 8 < cnt) {
                float2 o;
                o.x = acc[mb][nb][2] + bv.x;
                o.y = acc[mb][nb][3] + bv.y;
                if (RELU) { o.x = fmaxf(o.x, 0.f); o.y = fmaxf(o.y, 0.f); }
                *(float2*)(C + (size_t)(rowOff + rowBlock + mr + 8) * N + col) = o;
            }
        }
    }
}

// ---------------- launch ----------------------------------------------------
static const int SMEM_SZ = 24576 * 4;   // 96 KB

extern "C" void kernel_launch(void* const* d_in, const int* in_sizes, int n_in,
                              void* d_out, int out_size) {
    const int*   x     = (const int*)  d_in[0];
    const float* embed = (const float*)d_in[1];
    const float* Wg    = (const float*)d_in[2];
    const float* bg    = (const float*)d_in[3];
    const float* W1    = (const float*)d_in[4];
    const float* b1    = (const float*)d_in[5];
    const float* W2    = (const float*)d_in[6];
    const float* b2    = (const float*)d_in[7];
    const float* gamma = (const float*)d_in[8];
    const float* beta  = (const float*)d_in[9];
    const float* Wh    = (const float*)d_in[10];
    const float* bh    = (const float*)d_in[11];
    float* out = (float*)d_out;

    float *p_h, *p_a, *p_y, *p_xn;
    cudaGetSymbolAddress((void**)&p_h,  g_h);
    cudaGetSymbolAddress((void**)&p_a,  g_a);
    cudaGetSymbolAddress((void**)&p_y,  g_y);
    cudaGetSymbolAddress((void**)&p_xn, g_xn);

    cudaFuncSetAttribute((const void*)tgemm<DMODEL, HIDDEN, true, true, true>,
                         cudaFuncAttributeMaxDynamicSharedMemorySize, SMEM_SZ);
    cudaFuncSetAttribute((const void*)tgemm<HIDDEN, DMODEL, true, false, false>,
                         cudaFuncAttributeMaxDynamicSharedMemorySize, SMEM_SZ);
    cudaFuncSetAttribute((const void*)tgemm<DMODEL, VOCABSZ, false, false, false>,
                         cudaFuncAttributeMaxDynamicSharedMemorySize, SMEM_SZ);

    reset_kernel<<<1, 32>>>();
    gather_gate_kernel<<<TOKENS, 256>>>(x, embed, Wg, bg);
    scan_kernel<<<1, 1>>>();
    assign_kernel<<<(TOKENS + 255) / 256, 256>>>();

    // FFN1: per-expert [cnt,1024] x [1024,2048], ReLU, A row-gathered
    tgemm<DMODEL, HIDDEN, true, true, true>
        <<<dim3(HIDDEN / NT, 16, NEXP), 256, SMEM_SZ>>>(p_h, W1, b1, p_a, 0);
    // FFN2: per-expert [cnt,2048] x [2048,1024]
    tgemm<HIDDEN, DMODEL, true, false, false>
        <<<dim3(DMODEL / NT, 16, NEXP), 256, SMEM_SZ>>>(p_a, W2, b2, p_y, 0);

    combine_ln_kernel<<<TOKENS, 256>>>(gamma, beta);

    // Head: [2048,1024] x [1024,32000]; x = m-tiles so concurrent CTAs share Wh stripes in L2
    tgemm<DMODEL, VOCABSZ, false, false, false>
        <<<dim3(TOKENS / MT, VOCABSZ / NT, 1), 256, SMEM_SZ>>>(p_xn, Wh, bh, out, TOKENS);
}

// round 4
// speedup vs baseline: 3.2624x; 1.2927x over previous
#include <cuda_runtime.h>
#include <cstdint>
#include <math.h>

#define TOKENS   2048
#define DMODEL   1024
#define HIDDEN   2048
#define NEXP     8
#define VOCABSZ  32000
#define NASSIGN  (TOKENS * 2)
#define LN_EPS   1e-5f

#define MT 128
#define NT 256
#define KCH 32
#define STAGES 3

// ---------------- scratch (device globals; no allocation allowed) ----------
__device__ float g_h  [TOKENS  * DMODEL];      // tf32-rounded embeddings
__device__ float g_xn [TOKENS  * DMODEL];      // tf32-rounded LN output
__device__ float g_a  [NASSIGN * HIDDEN];      // tf32-rounded FFN1 act
__device__ float g_y  [NASSIGN * DMODEL];      // FFN2 out (fp32)
__device__ float g_w  [NASSIGN];
__device__ int   g_eidx[NASSIGN];
__device__ int   g_slot[NASSIGN];
__device__ int   g_tokOfSlot[NASSIGN];
__device__ int   g_cnt[NEXP];
__device__ int   g_off[NEXP + 1];
__device__ int   g_cur[NEXP];
// tf32-rounded weight copies
__device__ float g_Whc[VOCABSZ * DMODEL];
__device__ float g_W1c[NEXP * DMODEL * HIDDEN];
__device__ float g_W2c[NEXP * HIDDEN * DMODEL];

// ---------------- helpers ----------------------------------------------------
__device__ __forceinline__ uint32_t f2tf(float x) {
    uint32_t r;
    asm("cvt.rna.tf32.f32 %0, %1;" : "=r"(r) : "f"(x));
    return r;
}
__device__ __forceinline__ float f2tff(float x) {
    return __uint_as_float(f2tf(x));
}
__device__ __forceinline__ uint32_t smem_u32(const void* p) {
    uint32_t a;
    asm("{ .reg .u64 t; cvta.to.shared.u64 t, %1; cvt.u32.u64 %0, t; }"
        : "=r"(a) : "l"(p));
    return a;
}
__device__ __forceinline__ void cp16(uint32_t dst, const void* src, int sz) {
    asm volatile("cp.async.cg.shared.global [%0], [%1], 16, %2;"
                 :: "r"(dst), "l"(src), "r"(sz) : "memory");
}
__device__ __forceinline__ void cp_commit() {
    asm volatile("cp.async.commit_group;" ::: "memory");
}
template <int N>
__device__ __forceinline__ void cp_wait() {
    asm volatile("cp.async.wait_group %0;" :: "n"(N) : "memory");
}
__device__ __forceinline__ void mma_tf32(float c[4], const uint32_t a[4],
                                         const uint32_t b[2]) {
    asm volatile(
        "mma.sync.aligned.m16n8k8.row.col.f32.tf32.tf32.f32 "
        "{%0,%1,%2,%3}, {%4,%5,%6,%7}, {%8,%9}, {%0,%1,%2,%3};"
        : "+f"(c[0]), "+f"(c[1]), "+f"(c[2]), "+f"(c[3])
        : "r"(a[0]), "r"(a[1]), "r"(a[2]), "r"(a[3]), "r"(b[0]), "r"(b[1]));
}

// ---------------- weight tf32 pre-convert -----------------------------------
__global__ void cvt_kernel(const float4* __restrict__ src,
                           float4* __restrict__ dst, int n4) {
    int i = blockIdx.x * blockDim.x + threadIdx.x;
    if (i < n4) {
        float4 v = src[i];
        float4 o;
        o.x = f2tff(v.x); o.y = f2tff(v.y);
        o.z = f2tff(v.z); o.w = f2tff(v.w);
        dst[i] = o;
    }
}

// ---------------- tiny kernels ---------------------------------------------
__global__ void reset_kernel() {
    int i = threadIdx.x;
    if (i < NEXP) g_cnt[i] = 0;
}

__global__ void gather_gate_kernel(const int* __restrict__ x,
                                   const float* __restrict__ embed,
                                   const float* __restrict__ Wg,
                                   const float* __restrict__ bg) {
    int t   = blockIdx.x;
    int tid = threadIdx.x;
    int row = x[t];

    const float4* src = (const float4*)(embed + (size_t)row * DMODEL);
    float4 v = src[tid];
    float4 vr;
    vr.x = f2tff(v.x); vr.y = f2tff(v.y); vr.z = f2tff(v.z); vr.w = f2tff(v.w);
    ((float4*)(g_h + (size_t)t * DMODEL))[tid] = vr;

    float p[NEXP];
#pragma unroll
    for (int e = 0; e < NEXP; e++) p[e] = 0.f;
    float hv[4] = {v.x, v.y, v.z, v.w};
    int d0 = tid * 4;
#pragma unroll
    for (int j = 0; j < 4; j++) {
        const float* wgr = Wg + (size_t)(d0 + j) * NEXP;
#pragma unroll
        for (int e = 0; e < NEXP; e++) p[e] += hv[j] * wgr[e];
    }
#pragma unroll
    for (int e = 0; e < NEXP; e++)
        for (int o = 16; o > 0; o >>= 1)
            p[e] += __shfl_xor_sync(0xffffffffu, p[e], o);

    __shared__ float red[8][NEXP];
    int warp = tid >> 5, lane = tid & 31;
    if (lane == 0)
#pragma unroll
        for (int e = 0; e < NEXP; e++) red[warp][e] = p[e];
    __syncthreads();

    if (tid == 0) {
        float g[NEXP];
#pragma unroll
        for (int e = 0; e < NEXP; e++) {
            g[e] = bg[e];
#pragma unroll
            for (int w = 0; w < 8; w++) g[e] += red[w][e];
        }
        float mx = g[0];
#pragma unroll
        for (int e = 1; e < NEXP; e++) mx = fmaxf(mx, g[e]);
        float s = 0.f, pr[NEXP];
#pragma unroll
        for (int e = 0; e < NEXP; e++) { pr[e] = expf(g[e] - mx); s += pr[e]; }
        float inv = 1.f / s;
#pragma unroll
        for (int e = 0; e < NEXP; e++) pr[e] *= inv;

        int i0 = 0;
#pragma unroll
        for (int e = 1; e < NEXP; e++) if (pr[e] > pr[i0]) i0 = e;
        int i1 = (i0 == 0) ? 1 : 0;
#pragma unroll
        for (int e = 0; e < NEXP; e++)
            if (e != i0 && pr[e] > pr[i1]) i1 = e;

        g_w[2 * t]     = pr[i0];  g_eidx[2 * t]     = i0;
        g_w[2 * t + 1] = pr[i1];  g_eidx[2 * t + 1] = i1;
        atomicAdd(&g_cnt[i0], 1);
        atomicAdd(&g_cnt[i1], 1);
    }
}

__global__ void scan_kernel() {
    g_off[0] = 0;
    for (int e = 0; e < NEXP; e++) {
        g_off[e + 1] = g_off[e] + g_cnt[e];
        g_cur[e] = 0;
    }
}

__global__ void assign_kernel() {
    int t = blockIdx.x * blockDim.x + threadIdx.x;
    if (t >= TOKENS) return;
#pragma unroll
    for (int k = 0; k < 2; k++) {
        int e = g_eidx[2 * t + k];
        int pos = atomicAdd(&g_cur[e], 1);
        int slot = g_off[e] + pos;
        g_slot[2 * t + k] = slot;
        g_tokOfSlot[slot] = t;
    }
}

__global__ void combine_ln_kernel(const float* __restrict__ gamma,
                                  const float* __restrict__ beta) {
    int t = blockIdx.x, tid = threadIdx.x;
    int s0 = g_slot[2 * t], s1 = g_slot[2 * t + 1];
    float w0 = g_w[2 * t], w1 = g_w[2 * t + 1];

    float4 a = ((const float4*)(g_y + (size_t)s0 * DMODEL))[tid];
    float4 b = ((const float4*)(g_y + (size_t)s1 * DMODEL))[tid];
    float4 c;
    c.x = w0 * a.x + w1 * b.x;  c.y = w0 * a.y + w1 * b.y;
    c.z = w0 * a.z + w1 * b.z;  c.w = w0 * a.w + w1 * b.w;

    float sum = c.x + c.y + c.z + c.w;
    float ssq = c.x*c.x + c.y*c.y + c.z*c.z + c.w*c.w;
    for (int o = 16; o > 0; o >>= 1) {
        sum += __shfl_xor_sync(0xffffffffu, sum, o);
        ssq += __shfl_xor_sync(0xffffffffu, ssq, o);
    }
    __shared__ float rs[8], rq[8];
    __shared__ float s_mu, s_rstd;
    int warp = tid >> 5, lane = tid & 31;
    if (lane == 0) { rs[warp] = sum; rq[warp] = ssq; }
    __syncthreads();
    if (tid == 0) {
        float S = 0.f, Q = 0.f;
#pragma unroll
        for (int w = 0; w < 8; w++) { S += rs[w]; Q += rq[w]; }
        float mu = S / (float)DMODEL;
        float var = Q / (float)DMODEL - mu * mu;
        s_mu = mu;
        s_rstd = rsqrtf(var + LN_EPS);
    }
    __syncthreads();
    float mu = s_mu, rstd = s_rstd;
    float4 g4 = ((const float4*)gamma)[tid];
    float4 b4 = ((const float4*)beta)[tid];
    float4 o;
    o.x = f2tff((c.x - mu) * rstd * g4.x + b4.x);
    o.y = f2tff((c.y - mu) * rstd * g4.y + b4.y);
    o.z = f2tff((c.z - mu) * rstd * g4.z + b4.z);
    o.w = f2tff((c.w - mu) * rstd * g4.w + b4.w);
    ((float4*)(g_xn + (size_t)t * DMODEL))[tid] = o;
}

// ---------------- tf32 mma.sync GEMM with cp.async, 3 stages ----------------
// Operands in GMEM are already tf32-rounded fp32 bit patterns.
// A [M,K] row-major (optional row gather); B [K,N] row-major; C fp32 +bias.
// SMEM A: [kk(4)][m(128)][k8(8)], k8 ^= 4*((m>>2)&1)
// SMEM B: [k(32)][n(256)], n ^= (k&3)<<3
// Per stage: A 4096 floats, B 8192 floats (48KB); 3 stages = 144KB.
template <int K, int N, bool GROUPED, bool GATHER, bool RELU, bool CVTOUT>
__global__ void __launch_bounds__(256, 1)
tgemm(const float* __restrict__ A, const float* __restrict__ Ball,
      const float* __restrict__ biasAll, float* __restrict__ C, int Mtotal) {
    extern __shared__ float sm[];

    int e = GROUPED ? blockIdx.z : 0;
    int rowOff = GROUPED ? g_off[e] : 0;
    int cnt = GROUPED ? (g_off[e + 1] - rowOff) : Mtotal;
    int mTile = GROUPED ? blockIdx.y : blockIdx.x;
    int nTile = GROUPED ? blockIdx.x : blockIdx.y;
    int rowBlock = mTile * MT;
    if (rowBlock >= cnt) return;
    int colBlock = nTile * NT;

    const float* B = Ball + (GROUPED ? (size_t)e * K * N : (size_t)0);
    const float* bias = biasAll + (GROUPED ? (size_t)e * N : (size_t)0);

    int tid = threadIdx.x;
    int wid = tid >> 5, lane = tid & 31;
    int wm = wid >> 2, wn = wid & 3;
    int wmOff = wm * 64, wnOff = wn * 64;
    int g = lane >> 2, tg = lane & 3;

    // A loader: row r = tid>>1, k-half = (tid&1)*16, 4x 16B per chunk
    int r = tid >> 1;
    int khalf = (tid & 1) * 16;
    bool avalid = (rowBlock + r) < cnt;
    int asz = avalid ? 16 : 0;
    const float* arow;
    if (GATHER) {
        int tok = avalid ? g_tokOfSlot[rowOff + rowBlock + r] : 0;
        arow = A + (size_t)tok * K;
    } else {
        arow = A + (size_t)(rowOff + rowBlock + (avalid ? r : 0)) * K;
    }
    int aswz = ((r >> 2) & 1) * 4;
    const float* bbase = B + colBlock;

    uint32_t smb = smem_u32(sm);
    // precompute dst byte offsets within a stage
    uint32_t adst[4];
#pragma unroll
    for (int j = 0; j < 4; j++) {
        int k_in = khalf + j * 4;
        adst[j] = ((k_in >> 3) * 1024 + r * 8 + ((k_in & 7) ^ aswz)) * 4;
    }
    uint32_t bdst[8];
    int bkq[8], bn0[8];
#pragma unroll
    for (int i = 0; i < 8; i++) {
        int pos = i * 256 + tid;
        bkq[i] = pos >> 6;
        bn0[i] = (pos & 63) * 4;
        bdst[i] = (4096 + bkq[i] * 256 + (bn0[i] ^ ((bkq[i] & 3) << 3))) * 4;
    }

    auto issue_chunk = [&](int c, int s) {
        uint32_t base = smb + (uint32_t)s * 49152u;   // 12288 floats * 4
        const float* ap = arow + c * KCH;
#pragma unroll
        for (int j = 0; j < 4; j++)
            cp16(base + adst[j], ap + khalf + j * 4, asz);
#pragma unroll
        for (int i = 0; i < 8; i++)
            cp16(base + bdst[i], bbase + (size_t)(c * KCH + bkq[i]) * N + bn0[i], 16);
        cp_commit();
    };

    float acc[4][8][4];
#pragma unroll
    for (int i = 0; i < 4; i++)
#pragma unroll
        for (int j = 0; j < 8; j++)
#pragma unroll
            for (int q = 0; q < 4; q++) acc[i][j][q] = 0.f;

    const int NCH = K / KCH;
    issue_chunk(0, 0);
    issue_chunk(1, 1);

    for (int c = 0; c < NCH; c++) {
        int s = c % STAGES;
        if (c == NCH - 1) cp_wait<0>(); else cp_wait<1>();
        __syncthreads();
        if (c + 2 < NCH) issue_chunk(c + 2, (c + 2) % STAGES);

        const uint32_t* As = (const uint32_t*)(sm + s * 12288);
        const uint32_t* Bs = As + 4096;

        uint32_t af[2][4][4];
        uint32_t bf[2][8][2];
        // load ks=0 fragments
        {
            const uint32_t* aB = As;
            const uint32_t* bB = Bs;
#pragma unroll
            for (int mb = 0; mb < 4; mb++) {
                int m = wmOff + mb * 16 + g;
                int swz = ((m >> 2) & 1) * 4;
                int base = m * 8;
                af[0][mb][0] = aB[base + (tg ^ swz)];
                af[0][mb][1] = aB[base + 64 + (tg ^ swz)];
                af[0][mb][2] = aB[base + ((tg + 4) ^ swz)];
                af[0][mb][3] = aB[base + 64 + ((tg + 4) ^ swz)];
            }
#pragma unroll
            for (int nb = 0; nb < 8; nb++) {
                int n = wnOff + nb * 8 + g;
                int nsw = n ^ (tg << 3);
                bf[0][nb][0] = bB[tg * 256 + nsw];
                bf[0][nb][1] = bB[(tg + 4) * 256 + nsw];
            }
        }
#pragma unroll
        for (int ks = 0; ks < 4; ks++) {
            int cur = ks & 1, nxt = cur ^ 1;
            if (ks < 3) {
                const uint32_t* aB = As + (ks + 1) * 1024;
                const uint32_t* bB = Bs + (ks + 1) * 2048;
#pragma unroll
                for (int mb = 0; mb < 4; mb++) {
                    int m = wmOff + mb * 16 + g;
                    int swz = ((m >> 2) & 1) * 4;
                    int base = m * 8;
                    af[nxt][mb][0] = aB[base + (tg ^ swz)];
                    af[nxt][mb][1] = aB[base + 64 + (tg ^ swz)];
                    af[nxt][mb][2] = aB[base + ((tg + 4) ^ swz)];
                    af[nxt][mb][3] = aB[base + 64 + ((tg + 4) ^ swz)];
                }
#pragma unroll
                for (int nb = 0; nb < 8; nb++) {
                    int n = wnOff + nb * 8 + g;
                    int nsw = n ^ (tg << 3);
                    bf[nxt][nb][0] = bB[tg * 256 + nsw];
                    bf[nxt][nb][1] = bB[(tg + 4) * 256 + nsw];
                }
            }
#pragma unroll
            for (int mb = 0; mb < 4; mb++)
#pragma unroll
                for (int nb = 0; nb < 8; nb++)
                    mma_tf32(acc[mb][nb], af[cur][mb], bf[cur][nb]);
        }
    }

    // epilogue
#pragma unroll
    for (int nb = 0; nb < 8; nb++) {
        int col = colBlock + wnOff + nb * 8 + 2 * tg;
        float2 bv = *(const float2*)(bias + col);
#pragma unroll
        for (int mb = 0; mb < 4; mb++) {
            int mr = wmOff + mb * 16 + g;
            if (rowBlock + mr < cnt) {
                float2 o;
                o.x = acc[mb][nb][0] + bv.x;
                o.y = acc[mb][nb][1] + bv.y;
                if (RELU) { o.x = fmaxf(o.x, 0.f); o.y = fmaxf(o.y, 0.f); }
                if (CVTOUT) { o.x = f2tff(o.x); o.y = f2tff(o.y); }
                *(float2*)(C + (size_t)(rowOff + rowBlock + mr) * N + col) = o;
            }
            if (rowBlock + mr + 8 < cnt) {
                float2 o;
                o.x = acc[mb][nb][2] + bv.x;
                o.y = acc[mb][nb][3] + bv.y;
                if (RELU) { o.x = fmaxf(o.x, 0.f); o.y = fmaxf(o.y, 0.f); }
                if (CVTOUT) { o.x = f2tff(o.x); o.y = f2tff(o.y); }
                *(float2*)(C + (size_t)(rowOff + rowBlock + mr + 8) * N + col) = o;
            }
        }
    }
}

// ---------------- launch ----------------------------------------------------
static const int SMEM_SZ = STAGES * 49152;   // 144 KB

extern "C" void kernel_launch(void* const* d_in, const int* in_sizes, int n_in,
                              void* d_out, int out_size) {
    const int*   x     = (const int*)  d_in[0];
    const float* embed = (const float*)d_in[1];
    const float* Wg    = (const float*)d_in[2];
    const float* bg    = (const float*)d_in[3];
    const float* W1    = (const float*)d_in[4];
    const float* b1    = (const float*)d_in[5];
    const float* W2    = (const float*)d_in[6];
    const float* b2    = (const float*)d_in[7];
    const float* gamma = (const float*)d_in[8];
    const float* beta  = (const float*)d_in[9];
    const float* Wh    = (const float*)d_in[10];
    const float* bh    = (const float*)d_in[11];
    float* out = (float*)d_out;

    float *p_h, *p_a, *p_y, *p_xn, *p_Whc, *p_W1c, *p_W2c;
    cudaGetSymbolAddress((void**)&p_h,   g_h);
    cudaGetSymbolAddress((void**)&p_a,   g_a);
    cudaGetSymbolAddress((void**)&p_y,   g_y);
    cudaGetSymbolAddress((void**)&p_xn,  g_xn);
    cudaGetSymbolAddress((void**)&p_Whc, g_Whc);
    cudaGetSymbolAddress((void**)&p_W1c, g_W1c);
    cudaGetSymbolAddress((void**)&p_W2c, g_W2c);

    cudaFuncSetAttribute((const void*)tgemm<DMODEL, HIDDEN, true, true, true, true>,
                         cudaFuncAttributeMaxDynamicSharedMemorySize, SMEM_SZ);
    cudaFuncSetAttribute((const void*)tgemm<HIDDEN, DMODEL, true, false, false, false>,
                         cudaFuncAttributeMaxDynamicSharedMemorySize, SMEM_SZ);
    cudaFuncSetAttribute((const void*)tgemm<DMODEL, VOCABSZ, false, false, false, false>,
                         cudaFuncAttributeMaxDynamicSharedMemorySize, SMEM_SZ);

    // pre-convert weights to tf32-rounded bits (loop-invariant work, cheap)
    {
        int n4 = VOCABSZ * DMODEL / 4;
        cvt_kernel<<<(n4 + 255) / 256, 256>>>((const float4*)Wh, (float4*)p_Whc, n4);
        n4 = NEXP * DMODEL * HIDDEN / 4;
        cvt_kernel<<<(n4 + 255) / 256, 256>>>((const float4*)W1, (float4*)p_W1c, n4);
        cvt_kernel<<<(n4 + 255) / 256, 256>>>((const float4*)W2, (float4*)p_W2c, n4);
    }

    reset_kernel<<<1, 32>>>();
    gather_gate_kernel<<<TOKENS, 256>>>(x, embed, Wg, bg);
    scan_kernel<<<1, 1>>>();
    assign_kernel<<<(TOKENS + 255) / 256, 256>>>();

    // FFN1: per-expert [cnt,1024] x [1024,2048], ReLU, gathered A, tf32 out
    tgemm<DMODEL, HIDDEN, true, true, true, true>
        <<<dim3(HIDDEN / NT, 16, NEXP), 256, SMEM_SZ>>>(p_h, p_W1c, b1, p_a, 0);
    // FFN2: per-expert [cnt,2048] x [2048,1024], fp32 out
    tgemm<HIDDEN, DMODEL, true, false, false, false>
        <<<dim3(DMODEL / NT, 16, NEXP), 256, SMEM_SZ>>>(p_a, p_W2c, b2, p_y, 0);

    combine_ln_kernel<<<TOKENS, 256>>>(gamma, beta);

    // Head: [2048,1024] x [1024,32000]
    tgemm<DMODEL, VOCABSZ, false, false, false, false>
        <<<dim3(TOKENS / MT, VOCABSZ / NT, 1), 256, SMEM_SZ>>>(p_xn, p_Whc, bh, out, TOKENS);
}

// round 5
// speedup vs baseline: 5.6738x; 1.7392x over previous
#include <cuda_runtime.h>
#include <cuda_fp16.h>
#include <cstdint>
#include <math.h>

#define TOKENS   2048
#define DMODEL   1024
#define HIDDEN   2048
#define NEXP     8
#define VOCABSZ  32000
#define NASSIGN  (TOKENS * 2)
#define LN_EPS   1e-5f

#define MT 128
#define NT 256
#define KCH 32
// stage: A 128x32 half padded rows (5x16B) = 10240 B; B 32x256 half padded (33x16B) = 16896 B
#define STAGE_BYTES 27136
#define SMEM_SZ (4 * STAGE_BYTES)

// ---------------- scratch (device globals; no allocation allowed) ----------
__device__ __align__(16) __half g_h  [TOKENS  * DMODEL];
__device__ __align__(16) __half g_xn [TOKENS  * DMODEL];
__device__ __align__(16) __half g_a  [NASSIGN * HIDDEN];
__device__ __align__(16) float  g_y  [NASSIGN * DMODEL];
__device__ float g_w  [NASSIGN];
__device__ int   g_eidx[NASSIGN];
__device__ int   g_slot[NASSIGN];
__device__ int   g_tokOfSlot[NASSIGN];
__device__ int   g_cnt[NEXP];
__device__ int   g_off[NEXP + 1];
__device__ int   g_cur[NEXP];
// fp16 weight copies
__device__ __align__(16) __half g_Whh[VOCABSZ * DMODEL];
__device__ __align__(16) __half g_W1h[NEXP * DMODEL * HIDDEN];
__device__ __align__(16) __half g_W2h[NEXP * HIDDEN * DMODEL];

// ---------------- helpers ----------------------------------------------------
__device__ __forceinline__ uint32_t smem_u32(const void* p) {
    uint32_t a;
    asm("{ .reg .u64 t; cvta.to.shared.u64 t, %1; cvt.u32.u64 %0, t; }"
        : "=r"(a) : "l"(p));
    return a;
}
__device__ __forceinline__ void cp16(uint32_t dst, const void* src, int sz) {
    asm volatile("cp.async.cg.shared.global [%0], [%1], 16, %2;"
                 :: "r"(dst), "l"(src), "r"(sz) : "memory");
}
__device__ __forceinline__ void cp_commit() {
    asm volatile("cp.async.commit_group;" ::: "memory");
}
template <int N>
__device__ __forceinline__ void cp_wait() {
    asm volatile("cp.async.wait_group %0;" :: "n"(N) : "memory");
}
__device__ __forceinline__ void mma_f16(float c[4], const uint32_t a[4],
                                        const uint32_t b[2]) {
    asm volatile(
        "mma.sync.aligned.m16n8k16.row.col.f32.f16.f16.f32 "
        "{%0,%1,%2,%3}, {%4,%5,%6,%7}, {%8,%9}, {%0,%1,%2,%3};"
        : "+f"(c[0]), "+f"(c[1]), "+f"(c[2]), "+f"(c[3])
        : "r"(a[0]), "r"(a[1]), "r"(a[2]), "r"(a[3]), "r"(b[0]), "r"(b[1]));
}
__device__ __forceinline__ void ldsm4(uint32_t r[4], uint32_t addr) {
    asm volatile("ldmatrix.sync.aligned.m8n8.x4.shared.b16 {%0,%1,%2,%3}, [%4];"
                 : "=r"(r[0]), "=r"(r[1]), "=r"(r[2]), "=r"(r[3]) : "r"(addr));
}
__device__ __forceinline__ void ldsm4t(uint32_t r[4], uint32_t addr) {
    asm volatile("ldmatrix.sync.aligned.m8n8.x4.trans.shared.b16 {%0,%1,%2,%3}, [%4];"
                 : "=r"(r[0]), "=r"(r[1]), "=r"(r[2]), "=r"(r[3]) : "r"(addr));
}

// ---------------- weight fp16 pre-convert ------------------------------------
__global__ void cvt_h_kernel(const float4* __restrict__ src,
                             __half2* __restrict__ dst, int n4) {
    int i = blockIdx.x * blockDim.x + threadIdx.x;
    if (i < n4) {
        float4 v = src[i];
        dst[2 * i]     = __floats2half2_rn(v.x, v.y);
        dst[2 * i + 1] = __floats2half2_rn(v.z, v.w);
    }
}

// ---------------- tiny kernels ---------------------------------------------
__global__ void reset_kernel() {
    int i = threadIdx.x;
    if (i < NEXP) g_cnt[i] = 0;
}

__global__ void gather_gate_kernel(const int* __restrict__ x,
                                   const float* __restrict__ embed,
                                   const float* __restrict__ Wg,
                                   const float* __restrict__ bg) {
    int t   = blockIdx.x;
    int tid = threadIdx.x;
    int row = x[t];

    const float4* src = (const float4*)(embed + (size_t)row * DMODEL);
    float4 v = src[tid];
    __half2* hrow = (__half2*)(g_h + (size_t)t * DMODEL);
    hrow[2 * tid]     = __floats2half2_rn(v.x, v.y);
    hrow[2 * tid + 1] = __floats2half2_rn(v.z, v.w);

    float p[NEXP];
#pragma unroll
    for (int e = 0; e < NEXP; e++) p[e] = 0.f;
    float hv[4] = {v.x, v.y, v.z, v.w};
    int d0 = tid * 4;
#pragma unroll
    for (int j = 0; j < 4; j++) {
        const float* wgr = Wg + (size_t)(d0 + j) * NEXP;
#pragma unroll
        for (int e = 0; e < NEXP; e++) p[e] += hv[j] * wgr[e];
    }
#pragma unroll
    for (int e = 0; e < NEXP; e++)
        for (int o = 16; o > 0; o >>= 1)
            p[e] += __shfl_xor_sync(0xffffffffu, p[e], o);

    __shared__ float red[8][NEXP];
    int warp = tid >> 5, lane = tid & 31;
    if (lane == 0)
#pragma unroll
        for (int e = 0; e < NEXP; e++) red[warp][e] = p[e];
    __syncthreads();

    if (tid == 0) {
        float g[NEXP];
#pragma unroll
        for (int e = 0; e < NEXP; e++) {
            g[e] = bg[e];
#pragma unroll
            for (int w = 0; w < 8; w++) g[e] += red[w][e];
        }
        float mx = g[0];
#pragma unroll
        for (int e = 1; e < NEXP; e++) mx = fmaxf(mx, g[e]);
        float s = 0.f, pr[NEXP];
#pragma unroll
        for (int e = 0; e < NEXP; e++) { pr[e] = expf(g[e] - mx); s += pr[e]; }
        float inv = 1.f / s;
#pragma unroll
        for (int e = 0; e < NEXP; e++) pr[e] *= inv;

        int i0 = 0;
#pragma unroll
        for (int e = 1; e < NEXP; e++) if (pr[e] > pr[i0]) i0 = e;
        int i1 = (i0 == 0) ? 1 : 0;
#pragma unroll
        for (int e = 0; e < NEXP; e++)
            if (e != i0 && pr[e] > pr[i1]) i1 = e;

        g_w[2 * t]     = pr[i0];  g_eidx[2 * t]     = i0;
        g_w[2 * t + 1] = pr[i1];  g_eidx[2 * t + 1] = i1;
        atomicAdd(&g_cnt[i0], 1);
        atomicAdd(&g_cnt[i1], 1);
    }
}

__global__ void scan_kernel() {
    g_off[0] = 0;
    for (int e = 0; e < NEXP; e++) {
        g_off[e + 1] = g_off[e] + g_cnt[e];
        g_cur[e] = 0;
    }
}

__global__ void assign_kernel() {
    int t = blockIdx.x * blockDim.x + threadIdx.x;
    if (t >= TOKENS) return;
#pragma unroll
    for (int k = 0; k < 2; k++) {
        int e = g_eidx[2 * t + k];
        int pos = atomicAdd(&g_cur[e], 1);
        int slot = g_off[e] + pos;
        g_slot[2 * t + k] = slot;
        g_tokOfSlot[slot] = t;
    }
}

__global__ void combine_ln_kernel(const float* __restrict__ gamma,
                                  const float* __restrict__ beta) {
    int t = blockIdx.x, tid = threadIdx.x;
    int s0 = g_slot[2 * t], s1 = g_slot[2 * t + 1];
    float w0 = g_w[2 * t], w1 = g_w[2 * t + 1];

    float4 a = ((const float4*)(g_y + (size_t)s0 * DMODEL))[tid];
    float4 b = ((const float4*)(g_y + (size_t)s1 * DMODEL))[tid];
    float4 c;
    c.x = w0 * a.x + w1 * b.x;  c.y = w0 * a.y + w1 * b.y;
    c.z = w0 * a.z + w1 * b.z;  c.w = w0 * a.w + w1 * b.w;

    float sum = c.x + c.y + c.z + c.w;
    float ssq = c.x*c.x + c.y*c.y + c.z*c.z + c.w*c.w;
    for (int o = 16; o > 0; o >>= 1) {
        sum += __shfl_xor_sync(0xffffffffu, sum, o);
        ssq += __shfl_xor_sync(0xffffffffu, ssq, o);
    }
    __shared__ float rs[8], rq[8];
    __shared__ float s_mu, s_rstd;
    int warp = tid >> 5, lane = tid & 31;
    if (lane == 0) { rs[warp] = sum; rq[warp] = ssq; }
    __syncthreads();
    if (tid == 0) {
        float S = 0.f, Q = 0.f;
#pragma unroll
        for (int w = 0; w < 8; w++) { S += rs[w]; Q += rq[w]; }
        float mu = S / (float)DMODEL;
        float var = Q / (float)DMODEL - mu * mu;
        s_mu = mu;
        s_rstd = rsqrtf(var + LN_EPS);
    }
    __syncthreads();
    float mu = s_mu, rstd = s_rstd;
    float4 g4 = ((const float4*)gamma)[tid];
    float4 b4 = ((const float4*)beta)[tid];
    __half2* orow = (__half2*)(g_xn + (size_t)t * DMODEL);
    orow[2 * tid] = __floats2half2_rn((c.x - mu) * rstd * g4.x + b4.x,
                                      (c.y - mu) * rstd * g4.y + b4.y);
    orow[2 * tid + 1] = __floats2half2_rn((c.z - mu) * rstd * g4.z + b4.z,
                                          (c.w - mu) * rstd * g4.w + b4.w);
}

// ---------------- fp16 mma.sync GEMM, cp.async 4-stage, ldmatrix ------------
// A [M,K] half row-major (optional row gather); B [K,N] half row-major;
// C fp32 or fp16 (+bias fp32, opt ReLU). Tile 128x256, 8 warps (2x4), 64x64/warp.
// SMEM A: row m = 5 16B-units (32 k halves + pad), conflict-free ldmatrix.
// SMEM B: row k = 33 16B-units (256 n halves + pad), conflict-free ldmatrix.trans.
template <int K, int N, bool GROUPED, bool GATHER, bool RELU, bool HALFOUT>
__global__ void __launch_bounds__(256, 1)
hgemm(const __half* __restrict__ A, const __half* __restrict__ Ball,
      const float* __restrict__ biasAll, void* __restrict__ Cout, int Mtotal) {
    extern __shared__ char smc[];

    int e = GROUPED ? blockIdx.z : 0;
    int rowOff = GROUPED ? g_off[e] : 0;
    int cnt = GROUPED ? (g_off[e + 1] - rowOff) : Mtotal;
    int mTile = GROUPED ? blockIdx.y : blockIdx.x;
    int nTile = GROUPED ? blockIdx.x : blockIdx.y;
    int rowBlock = mTile * MT;
    if (rowBlock >= cnt) return;
    int colBlock = nTile * NT;

    const __half* B = Ball + (GROUPED ? (size_t)e * K * N : (size_t)0);
    const float* bias = biasAll + (GROUPED ? (size_t)e * N : (size_t)0);

    int tid = threadIdx.x;
    int wid = tid >> 5, lane = tid & 31;
    int wm = wid >> 2, wn = wid & 3;
    int wmOff = wm * 64, wnOff = wn * 64;
    int g = lane >> 2, tg = lane & 3;
    int b3 = lane >> 3, r8 = lane & 7;
    int aRow = (b3 & 1) * 8 + r8;    // + wmOff + mb*16
    int aKu  = b3 >> 1;              // + ks*2
    int bK   = (b3 & 1) * 8 + r8;    // + ks*16
    int bNu  = (b3 >> 1) + (wnOff >> 3);  // + p*2

    // A loader: m = tid>>1, two 16B units (8 halves each)
    int r = tid >> 1;
    bool avalid = (rowBlock + r) < cnt;
    int asz = avalid ? 16 : 0;
    const __half* arow;
    if (GATHER) {
        int tok = avalid ? g_tokOfSlot[rowOff + rowBlock + r] : 0;
        arow = A + (size_t)tok * K;
    } else {
        arow = A + (size_t)(rowOff + rowBlock + (avalid ? r : 0)) * K;
    }
    int aku0 = (tid & 1) * 2;
    const __half* bbase = B + colBlock;

    uint32_t smb = smem_u32(smc);
    uint32_t adst0 = (uint32_t)(r * 5 + aku0) * 16;
    // B loader: 4x 16B per thread
    int bk[4], bnu[4];
    uint32_t bdst[4];
#pragma unroll
    for (int i = 0; i < 4; i++) {
        int pos = i * 256 + tid;
        bk[i] = pos >> 5;
        bnu[i] = pos & 31;
        bdst[i] = 10240u + (uint32_t)(bk[i] * 33 + bnu[i]) * 16;
    }

    auto issue_chunk = [&](int c, int s) {
        uint32_t base = smb + (uint32_t)s * STAGE_BYTES;
        const __half* ap = arow + c * KCH + aku0 * 8;
        cp16(base + adst0, ap, asz);
        cp16(base + adst0 + 16, ap + 8, asz);
#pragma unroll
        for (int i = 0; i < 4; i++)
            cp16(base + bdst[i], bbase + (size_t)(c * KCH + bk[i]) * N + bnu[i] * 8, 16);
        cp_commit();
    };

    float acc[4][8][4];
#pragma unroll
    for (int i = 0; i < 4; i++)
#pragma unroll
        for (int j = 0; j < 8; j++)
#pragma unroll
            for (int q = 0; q < 4; q++) acc[i][j][q] = 0.f;

    const int NCH = K / KCH;
    issue_chunk(0, 0);
    issue_chunk(1, 1);
    issue_chunk(2, 2);

    for (int c = 0; c < NCH; c++) {
        int s = c & 3;
        cp_wait<2>();
        __syncthreads();
        if (c + 3 < NCH) issue_chunk(c + 3, (c + 3) & 3);
        else cp_commit();

        uint32_t sbase = smb + (uint32_t)s * STAGE_BYTES;
#pragma unroll
        for (int ks = 0; ks < 2; ks++) {
            uint32_t af[4][4];
            uint32_t bf[8][2];
#pragma unroll
            for (int mb = 0; mb < 4; mb++) {
                uint32_t addr = sbase +
                    (uint32_t)((wmOff + mb * 16 + aRow) * 5 + ks * 2 + aKu) * 16;
                ldsm4(af[mb], addr);
            }
#pragma unroll
            for (int p = 0; p < 4; p++) {
                uint32_t addr = sbase + 10240u +
                    (uint32_t)((ks * 16 + bK) * 33 + bNu + p * 2) * 16;
                uint32_t rr[4];
                ldsm4t(rr, addr);
                bf[2 * p][0] = rr[0]; bf[2 * p][1] = rr[1];
                bf[2 * p + 1][0] = rr[2]; bf[2 * p + 1][1] = rr[3];
            }
#pragma unroll
            for (int mb = 0; mb < 4; mb++)
#pragma unroll
                for (int nb = 0; nb < 8; nb++)
                    mma_f16(acc[mb][nb], af[mb], bf[nb]);
        }
    }

    // epilogue: c0,c1 at (row g, col tg*2), c2,c3 at (row g+8)
#pragma unroll
    for (int nb = 0; nb < 8; nb++) {
        int col = colBlock + wnOff + nb * 8 + tg * 2;
        float2 bv = *(const float2*)(bias + col);
#pragma unroll
        for (int mb = 0; mb < 4; mb++) {
            int mr = wmOff + mb * 16 + g;
#pragma unroll
            for (int h = 0; h < 2; h++) {
                int rr2 = mr + h * 8;
                if (rowBlock + rr2 < cnt) {
                    float ox = acc[mb][nb][2 * h]     + bv.x;
                    float oy = acc[mb][nb][2 * h + 1] + bv.y;
                    if (RELU) { ox = fmaxf(ox, 0.f); oy = fmaxf(oy, 0.f); }
                    size_t ro = (size_t)(rowOff + rowBlock + rr2) * N + col;
                    if (HALFOUT)
                        *(__half2*)((__half*)Cout + ro) = __floats2half2_rn(ox, oy);
                    else
                        *(float2*)((float*)Cout + ro) = make_float2(ox, oy);
                }
            }
        }
    }
}

// ---------------- launch ----------------------------------------------------
extern "C" void kernel_launch(void* const* d_in, const int* in_sizes, int n_in,
                              void* d_out, int out_size) {
    const int*   x     = (const int*)  d_in[0];
    const float* embed = (const float*)d_in[1];
    const float* Wg    = (const float*)d_in[2];
    const float* bg    = (const float*)d_in[3];
    const float* W1    = (const float*)d_in[4];
    const float* b1    = (const float*)d_in[5];
    const float* W2    = (const float*)d_in[6];
    const float* b2    = (const float*)d_in[7];
    const float* gamma = (const float*)d_in[8];
    const float* beta  = (const float*)d_in[9];
    const float* Wh    = (const float*)d_in[10];
    const float* bh    = (const float*)d_in[11];
    float* out = (float*)d_out;

    __half *p_h, *p_a, *p_xn, *p_Whh, *p_W1h, *p_W2h;
    float *p_y;
    cudaGetSymbolAddress((void**)&p_h,   g_h);
    cudaGetSymbolAddress((void**)&p_a,   g_a);
    cudaGetSymbolAddress((void**)&p_y,   g_y);
    cudaGetSymbolAddress((void**)&p_xn,  g_xn);
    cudaGetSymbolAddress((void**)&p_Whh, g_Whh);
    cudaGetSymbolAddress((void**)&p_W1h, g_W1h);
    cudaGetSymbolAddress((void**)&p_W2h, g_W2h);

    cudaFuncSetAttribute((const void*)hgemm<DMODEL, HIDDEN, true, true, true, true>,
                         cudaFuncAttributeMaxDynamicSharedMemorySize, SMEM_SZ);
    cudaFuncSetAttribute((const void*)hgemm<HIDDEN, DMODEL, true, false, false, false>,
                         cudaFuncAttributeMaxDynamicSharedMemorySize, SMEM_SZ);
    cudaFuncSetAttribute((const void*)hgemm<DMODEL, VOCABSZ, false, false, false, false>,
                         cudaFuncAttributeMaxDynamicSharedMemorySize, SMEM_SZ);

    // pre-convert weights to fp16 (loop-invariant)
    {
        int n4 = VOCABSZ * DMODEL / 4;
        cvt_h_kernel<<<(n4 + 255) / 256, 256>>>((const float4*)Wh, (__half2*)p_Whh, n4);
        n4 = NEXP * DMODEL * HIDDEN / 4;
        cvt_h_kernel<<<(n4 + 255) / 256, 256>>>((const float4*)W1, (__half2*)p_W1h, n4);
        cvt_h_kernel<<<(n4 + 255) / 256, 256>>>((const float4*)W2, (__half2*)p_W2h, n4);
    }

    reset_kernel<<<1, 32>>>();
    gather_gate_kernel<<<TOKENS, 256>>>(x, embed, Wg, bg);
    scan_kernel<<<1, 1>>>();
    assign_kernel<<<(TOKENS + 255) / 256, 256>>>();

    // FFN1: per-expert [cnt,1024] x [1024,2048], ReLU, gathered A, fp16 out
    hgemm<DMODEL, HIDDEN, true, true, true, true>
        <<<dim3(HIDDEN / NT, 16, NEXP), 256, SMEM_SZ>>>(p_h, p_W1h, b1, p_a, 0);
    // FFN2: per-expert [cnt,2048] x [2048,1024], fp32 out
    hgemm<HIDDEN, DMODEL, true, false, false, false>
        <<<dim3(DMODEL / NT, 16, NEXP), 256, SMEM_SZ>>>(p_a, p_W2h, b2, p_y, 0);

    combine_ln_kernel<<<TOKENS, 256>>>(gamma, beta);

    // Head: [2048,1024] x [1024,32000], fp32 out
    hgemm<DMODEL, VOCABSZ, false, false, false, false>
        <<<dim3(TOKENS / MT, VOCABSZ / NT, 1), 256, SMEM_SZ>>>(p_xn, p_Whh, bh, out, TOKENS);
}

// round 6
// speedup vs baseline: 5.7248x; 1.0090x over previous
#include <cuda_runtime.h>
#include <cuda_fp16.h>
#include <cstdint>
#include <math.h>

#define TOKENS   2048
#define DMODEL   1024
#define HIDDEN   2048
#define NEXP     8
#define VOCABSZ  32000
#define NASSIGN  (TOKENS * 2)
#define LN_EPS   1e-5f

#define MT 128
#define NT 256
#define KCH 32
// stage: A 128x32 half padded rows (5x16B) = 10240 B; B 32x256 half padded (33x16B) = 16896 B
#define STAGE_BYTES 27136
#define SMEM_SZ (4 * STAGE_BYTES)

// ---------------- scratch (device globals; no allocation allowed) ----------
__device__ __align__(16) __half g_h  [TOKENS  * DMODEL];
__device__ __align__(16) __half g_xn [TOKENS  * DMODEL];
__device__ __align__(16) __half g_a  [NASSIGN * HIDDEN];
__device__ __align__(16) float  g_y  [NASSIGN * DMODEL];
__device__ float g_w  [NASSIGN];
__device__ int   g_eidx[NASSIGN];
__device__ int   g_slot[NASSIGN];
__device__ int   g_tokOfSlot[NASSIGN];
__device__ int   g_cnt[NEXP];
__device__ int   g_off[NEXP + 1];
// fp16 weight copies
__device__ __align__(16) __half g_Whh[VOCABSZ * DMODEL];
__device__ __align__(16) __half g_W1h[NEXP * DMODEL * HIDDEN];
__device__ __align__(16) __half g_W2h[NEXP * HIDDEN * DMODEL];

// ---------------- helpers ----------------------------------------------------
__device__ __forceinline__ uint32_t smem_u32(const void* p) {
    uint32_t a;
    asm("{ .reg .u64 t; cvta.to.shared.u64 t, %1; cvt.u32.u64 %0, t; }"
        : "=r"(a) : "l"(p));
    return a;
}
__device__ __forceinline__ void cp16(uint32_t dst, const void* src, int sz) {
    asm volatile("cp.async.cg.shared.global [%0], [%1], 16, %2;"
                 :: "r"(dst), "l"(src), "r"(sz) : "memory");
}
__device__ __forceinline__ void cp_commit() {
    asm volatile("cp.async.commit_group;" ::: "memory");
}
template <int N>
__device__ __forceinline__ void cp_wait() {
    asm volatile("cp.async.wait_group %0;" :: "n"(N) : "memory");
}
__device__ __forceinline__ void mma_f16(float c[4], const uint32_t a[4],
                                        const uint32_t b[2]) {
    asm volatile(
        "mma.sync.aligned.m16n8k16.row.col.f32.f16.f16.f32 "
        "{%0,%1,%2,%3}, {%4,%5,%6,%7}, {%8,%9}, {%0,%1,%2,%3};"
        : "+f"(c[0]), "+f"(c[1]), "+f"(c[2]), "+f"(c[3])
        : "r"(a[0]), "r"(a[1]), "r"(a[2]), "r"(a[3]), "r"(b[0]), "r"(b[1]));
}
__device__ __forceinline__ void ldsm4(uint32_t r[4], uint32_t addr) {
    asm volatile("ldmatrix.sync.aligned.m8n8.x4.shared.b16 {%0,%1,%2,%3}, [%4];"
                 : "=r"(r[0]), "=r"(r[1]), "=r"(r[2]), "=r"(r[3]) : "r"(addr));
}
__device__ __forceinline__ void ldsm4t(uint32_t r[4], uint32_t addr) {
    asm volatile("ldmatrix.sync.aligned.m8n8.x4.trans.shared.b16 {%0,%1,%2,%3}, [%4];"
                 : "=r"(r[0]), "=r"(r[1]), "=r"(r[2]), "=r"(r[3]) : "r"(addr));
}

// ---------------- combined weight fp16 convert + counter reset ---------------
#define NH4 (VOCABSZ * DMODEL / 4)
#define NW4 (NEXP * DMODEL * HIDDEN / 4)
__global__ void cvt_all_kernel(const float4* __restrict__ Wh,
                               const float4* __restrict__ W1,
                               const float4* __restrict__ W2,
                               __half2* __restrict__ oWh,
                               __half2* __restrict__ oW1,
                               __half2* __restrict__ oW2) {
    if (blockIdx.x == 0 && threadIdx.x < NEXP) g_cnt[threadIdx.x] = 0;
    int i = blockIdx.x * blockDim.x + threadIdx.x;
    const float4* src;
    __half2* dst;
    int idx;
    if (i < NH4) { src = Wh; dst = oWh; idx = i; }
    else if (i < NH4 + NW4) { src = W1; dst = oW1; idx = i - NH4; }
    else if (i < NH4 + 2 * NW4) { src = W2; dst = oW2; idx = i - NH4 - NW4; }
    else return;
    float4 v = src[idx];
    dst[2 * idx]     = __floats2half2_rn(v.x, v.y);
    dst[2 * idx + 1] = __floats2half2_rn(v.z, v.w);
}

// ---------------- gather + gate ----------------------------------------------
__global__ void gather_gate_kernel(const int* __restrict__ x,
                                   const float* __restrict__ embed,
                                   const float* __restrict__ Wg,
                                   const float* __restrict__ bg) {
    int t   = blockIdx.x;
    int tid = threadIdx.x;
    int row = x[t];

    const float4* src = (const float4*)(embed + (size_t)row * DMODEL);
    float4 v = src[tid];
    __half2* hrow = (__half2*)(g_h + (size_t)t * DMODEL);
    hrow[2 * tid]     = __floats2half2_rn(v.x, v.y);
    hrow[2 * tid + 1] = __floats2half2_rn(v.z, v.w);

    float p[NEXP];
#pragma unroll
    for (int e = 0; e < NEXP; e++) p[e] = 0.f;
    float hv[4] = {v.x, v.y, v.z, v.w};
    int d0 = tid * 4;
#pragma unroll
    for (int j = 0; j < 4; j++) {
        const float* wgr = Wg + (size_t)(d0 + j) * NEXP;
#pragma unroll
        for (int e = 0; e < NEXP; e++) p[e] += hv[j] * wgr[e];
    }
#pragma unroll
    for (int e = 0; e < NEXP; e++)
        for (int o = 16; o > 0; o >>= 1)
            p[e] += __shfl_xor_sync(0xffffffffu, p[e], o);

    __shared__ float red[8][NEXP];
    int warp = tid >> 5, lane = tid & 31;
    if (lane == 0)
#pragma unroll
        for (int e = 0; e < NEXP; e++) red[warp][e] = p[e];
    __syncthreads();

    if (tid == 0) {
        float g[NEXP];
#pragma unroll
        for (int e = 0; e < NEXP; e++) {
            g[e] = bg[e];
#pragma unroll
            for (int w = 0; w < 8; w++) g[e] += red[w][e];
        }
        float mx = g[0];
#pragma unroll
        for (int e = 1; e < NEXP; e++) mx = fmaxf(mx, g[e]);
        float s = 0.f, pr[NEXP];
#pragma unroll
        for (int e = 0; e < NEXP; e++) { pr[e] = expf(g[e] - mx); s += pr[e]; }
        float inv = 1.f / s;
#pragma unroll
        for (int e = 0; e < NEXP; e++) pr[e] *= inv;

        int i0 = 0;
#pragma unroll
        for (int e = 1; e < NEXP; e++) if (pr[e] > pr[i0]) i0 = e;
        int i1 = (i0 == 0) ? 1 : 0;
#pragma unroll
        for (int e = 0; e < NEXP; e++)
            if (e != i0 && pr[e] > pr[i1]) i1 = e;

        g_w[2 * t]     = pr[i0];  g_eidx[2 * t]     = i0;
        g_w[2 * t + 1] = pr[i1];  g_eidx[2 * t + 1] = i1;
        atomicAdd(&g_cnt[i0], 1);
        atomicAdd(&g_cnt[i1], 1);
    }
}

// ---------------- fused scan + slot assignment (single block) ----------------
__global__ void scan_assign_kernel() {
    __shared__ int s_off[NEXP + 1];
    __shared__ int s_cur[NEXP];
    int tid = threadIdx.x;
    if (tid == 0) {
        s_off[0] = 0;
        for (int e = 0; e < NEXP; e++) s_off[e + 1] = s_off[e] + g_cnt[e];
        for (int e = 0; e <= NEXP; e++) g_off[e] = s_off[e];
    }
    if (tid < NEXP) s_cur[tid] = 0;
    __syncthreads();
    for (int t = tid; t < TOKENS; t += blockDim.x) {
#pragma unroll
        for (int k = 0; k < 2; k++) {
            int e = g_eidx[2 * t + k];
            int pos = atomicAdd(&s_cur[e], 1);
            int slot = s_off[e] + pos;
            g_slot[2 * t + k] = slot;
            g_tokOfSlot[slot] = t;
        }
    }
}

__global__ void combine_ln_kernel(const float* __restrict__ gamma,
                                  const float* __restrict__ beta) {
    int t = blockIdx.x, tid = threadIdx.x;
    int s0 = g_slot[2 * t], s1 = g_slot[2 * t + 1];
    float w0 = g_w[2 * t], w1 = g_w[2 * t + 1];

    float4 a = ((const float4*)(g_y + (size_t)s0 * DMODEL))[tid];
    float4 b = ((const float4*)(g_y + (size_t)s1 * DMODEL))[tid];
    float4 c;
    c.x = w0 * a.x + w1 * b.x;  c.y = w0 * a.y + w1 * b.y;
    c.z = w0 * a.z + w1 * b.z;  c.w = w0 * a.w + w1 * b.w;

    float sum = c.x + c.y + c.z + c.w;
    float ssq = c.x*c.x + c.y*c.y + c.z*c.z + c.w*c.w;
    for (int o = 16; o > 0; o >>= 1) {
        sum += __shfl_xor_sync(0xffffffffu, sum, o);
        ssq += __shfl_xor_sync(0xffffffffu, ssq, o);
    }
    __shared__ float rs[8], rq[8];
    __shared__ float s_mu, s_rstd;
    int warp = tid >> 5, lane = tid & 31;
    if (lane == 0) { rs[warp] = sum; rq[warp] = ssq; }
    __syncthreads();
    if (tid == 0) {
        float S = 0.f, Q = 0.f;
#pragma unroll
        for (int w = 0; w < 8; w++) { S += rs[w]; Q += rq[w]; }
        float mu = S / (float)DMODEL;
        float var = Q / (float)DMODEL - mu * mu;
        s_mu = mu;
        s_rstd = rsqrtf(var + LN_EPS);
    }
    __syncthreads();
    float mu = s_mu, rstd = s_rstd;
    float4 g4 = ((const float4*)gamma)[tid];
    float4 b4 = ((const float4*)beta)[tid];
    __half2* orow = (__half2*)(g_xn + (size_t)t * DMODEL);
    orow[2 * tid] = __floats2half2_rn((c.x - mu) * rstd * g4.x + b4.x,
                                      (c.y - mu) * rstd * g4.y + b4.y);
    orow[2 * tid + 1] = __floats2half2_rn((c.z - mu) * rstd * g4.z + b4.z,
                                          (c.w - mu) * rstd * g4.w + b4.w);
}

// ---------------- fp16 mma.sync GEMM, 512 thr (16 warps, 2x8), 4-stage -------
// CTA tile 128x256, warp tile 64x32 (64 accum regs) -> 4 warps/SMSP hiding.
// SMEM A: row m = 5 16B-units (32 k + pad); SMEM B: row k = 33 16B-units.
template <int K, int N, bool GROUPED, bool GATHER, bool RELU, bool HALFOUT>
__global__ void __launch_bounds__(512, 1)
hgemm(const __half* __restrict__ A, const __half* __restrict__ Ball,
      const float* __restrict__ biasAll, void* __restrict__ Cout, int Mtotal) {
    extern __shared__ char smc[];

    int e = GROUPED ? blockIdx.z : 0;
    int rowOff = GROUPED ? g_off[e] : 0;
    int cnt = GROUPED ? (g_off[e + 1] - rowOff) : Mtotal;
    int mTile = GROUPED ? blockIdx.y : blockIdx.x;
    int nTile = GROUPED ? blockIdx.x : blockIdx.y;
    int rowBlock = mTile * MT;
    if (rowBlock >= cnt) return;
    int colBlock = nTile * NT;

    const __half* B = Ball + (GROUPED ? (size_t)e * K * N : (size_t)0);
    const float* bias = biasAll + (GROUPED ? (size_t)e * N : (size_t)0);

    int tid = threadIdx.x;
    int wid = tid >> 5, lane = tid & 31;
    int wm = wid >> 3, wn = wid & 7;           // 2 x 8 warp grid
    int wmOff = wm * 64, wnOff = wn * 32;
    int g = lane >> 2, tg = lane & 3;
    int b3 = lane >> 3, r8 = lane & 7;
    int aRow = (b3 & 1) * 8 + r8;
    int aKu  = b3 >> 1;
    int bK   = (b3 & 1) * 8 + r8;
    int bNu  = (b3 >> 1) + (wnOff >> 3);

    // A loader: 512 units (128 rows x 4 data units of 16B); one per thread
    int r = tid >> 2;
    int au = tid & 3;
    bool avalid = (rowBlock + r) < cnt;
    int asz = avalid ? 16 : 0;
    const __half* arow;
    if (GATHER) {
        int tok = avalid ? g_tokOfSlot[rowOff + rowBlock + r] : 0;
        arow = A + (size_t)tok * K;
    } else {
        arow = A + (size_t)(rowOff + rowBlock + (avalid ? r : 0)) * K;
    }
    uint32_t smb = smem_u32(smc);
    uint32_t adst = (uint32_t)(r * 5 + au) * 16;
    // B loader: 1024 units, two per thread
    int bk[2], bn[2];
    uint32_t bdst[2];
#pragma unroll
    for (int i = 0; i < 2; i++) {
        int pos = i * 512 + tid;
        bk[i] = pos >> 5;
        bn[i] = pos & 31;
        bdst[i] = 10240u + (uint32_t)(bk[i] * 33 + bn[i]) * 16;
    }

    auto issue_chunk = [&](int c, int s) {
        uint32_t base = smb + (uint32_t)s * STAGE_BYTES;
        cp16(base + adst, arow + c * KCH + au * 8, asz);
#pragma unroll
        for (int i = 0; i < 2; i++)
            cp16(base + bdst[i], B + colBlock + (size_t)(c * KCH + bk[i]) * N + bn[i] * 8, 16);
        cp_commit();
    };

    float acc[4][4][4];
#pragma unroll
    for (int i = 0; i < 4; i++)
#pragma unroll
        for (int j = 0; j < 4; j++)
#pragma unroll
            for (int q = 0; q < 4; q++) acc[i][j][q] = 0.f;

    const int NCH = K / KCH;
    issue_chunk(0, 0);
    issue_chunk(1, 1);
    issue_chunk(2, 2);

    for (int c = 0; c < NCH; c++) {
        int s = c & 3;
        cp_wait<2>();
        __syncthreads();
        if (c + 3 < NCH) issue_chunk(c + 3, (c + 3) & 3);
        else cp_commit();

        uint32_t sbase = smb + (uint32_t)s * STAGE_BYTES;
#pragma unroll
        for (int ks = 0; ks < 2; ks++) {
            uint32_t af[4][4];
            uint32_t bf[4][2];
#pragma unroll
            for (int mb = 0; mb < 4; mb++) {
                uint32_t addr = sbase +
                    (uint32_t)((wmOff + mb * 16 + aRow) * 5 + ks * 2 + aKu) * 16;
                ldsm4(af[mb], addr);
            }
#pragma unroll
            for (int p = 0; p < 2; p++) {
                uint32_t addr = sbase + 10240u +
                    (uint32_t)((ks * 16 + bK) * 33 + bNu + p * 2) * 16;
                uint32_t rr[4];
                ldsm4t(rr, addr);
                bf[2 * p][0] = rr[0]; bf[2 * p][1] = rr[1];
                bf[2 * p + 1][0] = rr[2]; bf[2 * p + 1][1] = rr[3];
            }
#pragma unroll
            for (int mb = 0; mb < 4; mb++)
#pragma unroll
                for (int nb = 0; nb < 4; nb++)
                    mma_f16(acc[mb][nb], af[mb], bf[nb]);
        }
    }

    // epilogue
#pragma unroll
    for (int nb = 0; nb < 4; nb++) {
        int col = colBlock + wnOff + nb * 8 + tg * 2;
        float2 bv = *(const float2*)(bias + col);
#pragma unroll
        for (int mb = 0; mb < 4; mb++) {
            int mr = wmOff + mb * 16 + g;
#pragma unroll
            for (int h = 0; h < 2; h++) {
                int rr2 = mr + h * 8;
                if (rowBlock + rr2 < cnt) {
                    float ox = acc[mb][nb][2 * h]     + bv.x;
                    float oy = acc[mb][nb][2 * h + 1] + bv.y;
                    if (RELU) { ox = fmaxf(ox, 0.f); oy = fmaxf(oy, 0.f); }
                    size_t ro = (size_t)(rowOff + rowBlock + rr2) * N + col;
                    if (HALFOUT)
                        *(__half2*)((__half*)Cout + ro) = __floats2half2_rn(ox, oy);
                    else
                        *(float2*)((float*)Cout + ro) = make_float2(ox, oy);
                }
            }
        }
    }
}

// ---------------- launch ----------------------------------------------------
extern "C" void kernel_launch(void* const* d_in, const int* in_sizes, int n_in,
                              void* d_out, int out_size) {
    const int*   x     = (const int*)  d_in[0];
    const float* embed = (const float*)d_in[1];
    const float* Wg    = (const float*)d_in[2];
    const float* bg    = (const float*)d_in[3];
    const float* W1    = (const float*)d_in[4];
    const float* b1    = (const float*)d_in[5];
    const float* W2    = (const float*)d_in[6];
    const float* b2    = (const float*)d_in[7];
    const float* gamma = (const float*)d_in[8];
    const float* beta  = (const float*)d_in[9];
    const float* Wh    = (const float*)d_in[10];
    const float* bh    = (const float*)d_in[11];
    float* out = (float*)d_out;

    __half *p_h, *p_a, *p_xn, *p_Whh, *p_W1h, *p_W2h;
    float *p_y;
    cudaGetSymbolAddress((void**)&p_h,   g_h);
    cudaGetSymbolAddress((void**)&p_a,   g_a);
    cudaGetSymbolAddress((void**)&p_y,   g_y);
    cudaGetSymbolAddress((void**)&p_xn,  g_xn);
    cudaGetSymbolAddress((void**)&p_Whh, g_Whh);
    cudaGetSymbolAddress((void**)&p_W1h, g_W1h);
    cudaGetSymbolAddress((void**)&p_W2h, g_W2h);

    cudaFuncSetAttribute((const void*)hgemm<DMODEL, HIDDEN, true, true, true, true>,
                         cudaFuncAttributeMaxDynamicSharedMemorySize, SMEM_SZ);
    cudaFuncSetAttribute((const void*)hgemm<HIDDEN, DMODEL, true, false, false, false>,
                         cudaFuncAttributeMaxDynamicSharedMemorySize, SMEM_SZ);
    cudaFuncSetAttribute((const void*)hgemm<DMODEL, VOCABSZ, false, false, false, false>,
                         cudaFuncAttributeMaxDynamicSharedMemorySize, SMEM_SZ);

    // weights -> fp16 + reset counters (one launch)
    {
        int total = NH4 + 2 * NW4;
        cvt_all_kernel<<<(total + 255) / 256, 256>>>(
            (const float4*)Wh, (const float4*)W1, (const float4*)W2,
            (__half2*)p_Whh, (__half2*)p_W1h, (__half2*)p_W2h);
    }

    gather_gate_kernel<<<TOKENS, 256>>>(x, embed, Wg, bg);
    scan_assign_kernel<<<1, 1024>>>();

    // FFN1: per-expert [cnt,1024] x [1024,2048], ReLU, gathered A, fp16 out
    hgemm<DMODEL, HIDDEN, true, true, true, true>
        <<<dim3(HIDDEN / NT, 16, NEXP), 512, SMEM_SZ>>>(p_h, p_W1h, b1, p_a, 0);
    // FFN2: per-expert [cnt,2048] x [2048,1024], fp32 out
    hgemm<HIDDEN, DMODEL, true, false, false, false>
        <<<dim3(DMODEL / NT, 16, NEXP), 512, SMEM_SZ>>>(p_a, p_W2h, b2, p_y, 0);

    combine_ln_kernel<<<TOKENS, 256>>>(gamma, beta);

    // Head: [2048,1024] x [1024,32000], fp32 out
    hgemm<DMODEL, VOCABSZ, false, false, false, false>
        <<<dim3(TOKENS / MT, VOCABSZ / NT, 1), 512, SMEM_SZ>>>(p_xn, p_Whh, bh, out, TOKENS);
}

// round 8
// speedup vs baseline: 6.6418x; 1.1602x over previous
#include <cuda_runtime.h>
#include <cuda_fp16.h>
#include <cstdint>
#include <math.h>

#define TOKENS   2048
#define DMODEL   1024
#define HIDDEN   2048
#define NEXP     8
#define VOCABSZ  32000
#define LN_EPS   1e-5f

#define MT 128
#define NT 256
#define KCH 32
// packed block sizes (bytes): A 128 rows x 80B, B 32 rows x 528B
#define ABLK_B   10240
#define BBLK_B   16896
#define ABLK_H   5120
#define BBLK_H   8448
#define STAGE_BYTES (ABLK_B + BBLK_B)        // 27136
#define MBOFF (4 * STAGE_BYTES)
#define SMEM_SZ (MBOFF + 64)

#define NSLOTPAD 5120
#define SLOTTILES 40

// ---------------- scratch (device globals; no allocation allowed) ----------
__device__ float g_w  [TOKENS * 2];
__device__ int   g_eidx[TOKENS * 2];
__device__ int   g_slot[TOKENS * 2];
__device__ int   g_tokOfSlot[NSLOTPAD];
__device__ int   g_cnt[NEXP];
__device__ int   g_off[NEXP + 1];
__device__ float g_y  [NSLOTPAD * DMODEL];
// packed operands (SMEM-image blocks)
__device__ __align__(16) __half g_hpk [SLOTTILES * 32 * ABLK_H];  // FFN1 A
__device__ __align__(16) __half g_apk [SLOTTILES * 64 * ABLK_H];  // FFN2 A
__device__ __align__(16) __half g_xpk [16 * 32 * ABLK_H];         // head A
__device__ __align__(16) __half g_Whp [125 * 32 * BBLK_H];
__device__ __align__(16) __half g_W1p [NEXP * 8 * 32 * BBLK_H];
__device__ __align__(16) __half g_W2p [NEXP * 4 * 64 * BBLK_H];

// ---------------- helpers ----------------------------------------------------
__device__ __forceinline__ uint32_t h2u(__half2 h) {
    return *reinterpret_cast<uint32_t*>(&h);
}
__device__ __forceinline__ uint32_t smem_u32(const void* p) {
    uint32_t a;
    asm("{ .reg .u64 t; cvta.to.shared.u64 t, %1; cvt.u32.u64 %0, t; }"
        : "=r"(a) : "l"(p));
    return a;
}
__device__ __forceinline__ void mma_f16(float c[4], const uint32_t a[4],
                                        const uint32_t b[2]) {
    asm volatile(
        "mma.sync.aligned.m16n8k16.row.col.f32.f16.f16.f32 "
        "{%0,%1,%2,%3}, {%4,%5,%6,%7}, {%8,%9}, {%0,%1,%2,%3};"
        : "+f"(c[0]), "+f"(c[1]), "+f"(c[2]), "+f"(c[3])
        : "r"(a[0]), "r"(a[1]), "r"(a[2]), "r"(a[3]), "r"(b[0]), "r"(b[1]));
}
__device__ __forceinline__ void ldsm4(uint32_t r[4], uint32_t addr) {
    asm volatile("ldmatrix.sync.aligned.m8n8.x4.shared.b16 {%0,%1,%2,%3}, [%4];"
                 : "=r"(r[0]), "=r"(r[1]), "=r"(r[2]), "=r"(r[3]) : "r"(addr));
}
__device__ __forceinline__ void ldsm4t(uint32_t r[4], uint32_t addr) {
    asm volatile("ldmatrix.sync.aligned.m8n8.x4.trans.shared.b16 {%0,%1,%2,%3}, [%4];"
                 : "=r"(r[0]), "=r"(r[1]), "=r"(r[2]), "=r"(r[3]) : "r"(addr));
}
#define MBAR_INIT(a, n) \
    asm volatile("mbarrier.init.shared.b64 [%0], %1;" :: "r"((uint32_t)(a)), "r"((uint32_t)(n)) : "memory")
#define MBAR_EXPECT_TX(a, b) \
    asm volatile("mbarrier.arrive.expect_tx.shared.b64 _, [%0], %1;" :: "r"((uint32_t)(a)), "r"((uint32_t)(b)) : "memory")
#define MBAR_WAIT(a, par) do { \
    uint32_t _mb = (uint32_t)(a); uint32_t _pa = (uint32_t)(par); uint32_t _dn; \
    asm volatile("{\n\t.reg .pred p;\n\t" \
        "mbarrier.try_wait.parity.acquire.cta.shared::cta.b64 p, [%1], %2;\n\t" \
        "selp.b32 %0, 1, 0, p;\n\t}" : "=r"(_dn) : "r"(_mb), "r"(_pa) : "memory"); \
    if (!_dn) { \
        asm volatile("{\n\t.reg .pred P1;\n\t" \
            "WL_%=:\n\t" \
            "mbarrier.try_wait.parity.acquire.cta.shared::cta.b64 P1, [%0], %1, 0x989680;\n\t" \
            "@P1 bra.uni WD_%=;\n\t" \
            "bra.uni WL_%=;\n\t" \
            "WD_%=:\n\t}" :: "r"(_mb), "r"(_pa) : "memory"); \
    } } while (0)
__device__ __forceinline__ void bulk_ld(uint32_t dst, const void* src,
                                        uint32_t bytes, uint32_t mbar) {
    asm volatile(
        "cp.async.bulk.shared::cluster.global.mbarrier::complete_tx::bytes "
        "[%0], [%1], %2, [%3];"
        :: "r"(dst), "l"(src), "r"(bytes), "r"(mbar) : "memory");
}

// ---------------- weight fp16 convert + pack + counter reset ----------------
#define WH_UNITS (125 * 32 * 32 * 32)
#define W1_UNITS (NEXP * 8 * 32 * 32 * 32)
#define W2_UNITS (NEXP * 4 * 64 * 32 * 32)
__global__ void pack_w_kernel(const float* __restrict__ Wh,
                              const float* __restrict__ W1,
                              const float* __restrict__ W2) {
    if (blockIdx.x == 0 && threadIdx.x < NEXP) g_cnt[threadIdx.x] = 0;
    int idx = blockIdx.x * blockDim.x + threadIdx.x;
    const float* src;
    __half* dst;
    if (idx < WH_UNITS) {
        int u = idx & 31, k = (idx >> 5) & 31, ch = (idx >> 10) & 31, st = idx >> 15;
        src = Wh + (size_t)(ch * 32 + k) * VOCABSZ + st * 256 + u * 8;
        dst = g_Whp + (size_t)(st * 32 + ch) * BBLK_H + k * 264 + u * 8;
    } else if (idx < WH_UNITS + W1_UNITS) {
        int i = idx - WH_UNITS;
        int u = i & 31, k = (i >> 5) & 31, ch = (i >> 10) & 31, st = (i >> 15) & 7, e = i >> 18;
        src = W1 + (size_t)e * DMODEL * HIDDEN + (size_t)(ch * 32 + k) * HIDDEN + st * 256 + u * 8;
        dst = g_W1p + (size_t)((e * 8 + st) * 32 + ch) * BBLK_H + k * 264 + u * 8;
    } else if (idx < WH_UNITS + W1_UNITS + W2_UNITS) {
        int i = idx - WH_UNITS - W1_UNITS;
        int u = i & 31, k = (i >> 5) & 31, ch = (i >> 10) & 63, st = (i >> 16) & 3, e = i >> 18;
        src = W2 + (size_t)e * HIDDEN * DMODEL + (size_t)(ch * 32 + k) * DMODEL + st * 256 + u * 8;
        dst = g_W2p + (size_t)((e * 4 + st) * 64 + ch) * BBLK_H + k * 264 + u * 8;
    } else return;
    float4 v0 = *(const float4*)src;
    float4 v1 = *(const float4*)(src + 4);
    uint4 o;
    o.x = h2u(__floats2half2_rn(v0.x, v0.y));
    o.y = h2u(__floats2half2_rn(v0.z, v0.w));
    o.z = h2u(__floats2half2_rn(v1.x, v1.y));
    o.w = h2u(__floats2half2_rn(v1.z, v1.w));
    *(uint4*)dst = o;
}

// ---------------- gate ----------------------------------------------------
__global__ void gate_kernel(const int* __restrict__ x,
                            const float* __restrict__ embed,
                            const float* __restrict__ Wg,
                            const float* __restrict__ bg) {
    int t   = blockIdx.x;
    int tid = threadIdx.x;
    int row = x[t];
    float4 v = ((const float4*)(embed + (size_t)row * DMODEL))[tid];

    float p[NEXP];
#pragma unroll
    for (int e = 0; e < NEXP; e++) p[e] = 0.f;
    float hv[4] = {v.x, v.y, v.z, v.w};
    int d0 = tid * 4;
#pragma unroll
    for (int j = 0; j < 4; j++) {
        const float* wgr = Wg + (size_t)(d0 + j) * NEXP;
#pragma unroll
        for (int e = 0; e < NEXP; e++) p[e] += hv[j] * wgr[e];
    }
#pragma unroll
    for (int e = 0; e < NEXP; e++)
        for (int o = 16; o > 0; o >>= 1)
            p[e] += __shfl_xor_sync(0xffffffffu, p[e], o);

    __shared__ float red[8][NEXP];
    int warp = tid >> 5, lane = tid & 31;
    if (lane == 0)
#pragma unroll
        for (int e = 0; e < NEXP; e++) red[warp][e] = p[e];
    __syncthreads();

    if (tid == 0) {
        float g[NEXP];
#pragma unroll
        for (int e = 0; e < NEXP; e++) {
            g[e] = bg[e];
#pragma unroll
            for (int w = 0; w < 8; w++) g[e] += red[w][e];
        }
        float mx = g[0];
#pragma unroll
        for (int e = 1; e < NEXP; e++) mx = fmaxf(mx, g[e]);
        float s = 0.f, pr[NEXP];
#pragma unroll
        for (int e = 0; e < NEXP; e++) { pr[e] = expf(g[e] - mx); s += pr[e]; }
        float inv = 1.f / s;
#pragma unroll
        for (int e = 0; e < NEXP; e++) pr[e] *= inv;

        int i0 = 0;
#pragma unroll
        for (int e = 1; e < NEXP; e++) if (pr[e] > pr[i0]) i0 = e;
        int i1 = (i0 == 0) ? 1 : 0;
#pragma unroll
        for (int e = 0; e < NEXP; e++)
            if (e != i0 && pr[e] > pr[i1]) i1 = e;

        g_w[2 * t]     = pr[i0];  g_eidx[2 * t]     = i0;
        g_w[2 * t + 1] = pr[i1];  g_eidx[2 * t + 1] = i1;
        atomicAdd(&g_cnt[i0], 1);
        atomicAdd(&g_cnt[i1], 1);
    }
}

// ---------------- scan (128-aligned) + slot assignment ----------------------
__global__ void scan_assign_kernel() {
    __shared__ int s_off[NEXP + 1];
    __shared__ int s_cur[NEXP];
    int tid = threadIdx.x;
    for (int i = tid; i < NSLOTPAD; i += blockDim.x) g_tokOfSlot[i] = 0;
    if (tid == 0) {
        s_off[0] = 0;
        for (int e = 0; e < NEXP; e++)
            s_off[e + 1] = s_off[e] + ((g_cnt[e] + 127) & ~127);
        for (int e = 0; e <= NEXP; e++) g_off[e] = s_off[e];
    }
    if (tid < NEXP) s_cur[tid] = 0;
    __syncthreads();
    for (int t = tid; t < TOKENS; t += blockDim.x) {
#pragma unroll
        for (int k = 0; k < 2; k++) {
            int e = g_eidx[2 * t + k];
            int pos = atomicAdd(&s_cur[e], 1);
            int slot = s_off[e] + pos;
            g_slot[2 * t + k] = slot;
            g_tokOfSlot[slot] = t;
        }
    }
}

// ---------------- pack FFN1 A: embed rows (slot order) -> padded blocks -----
__global__ void pack_h_kernel(const int* __restrict__ x,
                              const float* __restrict__ embed) {
    int idx = blockIdx.x * blockDim.x + threadIdx.x;   // over NSLOTPAD*128
    if (idx >= NSLOTPAD * 128) return;
    int slot = idx >> 7;
    int u = idx & 127;
    int ch = u >> 2, pos = u & 3;
    int tok = g_tokOfSlot[slot];
    int row = x[tok];
    const float* src = embed + (size_t)row * DMODEL + ch * 32 + pos * 8;
    float4 v0 = *(const float4*)src;
    float4 v1 = *(const float4*)(src + 4);
    uint4 o;
    o.x = h2u(__floats2half2_rn(v0.x, v0.y));
    o.y = h2u(__floats2half2_rn(v0.z, v0.w));
    o.z = h2u(__floats2half2_rn(v1.x, v1.y));
    o.w = h2u(__floats2half2_rn(v1.z, v1.w));
    __half* dst = g_hpk + (size_t)((slot >> 7) * 32 + ch) * ABLK_H + (slot & 127) * 40 + pos * 8;
    *(uint4*)dst = o;
}

// ---------------- combine + LN -> packed head A ------------------------------
__global__ void combine_ln_kernel(const float* __restrict__ gamma,
                                  const float* __restrict__ beta) {
    int t = blockIdx.x, tid = threadIdx.x;
    int s0 = g_slot[2 * t], s1 = g_slot[2 * t + 1];
    float w0 = g_w[2 * t], w1 = g_w[2 * t + 1];

    float4 a = ((const float4*)(g_y + (size_t)s0 * DMODEL))[tid];
    float4 b = ((const float4*)(g_y + (size_t)s1 * DMODEL))[tid];
    float4 c;
    c.x = w0 * a.x + w1 * b.x;  c.y = w0 * a.y + w1 * b.y;
    c.z = w0 * a.z + w1 * b.z;  c.w = w0 * a.w + w1 * b.w;

    float sum = c.x + c.y + c.z + c.w;
    float ssq = c.x*c.x + c.y*c.y + c.z*c.z + c.w*c.w;
    for (int o = 16; o > 0; o >>= 1) {
        sum += __shfl_xor_sync(0xffffffffu, sum, o);
        ssq += __shfl_xor_sync(0xffffffffu, ssq, o);
    }
    __shared__ float rs[8], rq[8];
    __shared__ float s_mu, s_rstd;
    int warp = tid >> 5, lane = tid & 31;
    if (lane == 0) { rs[warp] = sum; rq[warp] = ssq; }
    __syncthreads();
    if (tid == 0) {
        float S = 0.f, Q = 0.f;
#pragma unroll
        for (int w = 0; w < 8; w++) { S += rs[w]; Q += rq[w]; }
        float mu = S / (float)DMODEL;
        float var = Q / (float)DMODEL - mu * mu;
        s_mu = mu;
        s_rstd = rsqrtf(var + LN_EPS);
    }
    __syncthreads();
    float mu = s_mu, rstd = s_rstd;
    float4 g4 = ((const float4*)gamma)[tid];
    float4 b4 = ((const float4*)beta)[tid];
    uint2 o;
    o.x = h2u(__floats2half2_rn((c.x - mu) * rstd * g4.x + b4.x,
                                (c.y - mu) * rstd * g4.y + b4.y));
    o.y = h2u(__floats2half2_rn((c.z - mu) * rstd * g4.z + b4.z,
                                (c.w - mu) * rstd * g4.w + b4.w));
    int d0 = tid * 4;
    int ch = d0 >> 5, c2 = d0 & 31;
    __half* dst = g_xpk + (size_t)((t >> 7) * 32 + ch) * ABLK_H + (t & 127) * 40 + c2;
    *(uint2*)dst = o;
}

// ---------------- fp16 GEMM: bulk-TMA mainloop, 512 thr, 16 warps ------------
// OUT: 0 = fp32 plain rows, 1 = half packed blocks (for next GEMM's A)
template <int K, int N, bool GROUPED, bool RELU, int OUT>
__global__ void __launch_bounds__(512, 1)
bgemm(const __half* __restrict__ Apk, const __half* __restrict__ Bpk,
      const float* __restrict__ biasAll, void* __restrict__ Cout, int Mtotal) {
    extern __shared__ __align__(128) char smc[];
    const int NCH = K / KCH;
    const int NSTRIPE = N / NT;

    int e = GROUPED ? blockIdx.z : 0;
    int rowOff = GROUPED ? g_off[e] : 0;
    int cnt = GROUPED ? g_cnt[e] : Mtotal;
    int mTile = GROUPED ? blockIdx.y : blockIdx.x;
    int nTile = GROUPED ? blockIdx.x : blockIdx.y;
    int rowBlock = mTile * MT;
    if (rowBlock >= cnt) return;
    int colBlock = nTile * NT;
    int gmTile = (rowOff >> 7) + mTile;

    const __half* Ablk = Apk + (size_t)gmTile * NCH * ABLK_H;
    const __half* Bblk = Bpk + (size_t)((GROUPED ? e * NSTRIPE : 0) + nTile) * NCH * BBLK_H;
    const float* bias = biasAll + (GROUPED ? (size_t)e * N : (size_t)0);

    int tid = threadIdx.x;
    int wid = tid >> 5, lane = tid & 31;
    int wm = wid >> 3, wn = wid & 7;
    int wmOff = wm * 64, wnOff = wn * 32;
    int g = lane >> 2, tg = lane & 3;
    int b3 = lane >> 3, r8 = lane & 7;
    int aRow = (b3 & 1) * 8 + r8;
    int aKu  = b3 >> 1;
    int bK   = (b3 & 1) * 8 + r8;
    int bNu  = (b3 >> 1) + (wnOff >> 3);

    uint32_t smb = smem_u32(smc);
    uint32_t mb0 = smb + MBOFF;

    if (tid == 0) {
#pragma unroll
        for (int s = 0; s < 4; s++) MBAR_INIT(mb0 + s * 8, 1);
    }
    __syncthreads();

    auto issue = [&](int c) {
        int s = c & 3;
        uint32_t stg = smb + (uint32_t)s * STAGE_BYTES;
        uint32_t mb = mb0 + s * 8;
        MBAR_EXPECT_TX(mb, STAGE_BYTES);
        bulk_ld(stg, Ablk + (size_t)c * ABLK_H, ABLK_B, mb);
        bulk_ld(stg + ABLK_B, Bblk + (size_t)c * BBLK_H, BBLK_B, mb);
    };

    if (tid == 0) {
        issue(0);
        if (NCH > 1) issue(1);
        if (NCH > 2) issue(2);
    }

    float acc[4][4][4];
#pragma unroll
    for (int i = 0; i < 4; i++)
#pragma unroll
        for (int j = 0; j < 4; j++)
#pragma unroll
            for (int q = 0; q < 4; q++) acc[i][j][q] = 0.f;

    for (int c = 0; c < NCH; c++) {
        int s = c & 3;
        if (tid == 0 && c + 3 < NCH) issue(c + 3);
        MBAR_WAIT(mb0 + s * 8, (c >> 2) & 1);

        uint32_t sbase = smb + (uint32_t)s * STAGE_BYTES;
#pragma unroll
        for (int ks = 0; ks < 2; ks++) {
            uint32_t af[4][4];
            uint32_t bf[4][2];
#pragma unroll
            for (int mb = 0; mb < 4; mb++) {
                uint32_t addr = sbase +
                    (uint32_t)((wmOff + mb * 16 + aRow) * 5 + ks * 2 + aKu) * 16;
                ldsm4(af[mb], addr);
            }
#pragma unroll
            for (int p = 0; p < 2; p++) {
                uint32_t addr = sbase + ABLK_B +
                    (uint32_t)((ks * 16 + bK) * 33 + bNu + p * 2) * 16;
                uint32_t rr[4];
                ldsm4t(rr, addr);
                bf[2 * p][0] = rr[0]; bf[2 * p][1] = rr[1];
                bf[2 * p + 1][0] = rr[2]; bf[2 * p + 1][1] = rr[3];
            }
#pragma unroll
            for (int mb = 0; mb < 4; mb++)
#pragma unroll
                for (int nb = 0; nb < 4; nb++)
                    mma_f16(acc[mb][nb], af[mb], bf[nb]);
        }
        __syncthreads();
    }

    // epilogue
#pragma unroll
    for (int nb = 0; nb < 4; nb++) {
        int col = colBlock + wnOff + nb * 8 + tg * 2;
        float2 bv = *(const float2*)(bias + col);
#pragma unroll
        for (int mb = 0; mb < 4; mb++) {
            int mr = wmOff + mb * 16 + g;
#pragma unroll
            for (int h = 0; h < 2; h++) {
                int rr2 = mr + h * 8;
                if (rowBlock + rr2 < cnt) {
                    float ox = acc[mb][nb][2 * h]     + bv.x;
                    float oy = acc[mb][nb][2 * h + 1] + bv.y;
                    if (RELU) { ox = fmaxf(ox, 0.f); oy = fmaxf(oy, 0.f); }
                    if (OUT == 1) {
                        int R = rowOff + rowBlock + rr2;
                        __half* dst = (__half*)Cout +
                            (size_t)((R >> 7) * (N / 32) + (col >> 5)) * ABLK_H +
                            (R & 127) * 40 + (col & 31);
                        *(__half2*)dst = __floats2half2_rn(ox, oy);
                    } else {
                        size_t ro = (size_t)(rowOff + rowBlock + rr2) * N + col;
                        *(float2*)((float*)Cout + ro) = make_float2(ox, oy);
                    }
                }
            }
        }
    }
}

// ---------------- launch ----------------------------------------------------
extern "C" void kernel_launch(void* const* d_in, const int* in_sizes, int n_in,
                              void* d_out, int out_size) {
    const int*   x     = (const int*)  d_in[0];
    const float* embed = (const float*)d_in[1];
    const float* Wg    = (const float*)d_in[2];
    const float* bg    = (const float*)d_in[3];
    const float* W1    = (const float*)d_in[4];
    const float* b1    = (const float*)d_in[5];
    const float* W2    = (const float*)d_in[6];
    const float* b2    = (const float*)d_in[7];
    const float* gamma = (const float*)d_in[8];
    const float* beta  = (const float*)d_in[9];
    const float* Wh    = (const float*)d_in[10];
    const float* bh    = (const float*)d_in[11];
    float* out = (float*)d_out;

    __half *p_hpk, *p_apk, *p_xpk, *p_Whp, *p_W1p, *p_W2p;
    float *p_y;
    cudaGetSymbolAddress((void**)&p_hpk, g_hpk);
    cudaGetSymbolAddress((void**)&p_apk, g_apk);
    cudaGetSymbolAddress((void**)&p_xpk, g_xpk);
    cudaGetSymbolAddress((void**)&p_Whp, g_Whp);
    cudaGetSymbolAddress((void**)&p_W1p, g_W1p);
    cudaGetSymbolAddress((void**)&p_W2p, g_W2p);
    cudaGetSymbolAddress((void**)&p_y,   g_y);

    cudaFuncSetAttribute((const void*)bgemm<DMODEL, HIDDEN, true, true, 1>,
                         cudaFuncAttributeMaxDynamicSharedMemorySize, SMEM_SZ);
    cudaFuncSetAttribute((const void*)bgemm<HIDDEN, DMODEL, true, false, 0>,
                         cudaFuncAttributeMaxDynamicSharedMemorySize, SMEM_SZ);
    cudaFuncSetAttribute((const void*)bgemm<DMODEL, VOCABSZ, false, false, 0>,
                         cudaFuncAttributeMaxDynamicSharedMemorySize, SMEM_SZ);

    // weights -> packed fp16 blocks + counter reset (one launch)
    {
        int total = WH_UNITS + W1_UNITS + W2_UNITS;
        pack_w_kernel<<<(total + 255) / 256, 256>>>(Wh, W1, W2);
    }

    gate_kernel<<<TOKENS, 256>>>(x, embed, Wg, bg);
    scan_assign_kernel<<<1, 1024>>>();
    pack_h_kernel<<<(NSLOTPAD * 128 + 255) / 256, 256>>>(x, embed);

    // FFN1: per-expert [cnt,1024] x [1024,2048], ReLU, packed-half out (FFN2 A)
    bgemm<DMODEL, HIDDEN, true, true, 1>
        <<<dim3(HIDDEN / NT, 16, NEXP), 512, SMEM_SZ>>>(p_hpk, p_W1p, b1, p_apk, 0);
    // FFN2: per-expert [cnt,2048] x [2048,1024], fp32 out
    bgemm<HIDDEN, DMODEL, true, false, 0>
        <<<dim3(DMODEL / NT, 16, NEXP), 512, SMEM_SZ>>>(p_apk, p_W2p, b2, p_y, 0);

    combine_ln_kernel<<<TOKENS, 256>>>(gamma, beta);

    // Head: [2048,1024] x [1024,32000], fp32 out
    bgemm<DMODEL, VOCABSZ, false, false, 0>
        <<<dim3(TOKENS / MT, VOCABSZ / NT, 1), 512, SMEM_SZ>>>(p_xpk, p_Whp, bh, out, TOKENS);
}

// round 9
// speedup vs baseline: 7.5824x; 1.1416x over previous
#include <cuda_runtime.h>
#include <cuda_fp16.h>
#include <cstdint>
#include <math.h>

#define TOKENS   2048
#define DMODEL   1024
#define HIDDEN   2048
#define NEXP     8
#define VOCABSZ  32000
#define LN_EPS   1e-5f

#define MT 128
#define NT 256
#define KCH 32
#define NSTG 8
// packed block sizes (bytes): A 128 rows x 80B, B 32 rows x 528B
#define ABLK_B   10240
#define BBLK_B   16896
#define ABLK_H   5120
#define BBLK_H   8448
#define STAGE_BYTES (ABLK_B + BBLK_B)        // 27136
#define MBOFF (NSTG * STAGE_BYTES)           // 217088
#define SMEM_SZ (MBOFF + 128)                // full[8] @ +0, empty[8] @ +64

#define NSLOTPAD 5120
#define SLOTTILES 40

// ---------------- scratch (device globals; no allocation allowed) ----------
__device__ float g_w  [TOKENS * 2];
__device__ int   g_eidx[TOKENS * 2];
__device__ int   g_slot[TOKENS * 2];
__device__ int   g_tokOfSlot[NSLOTPAD];
__device__ int   g_cnt[NEXP];
__device__ int   g_off[NEXP + 1];
__device__ float g_y  [NSLOTPAD * DMODEL];
// packed operands (SMEM-image blocks)
__device__ __align__(16) __half g_hpk [SLOTTILES * 32 * ABLK_H];  // FFN1 A
__device__ __align__(16) __half g_apk [SLOTTILES * 64 * ABLK_H];  // FFN2 A
__device__ __align__(16) __half g_xpk [16 * 32 * ABLK_H];         // head A
__device__ __align__(16) __half g_Whp [125 * 32 * BBLK_H];
__device__ __align__(16) __half g_W1p [NEXP * 8 * 32 * BBLK_H];
__device__ __align__(16) __half g_W2p [NEXP * 4 * 64 * BBLK_H];

// ---------------- helpers ----------------------------------------------------
__device__ __forceinline__ uint32_t h2u(__half2 h) {
    return *reinterpret_cast<uint32_t*>(&h);
}
__device__ __forceinline__ uint32_t smem_u32(const void* p) {
    uint32_t a;
    asm("{ .reg .u64 t; cvta.to.shared.u64 t, %1; cvt.u32.u64 %0, t; }"
        : "=r"(a) : "l"(p));
    return a;
}
__device__ __forceinline__ void mma_f16(float c[4], const uint32_t a[4],
                                        const uint32_t b[2]) {
    asm volatile(
        "mma.sync.aligned.m16n8k16.row.col.f32.f16.f16.f32 "
        "{%0,%1,%2,%3}, {%4,%5,%6,%7}, {%8,%9}, {%0,%1,%2,%3};"
        : "+f"(c[0]), "+f"(c[1]), "+f"(c[2]), "+f"(c[3])
        : "r"(a[0]), "r"(a[1]), "r"(a[2]), "r"(a[3]), "r"(b[0]), "r"(b[1]));
}
__device__ __forceinline__ void ldsm4(uint32_t r[4], uint32_t addr) {
    asm volatile("ldmatrix.sync.aligned.m8n8.x4.shared.b16 {%0,%1,%2,%3}, [%4];"
                 : "=r"(r[0]), "=r"(r[1]), "=r"(r[2]), "=r"(r[3]) : "r"(addr));
}
__device__ __forceinline__ void ldsm4t(uint32_t r[4], uint32_t addr) {
    asm volatile("ldmatrix.sync.aligned.m8n8.x4.trans.shared.b16 {%0,%1,%2,%3}, [%4];"
                 : "=r"(r[0]), "=r"(r[1]), "=r"(r[2]), "=r"(r[3]) : "r"(addr));
}
#define MBAR_INIT(a, n) \
    asm volatile("mbarrier.init.shared.b64 [%0], %1;" :: "r"((uint32_t)(a)), "r"((uint32_t)(n)) : "memory")
#define MBAR_EXPECT_TX(a, b) \
    asm volatile("mbarrier.arrive.expect_tx.shared.b64 _, [%0], %1;" :: "r"((uint32_t)(a)), "r"((uint32_t)(b)) : "memory")
#define MBAR_ARRIVE(a) \
    asm volatile("mbarrier.arrive.shared.b64 _, [%0];" :: "r"((uint32_t)(a)) : "memory")
#define MBAR_WAIT(a, par) do { \
    uint32_t _mb = (uint32_t)(a); uint32_t _pa = (uint32_t)(par); uint32_t _dn; \
    asm volatile("{\n\t.reg .pred p;\n\t" \
        "mbarrier.try_wait.parity.acquire.cta.shared::cta.b64 p, [%1], %2;\n\t" \
        "selp.b32 %0, 1, 0, p;\n\t}" : "=r"(_dn) : "r"(_mb), "r"(_pa) : "memory"); \
    if (!_dn) { \
        asm volatile("{\n\t.reg .pred P1;\n\t" \
            "WL_%=:\n\t" \
            "mbarrier.try_wait.parity.acquire.cta.shared::cta.b64 P1, [%0], %1, 0x989680;\n\t" \
            "@P1 bra.uni WD_%=;\n\t" \
            "bra.uni WL_%=;\n\t" \
            "WD_%=:\n\t}" :: "r"(_mb), "r"(_pa) : "memory"); \
    } } while (0)
__device__ __forceinline__ void bulk_ld(uint32_t dst, const void* src,
                                        uint32_t bytes, uint32_t mbar) {
    asm volatile(
        "cp.async.bulk.shared::cluster.global.mbarrier::complete_tx::bytes "
        "[%0], [%1], %2, [%3];"
        :: "r"(dst), "l"(src), "r"(bytes), "r"(mbar) : "memory");
}

// ---------------- weight fp16 convert + pack + counter reset ----------------
#define WH_UNITS (125 * 32 * 32 * 32)
#define W1_UNITS (NEXP * 8 * 32 * 32 * 32)
#define W2_UNITS (NEXP * 4 * 64 * 32 * 32)
__global__ void pack_w_kernel(const float* __restrict__ Wh,
                              const float* __restrict__ W1,
                              const float* __restrict__ W2) {
    if (blockIdx.x == 0 && threadIdx.x < NEXP) g_cnt[threadIdx.x] = 0;
    int idx = blockIdx.x * blockDim.x + threadIdx.x;
    const float* src;
    __half* dst;
    if (idx < WH_UNITS) {
        int u = idx & 31, k = (idx >> 5) & 31, ch = (idx >> 10) & 31, st = idx >> 15;
        src = Wh + (size_t)(ch * 32 + k) * VOCABSZ + st * 256 + u * 8;
        dst = g_Whp + (size_t)(st * 32 + ch) * BBLK_H + k * 264 + u * 8;
    } else if (idx < WH_UNITS + W1_UNITS) {
        int i = idx - WH_UNITS;
        int u = i & 31, k = (i >> 5) & 31, ch = (i >> 10) & 31, st = (i >> 15) & 7, e = i >> 18;
        src = W1 + (size_t)e * DMODEL * HIDDEN + (size_t)(ch * 32 + k) * HIDDEN + st * 256 + u * 8;
        dst = g_W1p + (size_t)((e * 8 + st) * 32 + ch) * BBLK_H + k * 264 + u * 8;
    } else if (idx < WH_UNITS + W1_UNITS + W2_UNITS) {
        int i = idx - WH_UNITS - W1_UNITS;
        int u = i & 31, k = (i >> 5) & 31, ch = (i >> 10) & 63, st = (i >> 16) & 3, e = i >> 18;
        src = W2 + (size_t)e * HIDDEN * DMODEL + (size_t)(ch * 32 + k) * DMODEL + st * 256 + u * 8;
        dst = g_W2p + (size_t)((e * 4 + st) * 64 + ch) * BBLK_H + k * 264 + u * 8;
    } else return;
    float4 v0 = *(const float4*)src;
    float4 v1 = *(const float4*)(src + 4);
    uint4 o;
    o.x = h2u(__floats2half2_rn(v0.x, v0.y));
    o.y = h2u(__floats2half2_rn(v0.z, v0.w));
    o.z = h2u(__floats2half2_rn(v1.x, v1.y));
    o.w = h2u(__floats2half2_rn(v1.z, v1.w));
    *(uint4*)dst = o;
}

// ---------------- gate ----------------------------------------------------
__global__ void gate_kernel(const int* __restrict__ x,
                            const float* __restrict__ embed,
                            const float* __restrict__ Wg,
                            const float* __restrict__ bg) {
    int t   = blockIdx.x;
    int tid = threadIdx.x;
    int row = x[t];
    float4 v = ((const float4*)(embed + (size_t)row * DMODEL))[tid];

    float p[NEXP];
#pragma unroll
    for (int e = 0; e < NEXP; e++) p[e] = 0.f;
    float hv[4] = {v.x, v.y, v.z, v.w};
    int d0 = tid * 4;
#pragma unroll
    for (int j = 0; j < 4; j++) {
        const float* wgr = Wg + (size_t)(d0 + j) * NEXP;
#pragma unroll
        for (int e = 0; e < NEXP; e++) p[e] += hv[j] * wgr[e];
    }
#pragma unroll
    for (int e = 0; e < NEXP; e++)
        for (int o = 16; o > 0; o >>= 1)
            p[e] += __shfl_xor_sync(0xffffffffu, p[e], o);

    __shared__ float red[8][NEXP];
    int warp = tid >> 5, lane = tid & 31;
    if (lane == 0)
#pragma unroll
        for (int e = 0; e < NEXP; e++) red[warp][e] = p[e];
    __syncthreads();

    if (tid == 0) {
        float g[NEXP];
#pragma unroll
        for (int e = 0; e < NEXP; e++) {
            g[e] = bg[e];
#pragma unroll
            for (int w = 0; w < 8; w++) g[e] += red[w][e];
        }
        float mx = g[0];
#pragma unroll
        for (int e = 1; e < NEXP; e++) mx = fmaxf(mx, g[e]);
        float s = 0.f, pr[NEXP];
#pragma unroll
        for (int e = 0; e < NEXP; e++) { pr[e] = expf(g[e] - mx); s += pr[e]; }
        float inv = 1.f / s;
#pragma unroll
        for (int e = 0; e < NEXP; e++) pr[e] *= inv;

        int i0 = 0;
#pragma unroll
        for (int e = 1; e < NEXP; e++) if (pr[e] > pr[i0]) i0 = e;
        int i1 = (i0 == 0) ? 1 : 0;
#pragma unroll
        for (int e = 0; e < NEXP; e++)
            if (e != i0 && pr[e] > pr[i1]) i1 = e;

        g_w[2 * t]     = pr[i0];  g_eidx[2 * t]     = i0;
        g_w[2 * t + 1] = pr[i1];  g_eidx[2 * t + 1] = i1;
        atomicAdd(&g_cnt[i0], 1);
        atomicAdd(&g_cnt[i1], 1);
    }
}

// ---------------- scan (128-aligned) + slot assignment ----------------------
__global__ void scan_assign_kernel() {
    __shared__ int s_off[NEXP + 1];
    __shared__ int s_cur[NEXP];
    int tid = threadIdx.x;
    for (int i = tid; i < NSLOTPAD; i += blockDim.x) g_tokOfSlot[i] = 0;
    if (tid == 0) {
        s_off[0] = 0;
        for (int e = 0; e < NEXP; e++)
            s_off[e + 1] = s_off[e] + ((g_cnt[e] + 127) & ~127);
        for (int e = 0; e <= NEXP; e++) g_off[e] = s_off[e];
    }
    if (tid < NEXP) s_cur[tid] = 0;
    __syncthreads();
    for (int t = tid; t < TOKENS; t += blockDim.x) {
#pragma unroll
        for (int k = 0; k < 2; k++) {
            int e = g_eidx[2 * t + k];
            int pos = atomicAdd(&s_cur[e], 1);
            int slot = s_off[e] + pos;
            g_slot[2 * t + k] = slot;
            g_tokOfSlot[slot] = t;
        }
    }
}

// ---------------- pack FFN1 A: embed rows (slot order) -> padded blocks -----
__global__ void pack_h_kernel(const int* __restrict__ x,
                              const float* __restrict__ embed) {
    int idx = blockIdx.x * blockDim.x + threadIdx.x;   // over NSLOTPAD*128
    if (idx >= NSLOTPAD * 128) return;
    int slot = idx >> 7;
    int u = idx & 127;
    int ch = u >> 2, pos = u & 3;
    int tok = g_tokOfSlot[slot];
    int row = x[tok];
    const float* src = embed + (size_t)row * DMODEL + ch * 32 + pos * 8;
    float4 v0 = *(const float4*)src;
    float4 v1 = *(const float4*)(src + 4);
    uint4 o;
    o.x = h2u(__floats2half2_rn(v0.x, v0.y));
    o.y = h2u(__floats2half2_rn(v0.z, v0.w));
    o.z = h2u(__floats2half2_rn(v1.x, v1.y));
    o.w = h2u(__floats2half2_rn(v1.z, v1.w));
    __half* dst = g_hpk + (size_t)((slot >> 7) * 32 + ch) * ABLK_H + (slot & 127) * 40 + pos * 8;
    *(uint4*)dst = o;
}

// ---------------- combine + LN -> packed head A ------------------------------
__global__ void combine_ln_kernel(const float* __restrict__ gamma,
                                  const float* __restrict__ beta) {
    int t = blockIdx.x, tid = threadIdx.x;
    int s0 = g_slot[2 * t], s1 = g_slot[2 * t + 1];
    float w0 = g_w[2 * t], w1 = g_w[2 * t + 1];

    float4 a = ((const float4*)(g_y + (size_t)s0 * DMODEL))[tid];
    float4 b = ((const float4*)(g_y + (size_t)s1 * DMODEL))[tid];
    float4 c;
    c.x = w0 * a.x + w1 * b.x;  c.y = w0 * a.y + w1 * b.y;
    c.z = w0 * a.z + w1 * b.z;  c.w = w0 * a.w + w1 * b.w;

    float sum = c.x + c.y + c.z + c.w;
    float ssq = c.x*c.x + c.y*c.y + c.z*c.z + c.w*c.w;
    for (int o = 16; o > 0; o >>= 1) {
        sum += __shfl_xor_sync(0xffffffffu, sum, o);
        ssq += __shfl_xor_sync(0xffffffffu, ssq, o);
    }
    __shared__ float rs[8], rq[8];
    __shared__ float s_mu, s_rstd;
    int warp = tid >> 5, lane = tid & 31;
    if (lane == 0) { rs[warp] = sum; rq[warp] = ssq; }
    __syncthreads();
    if (tid == 0) {
        float S = 0.f, Q = 0.f;
#pragma unroll
        for (int w = 0; w < 8; w++) { S += rs[w]; Q += rq[w]; }
        float mu = S / (float)DMODEL;
        float var = Q / (float)DMODEL - mu * mu;
        s_mu = mu;
        s_rstd = rsqrtf(var + LN_EPS);
    }
    __syncthreads();
    float mu = s_mu, rstd = s_rstd;
    float4 g4 = ((const float4*)gamma)[tid];
    float4 b4 = ((const float4*)beta)[tid];
    uint2 o;
    o.x = h2u(__floats2half2_rn((c.x - mu) * rstd * g4.x + b4.x,
                                (c.y - mu) * rstd * g4.y + b4.y));
    o.y = h2u(__floats2half2_rn((c.z - mu) * rstd * g4.z + b4.z,
                                (c.w - mu) * rstd * g4.w + b4.w));
    int d0 = tid * 4;
    int ch = d0 >> 5, c2 = d0 & 31;
    __half* dst = g_xpk + (size_t)((t >> 7) * 32 + ch) * ABLK_H + (t & 127) * 40 + c2;
    *(uint2*)dst = o;
}

// ---------------- fp16 GEMM: TMA + full/empty mbar pipeline, no CTA sync ----
// OUT: 0 = fp32 plain rows, 1 = half packed blocks (for next GEMM's A)
template <int K, int N, bool GROUPED, bool RELU, int OUT>
__global__ void __launch_bounds__(512, 1)
bgemm(const __half* __restrict__ Apk, const __half* __restrict__ Bpk,
      const float* __restrict__ biasAll, void* __restrict__ Cout, int Mtotal) {
    extern __shared__ __align__(128) char smc[];
    const int NCH = K / KCH;
    const int NSTRIPE = N / NT;

    int e = GROUPED ? blockIdx.z : 0;
    int rowOff = GROUPED ? g_off[e] : 0;
    int cnt = GROUPED ? g_cnt[e] : Mtotal;
    int mTile = GROUPED ? blockIdx.y : blockIdx.x;
    int nTile = GROUPED ? blockIdx.x : blockIdx.y;
    int rowBlock = mTile * MT;
    if (rowBlock >= cnt) return;
    int colBlock = nTile * NT;
    int gmTile = (rowOff >> 7) + mTile;

    const __half* Ablk = Apk + (size_t)gmTile * NCH * ABLK_H;
    const __half* Bblk = Bpk + (size_t)((GROUPED ? e * NSTRIPE : 0) + nTile) * NCH * BBLK_H;
    const float* bias = biasAll + (GROUPED ? (size_t)e * N : (size_t)0);

    int tid = threadIdx.x;
    int wid = tid >> 5, lane = tid & 31;
    int wm = wid >> 3, wn = wid & 7;
    int wmOff = wm * 64, wnOff = wn * 32;
    int g = lane >> 2, tg = lane & 3;
    int b3 = lane >> 3, r8 = lane & 7;
    int aRow = (b3 & 1) * 8 + r8;
    int aKu  = b3 >> 1;
    int bK   = (b3 & 1) * 8 + r8;
    int bNu  = (b3 >> 1) + (wnOff >> 3);

    uint32_t smb = smem_u32(smc);
    uint32_t mbF = smb + MBOFF;        // full[8]
    uint32_t mbE = smb + MBOFF + 64;   // empty[8]

    if (tid == 0) {
#pragma unroll
        for (int s = 0; s < NSTG; s++) {
            MBAR_INIT(mbF + s * 8, 1);
            MBAR_INIT(mbE + s * 8, 16);
        }
    }
    __syncthreads();

    auto issue = [&](int c) {
        int s = c & (NSTG - 1);
        uint32_t stg = smb + (uint32_t)s * STAGE_BYTES;
        uint32_t mb = mbF + s * 8;
        MBAR_EXPECT_TX(mb, STAGE_BYTES);
        bulk_ld(stg, Ablk + (size_t)c * ABLK_H, ABLK_B, mb);
        bulk_ld(stg + ABLK_B, Bblk + (size_t)c * BBLK_H, BBLK_B, mb);
    };

    if (tid == 0) {
#pragma unroll
        for (int c0 = 0; c0 < NSTG; c0++) issue(c0);   // NCH >= NSTG always
    }

    float acc[4][4][4];
#pragma unroll
    for (int i = 0; i < 4; i++)
#pragma unroll
        for (int j = 0; j < 4; j++)
#pragma unroll
            for (int q = 0; q < 4; q++) acc[i][j][q] = 0.f;

    for (int c = 0; c < NCH; c++) {
        int s = c & (NSTG - 1);
        int par = (c >> 3) & 1;
        MBAR_WAIT(mbF + s * 8, par);

        uint32_t sbase = smb + (uint32_t)s * STAGE_BYTES;
        uint32_t af[2][4][4];
        uint32_t bf[2][4][2];
#pragma unroll
        for (int ks = 0; ks < 2; ks++) {
#pragma unroll
            for (int mb = 0; mb < 4; mb++) {
                uint32_t addr = sbase +
                    (uint32_t)((wmOff + mb * 16 + aRow) * 5 + ks * 2 + aKu) * 16;
                ldsm4(af[ks][mb], addr);
            }
#pragma unroll
            for (int p = 0; p < 2; p++) {
                uint32_t addr = sbase + ABLK_B +
                    (uint32_t)((ks * 16 + bK) * 33 + bNu + p * 2) * 16;
                uint32_t rr[4];
                ldsm4t(rr, addr);
                bf[ks][2 * p][0] = rr[0]; bf[ks][2 * p][1] = rr[1];
                bf[ks][2 * p + 1][0] = rr[2]; bf[ks][2 * p + 1][1] = rr[3];
            }
        }
        // all fragment reads of this stage are in registers -> release stage
        __syncwarp();
        if (lane == 0) MBAR_ARRIVE(mbE + s * 8);
        // producer refills this stage once all 16 warps have released it
        if (tid == 0 && c + NSTG < NCH) {
            MBAR_WAIT(mbE + s * 8, par);
            issue(c + NSTG);
        }
#pragma unroll
        for (int ks = 0; ks < 2; ks++)
#pragma unroll
            for (int mb = 0; mb < 4; mb++)
#pragma unroll
                for (int nb = 0; nb < 4; nb++)
                    mma_f16(acc[ks & 0 ? 0 : mb][nb], af[ks][mb], bf[ks][nb]);
    }

    // epilogue
#pragma unroll
    for (int nb = 0; nb < 4; nb++) {
        int col = colBlock + wnOff + nb * 8 + tg * 2;
        float2 bv = *(const float2*)(bias + col);
#pragma unroll
        for (int mb = 0; mb < 4; mb++) {
            int mr = wmOff + mb * 16 + g;
#pragma unroll
            for (int h = 0; h < 2; h++) {
                int rr2 = mr + h * 8;
                if (rowBlock + rr2 < cnt) {
                    float ox = acc[mb][nb][2 * h]     + bv.x;
                    float oy = acc[mb][nb][2 * h + 1] + bv.y;
                    if (RELU) { ox = fmaxf(ox, 0.f); oy = fmaxf(oy, 0.f); }
                    if (OUT == 1) {
                        int R = rowOff + rowBlock + rr2;
                        __half* dst = (__half*)Cout +
                            (size_t)((R >> 7) * (N / 32) + (col >> 5)) * ABLK_H +
                            (R & 127) * 40 + (col & 31);
                        *(__half2*)dst = __floats2half2_rn(ox, oy);
                    } else {
                        size_t ro = (size_t)(rowOff + rowBlock + rr2) * N + col;
                        *(float2*)((float*)Cout + ro) = make_float2(ox, oy);
                    }
                }
            }
        }
    }
}

// ---------------- launch ----------------------------------------------------
extern "C" void kernel_launch(void* const* d_in, const int* in_sizes, int n_in,
                              void* d_out, int out_size) {
    const int*   x     = (const int*)  d_in[0];
    const float* embed = (const float*)d_in[1];
    const float* Wg    = (const float*)d_in[2];
    const float* bg    = (const float*)d_in[3];
    const float* W1    = (const float*)d_in[4];
    const float* b1    = (const float*)d_in[5];
    const float* W2    = (const float*)d_in[6];
    const float* b2    = (const float*)d_in[7];
    const float* gamma = (const float*)d_in[8];
    const float* beta  = (const float*)d_in[9];
    const float* Wh    = (const float*)d_in[10];
    const float* bh    = (const float*)d_in[11];
    float* out = (float*)d_out;

    __half *p_hpk, *p_apk, *p_xpk, *p_Whp, *p_W1p, *p_W2p;
    float *p_y;
    cudaGetSymbolAddress((void**)&p_hpk, g_hpk);
    cudaGetSymbolAddress((void**)&p_apk, g_apk);
    cudaGetSymbolAddress((void**)&p_xpk, g_xpk);
    cudaGetSymbolAddress((void**)&p_Whp, g_Whp);
    cudaGetSymbolAddress((void**)&p_W1p, g_W1p);
    cudaGetSymbolAddress((void**)&p_W2p, g_W2p);
    cudaGetSymbolAddress((void**)&p_y,   g_y);

    cudaFuncSetAttribute((const void*)bgemm<DMODEL, HIDDEN, true, true, 1>,
                         cudaFuncAttributeMaxDynamicSharedMemorySize, SMEM_SZ);
    cudaFuncSetAttribute((const void*)bgemm<HIDDEN, DMODEL, true, false, 0>,
                         cudaFuncAttributeMaxDynamicSharedMemorySize, SMEM_SZ);
    cudaFuncSetAttribute((const void*)bgemm<DMODEL, VOCABSZ, false, false, 0>,
                         cudaFuncAttributeMaxDynamicSharedMemorySize, SMEM_SZ);

    // weights -> packed fp16 blocks + counter reset (one launch)
    {
        int total = WH_UNITS + W1_UNITS + W2_UNITS;
        pack_w_kernel<<<(total + 255) / 256, 256>>>(Wh, W1, W2);
    }

    gate_kernel<<<TOKENS, 256>>>(x, embed, Wg, bg);
    scan_assign_kernel<<<1, 1024>>>();
    pack_h_kernel<<<(NSLOTPAD * 128 + 255) / 256, 256>>>(x, embed);

    // FFN1: per-expert [cnt,1024] x [1024,2048], ReLU, packed-half out (FFN2 A)
    bgemm<DMODEL, HIDDEN, true, true, 1>
        <<<dim3(HIDDEN / NT, 16, NEXP), 512, SMEM_SZ>>>(p_hpk, p_W1p, b1, p_apk, 0);
    // FFN2: per-expert [cnt,2048] x [2048,1024], fp32 out
    bgemm<HIDDEN, DMODEL, true, false, 0>
        <<<dim3(DMODEL / NT, 16, NEXP), 512, SMEM_SZ>>>(p_apk, p_W2p, b2, p_y, 0);

    combine_ln_kernel<<<TOKENS, 256>>>(gamma, beta);

    // Head: [2048,1024] x [1024,32000], fp32 out
    bgemm<DMODEL, VOCABSZ, false, false, 0>
        <<<dim3(TOKENS / MT, VOCABSZ / NT, 1), 512, SMEM_SZ>>>(p_xpk, p_Whp, bh, out, TOKENS);
}

// round 10
// speedup vs baseline: 7.8671x; 1.0375x over previous
#include <cuda_runtime.h>
#include <cuda_fp16.h>
#include <cstdint>
#include <math.h>

#define TOKENS   2048
#define DMODEL   1024
#define HIDDEN   2048
#define NEXP     8
#define VOCABSZ  32000
#define LN_EPS   1e-5f

#define MT 128
#define NT 256
#define KCH 32
#define NSTG 4
// packed block sizes (bytes): A 128 rows x 80B, B 32 rows x 528B
#define ABLK_B   10240
#define BBLK_B   16896
#define ABLK_H   5120
#define BBLK_H   8448
#define STG2 (2 * (ABLK_B + BBLK_B))         // 54272 (two K-chunks per stage)
#define MBOFF (NSTG * STG2)                  // 217088
#define SMEM_SZ (MBOFF + 128)

#define NSLOTPAD 5120
#define SLOTTILES 40

// ---------------- scratch (device globals; no allocation allowed) ----------
__device__ float g_w  [TOKENS * 2];
__device__ int   g_eidx[TOKENS * 2];
__device__ int   g_slot[TOKENS * 2];
__device__ int   g_tokOfSlot[NSLOTPAD];
__device__ int   g_cnt[NEXP];
__device__ int   g_off[NEXP + 1];
__device__ float g_y  [NSLOTPAD * DMODEL];
// packed operands (SMEM-image blocks)
__device__ __align__(16) __half g_hpk [SLOTTILES * 32 * ABLK_H];  // FFN1 A
__device__ __align__(16) __half g_apk [SLOTTILES * 64 * ABLK_H];  // FFN2 A
__device__ __align__(16) __half g_xpk [16 * 32 * ABLK_H];         // head A
__device__ __align__(16) __half g_Whp [125 * 32 * BBLK_H];
__device__ __align__(16) __half g_W1p [NEXP * 8 * 32 * BBLK_H];
__device__ __align__(16) __half g_W2p [NEXP * 4 * 64 * BBLK_H];

// ---------------- helpers ----------------------------------------------------
__device__ __forceinline__ uint32_t h2u(__half2 h) {
    return *reinterpret_cast<uint32_t*>(&h);
}
__device__ __forceinline__ uint32_t smem_u32(const void* p) {
    uint32_t a;
    asm("{ .reg .u64 t; cvta.to.shared.u64 t, %1; cvt.u32.u64 %0, t; }"
        : "=r"(a) : "l"(p));
    return a;
}
__device__ __forceinline__ void mma_f16(float c[4], const uint32_t a[4],
                                        const uint32_t b[2]) {
    asm volatile(
        "mma.sync.aligned.m16n8k16.row.col.f32.f16.f16.f32 "
        "{%0,%1,%2,%3}, {%4,%5,%6,%7}, {%8,%9}, {%0,%1,%2,%3};"
        : "+f"(c[0]), "+f"(c[1]), "+f"(c[2]), "+f"(c[3])
        : "r"(a[0]), "r"(a[1]), "r"(a[2]), "r"(a[3]), "r"(b[0]), "r"(b[1]));
}
__device__ __forceinline__ void ldsm4(uint32_t r[4], uint32_t addr) {
    asm volatile("ldmatrix.sync.aligned.m8n8.x4.shared.b16 {%0,%1,%2,%3}, [%4];"
                 : "=r"(r[0]), "=r"(r[1]), "=r"(r[2]), "=r"(r[3]) : "r"(addr));
}
__device__ __forceinline__ void ldsm4t(uint32_t r[4], uint32_t addr) {
    asm volatile("ldmatrix.sync.aligned.m8n8.x4.trans.shared.b16 {%0,%1,%2,%3}, [%4];"
                 : "=r"(r[0]), "=r"(r[1]), "=r"(r[2]), "=r"(r[3]) : "r"(addr));
}
#define MBAR_INIT(a, n) \
    asm volatile("mbarrier.init.shared.b64 [%0], %1;" :: "r"((uint32_t)(a)), "r"((uint32_t)(n)) : "memory")
#define MBAR_EXPECT_TX(a, b) \
    asm volatile("mbarrier.arrive.expect_tx.shared.b64 _, [%0], %1;" :: "r"((uint32_t)(a)), "r"((uint32_t)(b)) : "memory")
#define MBAR_ARRIVE(a) \
    asm volatile("mbarrier.arrive.shared.b64 _, [%0];" :: "r"((uint32_t)(a)) : "memory")
#define MBAR_WAIT(a, par) do { \
    uint32_t _mb = (uint32_t)(a); uint32_t _pa = (uint32_t)(par); uint32_t _dn; \
    asm volatile("{\n\t.reg .pred p;\n\t" \
        "mbarrier.try_wait.parity.acquire.cta.shared::cta.b64 p, [%1], %2;\n\t" \
        "selp.b32 %0, 1, 0, p;\n\t}" : "=r"(_dn) : "r"(_mb), "r"(_pa) : "memory"); \
    if (!_dn) { \
        asm volatile("{\n\t.reg .pred P1;\n\t" \
            "WL_%=:\n\t" \
            "mbarrier.try_wait.parity.acquire.cta.shared::cta.b64 P1, [%0], %1, 0x989680;\n\t" \
            "@P1 bra.uni WD_%=;\n\t" \
            "bra.uni WL_%=;\n\t" \
            "WD_%=:\n\t}" :: "r"(_mb), "r"(_pa) : "memory"); \
    } } while (0)
__device__ __forceinline__ void bulk_ld(uint32_t dst, const void* src,
                                        uint32_t bytes, uint32_t mbar) {
    asm volatile(
        "cp.async.bulk.shared::cluster.global.mbarrier::complete_tx::bytes "
        "[%0], [%1], %2, [%3];"
        :: "r"(dst), "l"(src), "r"(bytes), "r"(mbar) : "memory");
}

// ---------------- weight fp16 convert + pack + counter reset ----------------
#define WH_UNITS (125 * 32 * 32 * 32)
#define W1_UNITS (NEXP * 8 * 32 * 32 * 32)
#define W2_UNITS (NEXP * 4 * 64 * 32 * 32)
__global__ void pack_w_kernel(const float* __restrict__ Wh,
                              const float* __restrict__ W1,
                              const float* __restrict__ W2) {
    if (blockIdx.x == 0 && threadIdx.x < NEXP) g_cnt[threadIdx.x] = 0;
    int idx = blockIdx.x * blockDim.x + threadIdx.x;
    const float* src;
    __half* dst;
    if (idx < WH_UNITS) {
        int u = idx & 31, k = (idx >> 5) & 31, ch = (idx >> 10) & 31, st = idx >> 15;
        src = Wh + (size_t)(ch * 32 + k) * VOCABSZ + st * 256 + u * 8;
        dst = g_Whp + (size_t)(st * 32 + ch) * BBLK_H + k * 264 + u * 8;
    } else if (idx < WH_UNITS + W1_UNITS) {
        int i = idx - WH_UNITS;
        int u = i & 31, k = (i >> 5) & 31, ch = (i >> 10) & 31, st = (i >> 15) & 7, e = i >> 18;
        src = W1 + (size_t)e * DMODEL * HIDDEN + (size_t)(ch * 32 + k) * HIDDEN + st * 256 + u * 8;
        dst = g_W1p + (size_t)((e * 8 + st) * 32 + ch) * BBLK_H + k * 264 + u * 8;
    } else if (idx < WH_UNITS + W1_UNITS + W2_UNITS) {
        int i = idx - WH_UNITS - W1_UNITS;
        int u = i & 31, k = (i >> 5) & 31, ch = (i >> 10) & 63, st = (i >> 16) & 3, e = i >> 18;
        src = W2 + (size_t)e * HIDDEN * DMODEL + (size_t)(ch * 32 + k) * DMODEL + st * 256 + u * 8;
        dst = g_W2p + (size_t)((e * 4 + st) * 64 + ch) * BBLK_H + k * 264 + u * 8;
    } else return;
    float4 v0 = *(const float4*)src;
    float4 v1 = *(const float4*)(src + 4);
    uint4 o;
    o.x = h2u(__floats2half2_rn(v0.x, v0.y));
    o.y = h2u(__floats2half2_rn(v0.z, v0.w));
    o.z = h2u(__floats2half2_rn(v1.x, v1.y));
    o.w = h2u(__floats2half2_rn(v1.z, v1.w));
    *(uint4*)dst = o;
}

// ---------------- gate ----------------------------------------------------
__global__ void gate_kernel(const int* __restrict__ x,
                            const float* __restrict__ embed,
                            const float* __restrict__ Wg,
                            const float* __restrict__ bg) {
    int t   = blockIdx.x;
    int tid = threadIdx.x;
    int row = x[t];
    float4 v = ((const float4*)(embed + (size_t)row * DMODEL))[tid];

    float p[NEXP];
#pragma unroll
    for (int e = 0; e < NEXP; e++) p[e] = 0.f;
    float hv[4] = {v.x, v.y, v.z, v.w};
    int d0 = tid * 4;
#pragma unroll
    for (int j = 0; j < 4; j++) {
        const float* wgr = Wg + (size_t)(d0 + j) * NEXP;
#pragma unroll
        for (int e = 0; e < NEXP; e++) p[e] += hv[j] * wgr[e];
    }
#pragma unroll
    for (int e = 0; e < NEXP; e++)
        for (int o = 16; o > 0; o >>= 1)
            p[e] += __shfl_xor_sync(0xffffffffu, p[e], o);

    __shared__ float red[8][NEXP];
    int warp = tid >> 5, lane = tid & 31;
    if (lane == 0)
#pragma unroll
        for (int e = 0; e < NEXP; e++) red[warp][e] = p[e];
    __syncthreads();

    if (tid == 0) {
        float g[NEXP];
#pragma unroll
        for (int e = 0; e < NEXP; e++) {
            g[e] = bg[e];
#pragma unroll
            for (int w = 0; w < 8; w++) g[e] += red[w][e];
        }
        float mx = g[0];
#pragma unroll
        for (int e = 1; e < NEXP; e++) mx = fmaxf(mx, g[e]);
        float s = 0.f, pr[NEXP];
#pragma unroll
        for (int e = 0; e < NEXP; e++) { pr[e] = expf(g[e] - mx); s += pr[e]; }
        float inv = 1.f / s;
#pragma unroll
        for (int e = 0; e < NEXP; e++) pr[e] *= inv;

        int i0 = 0;
#pragma unroll
        for (int e = 1; e < NEXP; e++) if (pr[e] > pr[i0]) i0 = e;
        int i1 = (i0 == 0) ? 1 : 0;
#pragma unroll
        for (int e = 0; e < NEXP; e++)
            if (e != i0 && pr[e] > pr[i1]) i1 = e;

        g_w[2 * t]     = pr[i0];  g_eidx[2 * t]     = i0;
        g_w[2 * t + 1] = pr[i1];  g_eidx[2 * t + 1] = i1;
        atomicAdd(&g_cnt[i0], 1);
        atomicAdd(&g_cnt[i1], 1);
    }
}

// ---------------- scan (128-aligned) + slot assignment ----------------------
__global__ void scan_assign_kernel() {
    __shared__ int s_off[NEXP + 1];
    __shared__ int s_cur[NEXP];
    int tid = threadIdx.x;
    for (int i = tid; i < NSLOTPAD; i += blockDim.x) g_tokOfSlot[i] = 0;
    if (tid == 0) {
        s_off[0] = 0;
        for (int e = 0; e < NEXP; e++)
            s_off[e + 1] = s_off[e] + ((g_cnt[e] + 127) & ~127);
        for (int e = 0; e <= NEXP; e++) g_off[e] = s_off[e];
    }
    if (tid < NEXP) s_cur[tid] = 0;
    __syncthreads();
    for (int t = tid; t < TOKENS; t += blockDim.x) {
#pragma unroll
        for (int k = 0; k < 2; k++) {
            int e = g_eidx[2 * t + k];
            int pos = atomicAdd(&s_cur[e], 1);
            int slot = s_off[e] + pos;
            g_slot[2 * t + k] = slot;
            g_tokOfSlot[slot] = t;
        }
    }
}

// ---------------- pack FFN1 A: embed rows (slot order) -> padded blocks -----
__global__ void pack_h_kernel(const int* __restrict__ x,
                              const float* __restrict__ embed) {
    int idx = blockIdx.x * blockDim.x + threadIdx.x;   // over NSLOTPAD*128
    if (idx >= NSLOTPAD * 128) return;
    int slot = idx >> 7;
    int u = idx & 127;
    int ch = u >> 2, pos = u & 3;
    int tok = g_tokOfSlot[slot];
    int row = x[tok];
    const float* src = embed + (size_t)row * DMODEL + ch * 32 + pos * 8;
    float4 v0 = *(const float4*)src;
    float4 v1 = *(const float4*)(src + 4);
    uint4 o;
    o.x = h2u(__floats2half2_rn(v0.x, v0.y));
    o.y = h2u(__floats2half2_rn(v0.z, v0.w));
    o.z = h2u(__floats2half2_rn(v1.x, v1.y));
    o.w = h2u(__floats2half2_rn(v1.z, v1.w));
    __half* dst = g_hpk + (size_t)((slot >> 7) * 32 + ch) * ABLK_H + (slot & 127) * 40 + pos * 8;
    *(uint4*)dst = o;
}

// ---------------- combine + LN -> packed head A ------------------------------
__global__ void combine_ln_kernel(const float* __restrict__ gamma,
                                  const float* __restrict__ beta) {
    int t = blockIdx.x, tid = threadIdx.x;
    int s0 = g_slot[2 * t], s1 = g_slot[2 * t + 1];
    float w0 = g_w[2 * t], w1 = g_w[2 * t + 1];

    float4 a = ((const float4*)(g_y + (size_t)s0 * DMODEL))[tid];
    float4 b = ((const float4*)(g_y + (size_t)s1 * DMODEL))[tid];
    float4 c;
    c.x = w0 * a.x + w1 * b.x;  c.y = w0 * a.y + w1 * b.y;
    c.z = w0 * a.z + w1 * b.z;  c.w = w0 * a.w + w1 * b.w;

    float sum = c.x + c.y + c.z + c.w;
    float ssq = c.x*c.x + c.y*c.y + c.z*c.z + c.w*c.w;
    for (int o = 16; o > 0; o >>= 1) {
        sum += __shfl_xor_sync(0xffffffffu, sum, o);
        ssq += __shfl_xor_sync(0xffffffffu, ssq, o);
    }
    __shared__ float rs[8], rq[8];
    __shared__ float s_mu, s_rstd;
    int warp = tid >> 5, lane = tid & 31;
    if (lane == 0) { rs[warp] = sum; rq[warp] = ssq; }
    __syncthreads();
    if (tid == 0) {
        float S = 0.f, Q = 0.f;
#pragma unroll
        for (int w = 0; w < 8; w++) { S += rs[w]; Q += rq[w]; }
        float mu = S / (float)DMODEL;
        float var = Q / (float)DMODEL - mu * mu;
        s_mu = mu;
        s_rstd = rsqrtf(var + LN_EPS);
    }
    __syncthreads();
    float mu = s_mu, rstd = s_rstd;
    float4 g4 = ((const float4*)gamma)[tid];
    float4 b4 = ((const float4*)beta)[tid];
    uint2 o;
    o.x = h2u(__floats2half2_rn((c.x - mu) * rstd * g4.x + b4.x,
                                (c.y - mu) * rstd * g4.y + b4.y));
    o.y = h2u(__floats2half2_rn((c.z - mu) * rstd * g4.z + b4.z,
                                (c.w - mu) * rstd * g4.w + b4.w));
    int d0 = tid * 4;
    int ch = d0 >> 5, c2 = d0 & 31;
    __half* dst = g_xpk + (size_t)((t >> 7) * 32 + ch) * ABLK_H + (t & 127) * 40 + c2;
    *(uint2*)dst = o;
}

// ---------------- fp16 GEMM: TMA, 64-deep K stages, sub-chunk pipelining ----
// OUT: 0 = fp32 plain rows, 1 = half packed blocks (for next GEMM's A)
template <int K, int N, bool GROUPED, bool RELU, int OUT>
__global__ void __launch_bounds__(512, 1)
bgemm(const __half* __restrict__ Apk, const __half* __restrict__ Bpk,
      const float* __restrict__ biasAll, void* __restrict__ Cout, int Mtotal) {
    extern __shared__ __align__(128) char smc[];
    const int NCH = K / KCH;          // 32-k chunks in gmem layout
    const int NC2 = K / (2 * KCH);    // 64-k stages
    const int NSTRIPE = N / NT;

    int e = GROUPED ? blockIdx.z : 0;
    int rowOff = GROUPED ? g_off[e] : 0;
    int cnt = GROUPED ? g_cnt[e] : Mtotal;
    int mTile = GROUPED ? blockIdx.y : blockIdx.x;
    int nTile = GROUPED ? blockIdx.x : blockIdx.y;
    int rowBlock = mTile * MT;
    if (rowBlock >= cnt) return;
    int colBlock = nTile * NT;
    int gmTile = (rowOff >> 7) + mTile;

    const __half* Ablk = Apk + (size_t)gmTile * NCH * ABLK_H;
    const __half* Bblk = Bpk + (size_t)((GROUPED ? e * NSTRIPE : 0) + nTile) * NCH * BBLK_H;
    const float* bias = biasAll + (GROUPED ? (size_t)e * N : (size_t)0);

    int tid = threadIdx.x;
    int wid = tid >> 5, lane = tid & 31;
    int wm = wid >> 3, wn = wid & 7;
    int wmOff = wm * 64, wnOff = wn * 32;
    int g = lane >> 2, tg = lane & 3;
    int b3 = lane >> 3, r8 = lane & 7;
    int aRow = (b3 & 1) * 8 + r8;
    int aKu  = b3 >> 1;
    int bK   = (b3 & 1) * 8 + r8;
    int bNu  = (b3 >> 1) + (wnOff >> 3);

    uint32_t smb = smem_u32(smc);
    uint32_t mbF = smb + MBOFF;        // full[4]
    uint32_t mbE = smb + MBOFF + 64;   // empty[4]

    if (tid == 0) {
#pragma unroll
        for (int s = 0; s < NSTG; s++) {
            MBAR_INIT(mbF + s * 8, 1);
            MBAR_INIT(mbE + s * 8, 16);
        }
    }
    __syncthreads();

    auto issue = [&](int c2) {
        int s = c2 & (NSTG - 1);
        uint32_t stg = smb + (uint32_t)s * STG2;
        uint32_t mb = mbF + s * 8;
        MBAR_EXPECT_TX(mb, STG2);
        bulk_ld(stg, Ablk + (size_t)(2 * c2) * ABLK_H, 2 * ABLK_B, mb);
        bulk_ld(stg + 2 * ABLK_B, Bblk + (size_t)(2 * c2) * BBLK_H, 2 * BBLK_B, mb);
    };

    if (tid == 0) {
#pragma unroll
        for (int c0 = 0; c0 < NSTG; c0++) issue(c0);   // NC2 >= NSTG always
    }

    float acc[4][4][4];
#pragma unroll
    for (int i = 0; i < 4; i++)
#pragma unroll
        for (int j = 0; j < 4; j++)
#pragma unroll
            for (int q = 0; q < 4; q++) acc[i][j][q] = 0.f;

    uint32_t af[2][4][4];
    uint32_t bf[2][4][2];

    for (int c2 = 0; c2 < NC2; c2++) {
        int s = c2 & (NSTG - 1);
        int par = (c2 >> 2) & 1;
        MBAR_WAIT(mbF + s * 8, par);

        uint32_t sbase = smb + (uint32_t)s * STG2;
        // ---- load fragments sub0 ----
        {
            uint32_t ab = sbase;
            uint32_t bb = sbase + 2 * ABLK_B;
#pragma unroll
            for (int ks = 0; ks < 2; ks++) {
#pragma unroll
                for (int mb = 0; mb < 4; mb++)
                    ldsm4(af[0][mb], ab + (uint32_t)((wmOff + mb * 16 + aRow) * 5 + ks * 2 + aKu) * 16);
#pragma unroll
                for (int p = 0; p < 2; p++) {
                    uint32_t rr[4];
                    ldsm4t(rr, bb + (uint32_t)((ks * 16 + bK) * 33 + bNu + p * 2) * 16);
                    bf[0][2 * p][0] = rr[0]; bf[0][2 * p][1] = rr[1];
                    bf[0][2 * p + 1][0] = rr[2]; bf[0][2 * p + 1][1] = rr[3];
                }
                if (ks == 0) {
                    // hold ks0 frags in [0], mma immediately to shorten burst
#pragma unroll
                    for (int mb = 0; mb < 4; mb++)
#pragma unroll
                        for (int nb = 0; nb < 4; nb++)
                            mma_f16(acc[mb][nb], af[0][mb], bf[0][nb]);
                } else {
#pragma unroll
                    for (int mb = 0; mb < 4; mb++)
#pragma unroll
                        for (int nb = 0; nb < 4; nb++)
                            mma_f16(acc[mb][nb], af[0][mb], bf[0][nb]);
                }
            }
        }
        // ---- load fragments sub1 (overlaps sub0 MMA drain) ----
        {
            uint32_t ab = sbase + ABLK_B;
            uint32_t bb = sbase + 2 * ABLK_B + BBLK_B;
#pragma unroll
            for (int ks = 0; ks < 2; ks++) {
#pragma unroll
                for (int mb = 0; mb < 4; mb++)
                    ldsm4(af[1][mb], ab + (uint32_t)((wmOff + mb * 16 + aRow) * 5 + ks * 2 + aKu) * 16);
#pragma unroll
                for (int p = 0; p < 2; p++) {
                    uint32_t rr[4];
                    ldsm4t(rr, bb + (uint32_t)((ks * 16 + bK) * 33 + bNu + p * 2) * 16);
                    bf[1][2 * p][0] = rr[0]; bf[1][2 * p][1] = rr[1];
                    bf[1][2 * p + 1][0] = rr[2]; bf[1][2 * p + 1][1] = rr[3];
                }
                if (ks == 1) {
                    // stage fully read into regs -> release for refill
                    __syncwarp();
                    if (lane == 0) MBAR_ARRIVE(mbE + s * 8);
                }
#pragma unroll
                for (int mb = 0; mb < 4; mb++)
#pragma unroll
                    for (int nb = 0; nb < 4; nb++)
                        mma_f16(acc[mb][nb], af[1][mb], bf[1][nb]);
            }
        }
        // producer refills stage once all 16 warps released it
        if (tid == 0 && c2 + NSTG < NC2) {
            MBAR_WAIT(mbE + s * 8, par);
            issue(c2 + NSTG);
        }
    }

    // epilogue
#pragma unroll
    for (int nb = 0; nb < 4; nb++) {
        int col = colBlock + wnOff + nb * 8 + tg * 2;
        float2 bv = *(const float2*)(bias + col);
#pragma unroll
        for (int mb = 0; mb < 4; mb++) {
            int mr = wmOff + mb * 16 + g;
#pragma unroll
            for (int h = 0; h < 2; h++) {
                int rr2 = mr + h * 8;
                if (rowBlock + rr2 < cnt) {
                    float ox = acc[mb][nb][2 * h]     + bv.x;
                    float oy = acc[mb][nb][2 * h + 1] + bv.y;
                    if (RELU) { ox = fmaxf(ox, 0.f); oy = fmaxf(oy, 0.f); }
                    if (OUT == 1) {
                        int R = rowOff + rowBlock + rr2;
                        __half* dst = (__half*)Cout +
                            (size_t)((R >> 7) * (N / 32) + (col >> 5)) * ABLK_H +
                            (R & 127) * 40 + (col & 31);
                        *(__half2*)dst = __floats2half2_rn(ox, oy);
                    } else {
                        size_t ro = (size_t)(rowOff + rowBlock + rr2) * N + col;
                        *(float2*)((float*)Cout + ro) = make_float2(ox, oy);
                    }
                }
            }
        }
    }
}

// ---------------- launch ----------------------------------------------------
extern "C" void kernel_launch(void* const* d_in, const int* in_sizes, int n_in,
                              void* d_out, int out_size) {
    const int*   x     = (const int*)  d_in[0];
    const float* embed = (const float*)d_in[1];
    const float* Wg    = (const float*)d_in[2];
    const float* bg    = (const float*)d_in[3];
    const float* W1    = (const float*)d_in[4];
    const float* b1    = (const float*)d_in[5];
    const float* W2    = (const float*)d_in[6];
    const float* b2    = (const float*)d_in[7];
    const float* gamma = (const float*)d_in[8];
    const float* beta  = (const float*)d_in[9];
    const float* Wh    = (const float*)d_in[10];
    const float* bh    = (const float*)d_in[11];
    float* out = (float*)d_out;

    __half *p_hpk, *p_apk, *p_xpk, *p_Whp, *p_W1p, *p_W2p;
    float *p_y;
    cudaGetSymbolAddress((void**)&p_hpk, g_hpk);
    cudaGetSymbolAddress((void**)&p_apk, g_apk);
    cudaGetSymbolAddress((void**)&p_xpk, g_xpk);
    cudaGetSymbolAddress((void**)&p_Whp, g_Whp);
    cudaGetSymbolAddress((void**)&p_W1p, g_W1p);
    cudaGetSymbolAddress((void**)&p_W2p, g_W2p);
    cudaGetSymbolAddress((void**)&p_y,   g_y);

    cudaFuncSetAttribute((const void*)bgemm<DMODEL, HIDDEN, true, true, 1>,
                         cudaFuncAttributeMaxDynamicSharedMemorySize, SMEM_SZ);
    cudaFuncSetAttribute((const void*)bgemm<HIDDEN, DMODEL, true, false, 0>,
                         cudaFuncAttributeMaxDynamicSharedMemorySize, SMEM_SZ);
    cudaFuncSetAttribute((const void*)bgemm<DMODEL, VOCABSZ, false, false, 0>,
                         cudaFuncAttributeMaxDynamicSharedMemorySize, SMEM_SZ);

    // weights -> packed fp16 blocks + counter reset (one launch)
    {
        int total = WH_UNITS + W1_UNITS + W2_UNITS;
        pack_w_kernel<<<(total + 255) / 256, 256>>>(Wh, W1, W2);
    }

    gate_kernel<<<TOKENS, 256>>>(x, embed, Wg, bg);
    scan_assign_kernel<<<1, 1024>>>();
    pack_h_kernel<<<(NSLOTPAD * 128 + 255) / 256, 256>>>(x, embed);

    // FFN1: per-expert [cnt,1024] x [1024,2048], ReLU, packed-half out (FFN2 A)
    bgemm<DMODEL, HIDDEN, true, true, 1>
        <<<dim3(HIDDEN / NT, 16, NEXP), 512, SMEM_SZ>>>(p_hpk, p_W1p, b1, p_apk, 0);
    // FFN2: per-expert [cnt,2048] x [2048,1024], fp32 out
    bgemm<HIDDEN, DMODEL, true, false, 0>
        <<<dim3(DMODEL / NT, 16, NEXP), 512, SMEM_SZ>>>(p_apk, p_W2p, b2, p_y, 0);

    combine_ln_kernel<<<TOKENS, 256>>>(gamma, beta);

    // Head: [2048,1024] x [1024,32000], fp32 out
    bgemm<DMODEL, VOCABSZ, false, false, 0>
        <<<dim3(TOKENS / MT, VOCABSZ / NT, 1), 512, SMEM_SZ>>>(p_xpk, p_Whp, bh, out, TOKENS);
}

// round 11
// speedup vs baseline: 8.1106x; 1.0310x over previous
#include <cuda_runtime.h>
#include <cuda_fp16.h>
#include <cstdint>
#include <math.h>

#define TOKENS   2048
#define DMODEL   1024
#define HIDDEN   2048
#define NEXP     8
#define VOCABSZ  32000
#define LN_EPS   1e-5f

#define MT 128
#define NT 256
#define KCH 32
#define NSTG 4
// packed block sizes (bytes): A 128 rows x 80B, B 32 rows x 528B
#define ABLK_B   10240
#define BBLK_B   16896
#define ABLK_H   5120
#define BBLK_H   8448
#define STG2 (2 * (ABLK_B + BBLK_B))         // 54272 (two K-chunks per stage)
#define MBOFF (NSTG * STG2)                  // 217088
#define SMEM_SZ (MBOFF + 128)

#define NSLOTPAD 5120
#define SLOTTILES 40
#define NSM 152

// ---------------- scratch (device globals; no allocation allowed) ----------
__device__ float g_w  [TOKENS * 2];
__device__ int   g_eidx[TOKENS * 2];
__device__ int   g_slot[TOKENS * 2];
__device__ int   g_tokOfSlot[NSLOTPAD];
__device__ int   g_cnt[NEXP];
__device__ int   g_off[NEXP + 1];
__device__ float g_y  [NSLOTPAD * DMODEL];
// packed operands (SMEM-image blocks)
__device__ __align__(16) __half g_hpk [SLOTTILES * 32 * ABLK_H];  // FFN1 A
__device__ __align__(16) __half g_apk [SLOTTILES * 64 * ABLK_H];  // FFN2 A
__device__ __align__(16) __half g_xpk [16 * 32 * ABLK_H];         // head A
__device__ __align__(16) __half g_Whp [125 * 32 * BBLK_H];
__device__ __align__(16) __half g_W1p [NEXP * 8 * 32 * BBLK_H];
__device__ __align__(16) __half g_W2p [NEXP * 4 * 64 * BBLK_H];

// ---------------- helpers ----------------------------------------------------
__device__ __forceinline__ uint32_t h2u(__half2 h) {
    return *reinterpret_cast<uint32_t*>(&h);
}
__device__ __forceinline__ uint32_t smem_u32(const void* p) {
    uint32_t a;
    asm("{ .reg .u64 t; cvta.to.shared.u64 t, %1; cvt.u32.u64 %0, t; }"
        : "=r"(a) : "l"(p));
    return a;
}
__device__ __forceinline__ void mma_f16(float c[4], const uint32_t a[4],
                                        const uint32_t b[2]) {
    asm volatile(
        "mma.sync.aligned.m16n8k16.row.col.f32.f16.f16.f32 "
        "{%0,%1,%2,%3}, {%4,%5,%6,%7}, {%8,%9}, {%0,%1,%2,%3};"
        : "+f"(c[0]), "+f"(c[1]), "+f"(c[2]), "+f"(c[3])
        : "r"(a[0]), "r"(a[1]), "r"(a[2]), "r"(a[3]), "r"(b[0]), "r"(b[1]));
}
__device__ __forceinline__ void ldsm4(uint32_t r[4], uint32_t addr) {
    asm volatile("ldmatrix.sync.aligned.m8n8.x4.shared.b16 {%0,%1,%2,%3}, [%4];"
                 : "=r"(r[0]), "=r"(r[1]), "=r"(r[2]), "=r"(r[3]) : "r"(addr));
}
__device__ __forceinline__ void ldsm4t(uint32_t r[4], uint32_t addr) {
    asm volatile("ldmatrix.sync.aligned.m8n8.x4.trans.shared.b16 {%0,%1,%2,%3}, [%4];"
                 : "=r"(r[0]), "=r"(r[1]), "=r"(r[2]), "=r"(r[3]) : "r"(addr));
}
#define MBAR_INIT(a, n) \
    asm volatile("mbarrier.init.shared.b64 [%0], %1;" :: "r"((uint32_t)(a)), "r"((uint32_t)(n)) : "memory")
#define MBAR_EXPECT_TX(a, b) \
    asm volatile("mbarrier.arrive.expect_tx.shared.b64 _, [%0], %1;" :: "r"((uint32_t)(a)), "r"((uint32_t)(b)) : "memory")
#define MBAR_ARRIVE(a) \
    asm volatile("mbarrier.arrive.shared.b64 _, [%0];" :: "r"((uint32_t)(a)) : "memory")
#define MBAR_WAIT(a, par) do { \
    uint32_t _mb = (uint32_t)(a); uint32_t _pa = (uint32_t)(par); uint32_t _dn; \
    asm volatile("{\n\t.reg .pred p;\n\t" \
        "mbarrier.try_wait.parity.acquire.cta.shared::cta.b64 p, [%1], %2;\n\t" \
        "selp.b32 %0, 1, 0, p;\n\t}" : "=r"(_dn) : "r"(_mb), "r"(_pa) : "memory"); \
    if (!_dn) { \
        asm volatile("{\n\t.reg .pred P1;\n\t" \
            "WL_%=:\n\t" \
            "mbarrier.try_wait.parity.acquire.cta.shared::cta.b64 P1, [%0], %1, 0x989680;\n\t" \
            "@P1 bra.uni WD_%=;\n\t" \
            "bra.uni WL_%=;\n\t" \
            "WD_%=:\n\t}" :: "r"(_mb), "r"(_pa) : "memory"); \
    } } while (0)
__device__ __forceinline__ void bulk_ld(uint32_t dst, const void* src,
                                        uint32_t bytes, uint32_t mbar) {
    asm volatile(
        "cp.async.bulk.shared::cluster.global.mbarrier::complete_tx::bytes "
        "[%0], [%1], %2, [%3];"
        :: "r"(dst), "l"(src), "r"(bytes), "r"(mbar) : "memory");
}

// ---------------- fused: weight pack + gate ----------------------------------
#define WH_UNITS (125 * 32 * 32 * 32)
#define W1_UNITS (NEXP * 8 * 32 * 32 * 32)
#define W2_UNITS (NEXP * 4 * 64 * 32 * 32)
#define W_TOTAL  (WH_UNITS + W1_UNITS + W2_UNITS)
#define WBLOCKS  ((W_TOTAL + 255) / 256)

__global__ void prep_kernel(const int* __restrict__ x,
                            const float* __restrict__ embed,
                            const float* __restrict__ Wg,
                            const float* __restrict__ bg,
                            const float* __restrict__ Wh,
                            const float* __restrict__ W1,
                            const float* __restrict__ W2) {
    if (blockIdx.x < WBLOCKS) {
        // ---- weight pack ----
        int idx = blockIdx.x * blockDim.x + threadIdx.x;
        const float* src;
        __half* dst;
        if (idx < WH_UNITS) {
            int u = idx & 31, k = (idx >> 5) & 31, ch = (idx >> 10) & 31, st = idx >> 15;
            src = Wh + (size_t)(ch * 32 + k) * VOCABSZ + st * 256 + u * 8;
            dst = g_Whp + (size_t)(st * 32 + ch) * BBLK_H + k * 264 + u * 8;
        } else if (idx < WH_UNITS + W1_UNITS) {
            int i = idx - WH_UNITS;
            int u = i & 31, k = (i >> 5) & 31, ch = (i >> 10) & 31, st = (i >> 15) & 7, e = i >> 18;
            src = W1 + (size_t)e * DMODEL * HIDDEN + (size_t)(ch * 32 + k) * HIDDEN + st * 256 + u * 8;
            dst = g_W1p + (size_t)((e * 8 + st) * 32 + ch) * BBLK_H + k * 264 + u * 8;
        } else if (idx < W_TOTAL) {
            int i = idx - WH_UNITS - W1_UNITS;
            int u = i & 31, k = (i >> 5) & 31, ch = (i >> 10) & 63, st = (i >> 16) & 3, e = i >> 18;
            src = W2 + (size_t)e * HIDDEN * DMODEL + (size_t)(ch * 32 + k) * DMODEL + st * 256 + u * 8;
            dst = g_W2p + (size_t)((e * 4 + st) * 64 + ch) * BBLK_H + k * 264 + u * 8;
        } else return;
        float4 v0 = *(const float4*)src;
        float4 v1 = *(const float4*)(src + 4);
        uint4 o;
        o.x = h2u(__floats2half2_rn(v0.x, v0.y));
        o.y = h2u(__floats2half2_rn(v0.z, v0.w));
        o.z = h2u(__floats2half2_rn(v1.x, v1.y));
        o.w = h2u(__floats2half2_rn(v1.z, v1.w));
        *(uint4*)dst = o;
        return;
    }
    // ---- gate (one block per token) ----
    int t   = blockIdx.x - WBLOCKS;
    int tid = threadIdx.x;
    int row = x[t];
    float4 v = ((const float4*)(embed + (size_t)row * DMODEL))[tid];

    float p[NEXP];
#pragma unroll
    for (int e = 0; e < NEXP; e++) p[e] = 0.f;
    float hv[4] = {v.x, v.y, v.z, v.w};
    int d0 = tid * 4;
#pragma unroll
    for (int j = 0; j < 4; j++) {
        const float* wgr = Wg + (size_t)(d0 + j) * NEXP;
#pragma unroll
        for (int e = 0; e < NEXP; e++) p[e] += hv[j] * wgr[e];
    }
#pragma unroll
    for (int e = 0; e < NEXP; e++)
        for (int o = 16; o > 0; o >>= 1)
            p[e] += __shfl_xor_sync(0xffffffffu, p[e], o);

    __shared__ float red[8][NEXP];
    int warp = tid >> 5, lane = tid & 31;
    if (lane == 0)
#pragma unroll
        for (int e = 0; e < NEXP; e++) red[warp][e] = p[e];
    __syncthreads();

    if (tid == 0) {
        float g[NEXP];
#pragma unroll
        for (int e = 0; e < NEXP; e++) {
            g[e] = bg[e];
#pragma unroll
            for (int w = 0; w < 8; w++) g[e] += red[w][e];
        }
        float mx = g[0];
#pragma unroll
        for (int e = 1; e < NEXP; e++) mx = fmaxf(mx, g[e]);
        float s = 0.f, pr[NEXP];
#pragma unroll
        for (int e = 0; e < NEXP; e++) { pr[e] = expf(g[e] - mx); s += pr[e]; }
        float inv = 1.f / s;
#pragma unroll
        for (int e = 0; e < NEXP; e++) pr[e] *= inv;

        int i0 = 0;
#pragma unroll
        for (int e = 1; e < NEXP; e++) if (pr[e] > pr[i0]) i0 = e;
        int i1 = (i0 == 0) ? 1 : 0;
#pragma unroll
        for (int e = 0; e < NEXP; e++)
            if (e != i0 && pr[e] > pr[i1]) i1 = e;

        g_w[2 * t]     = pr[i0];  g_eidx[2 * t]     = i0;
        g_w[2 * t + 1] = pr[i1];  g_eidx[2 * t + 1] = i1;
    }
}

// ---------------- count + scan (128-aligned) + slot assignment ---------------
__global__ void scan_assign_kernel() {
    __shared__ int s_cnt[NEXP];
    __shared__ int s_off[NEXP + 1];
    __shared__ int s_cur[NEXP];
    int tid = threadIdx.x;
    for (int i = tid; i < NSLOTPAD; i += blockDim.x) g_tokOfSlot[i] = 0;
    if (tid < NEXP) { s_cnt[tid] = 0; s_cur[tid] = 0; }
    __syncthreads();
    for (int i = tid; i < TOKENS * 2; i += blockDim.x)
        atomicAdd(&s_cnt[g_eidx[i]], 1);
    __syncthreads();
    if (tid == 0) {
        s_off[0] = 0;
        for (int e = 0; e < NEXP; e++) {
            s_off[e + 1] = s_off[e] + ((s_cnt[e] + 127) & ~127);
            g_cnt[e] = s_cnt[e];
        }
        for (int e = 0; e <= NEXP; e++) g_off[e] = s_off[e];
    }
    __syncthreads();
    for (int t = tid; t < TOKENS; t += blockDim.x) {
#pragma unroll
        for (int k = 0; k < 2; k++) {
            int e = g_eidx[2 * t + k];
            int pos = atomicAdd(&s_cur[e], 1);
            int slot = s_off[e] + pos;
            g_slot[2 * t + k] = slot;
            g_tokOfSlot[slot] = t;
        }
    }
}

// ---------------- pack FFN1 A: embed rows (slot order) -> padded blocks -----
__global__ void pack_h_kernel(const int* __restrict__ x,
                              const float* __restrict__ embed) {
    int idx = blockIdx.x * blockDim.x + threadIdx.x;
    if (idx >= NSLOTPAD * 128) return;
    int slot = idx >> 7;
    int u = idx & 127;
    int ch = u >> 2, pos = u & 3;
    int tok = g_tokOfSlot[slot];
    int row = x[tok];
    const float* src = embed + (size_t)row * DMODEL + ch * 32 + pos * 8;
    float4 v0 = *(const float4*)src;
    float4 v1 = *(const float4*)(src + 4);
    uint4 o;
    o.x = h2u(__floats2half2_rn(v0.x, v0.y));
    o.y = h2u(__floats2half2_rn(v0.z, v0.w));
    o.z = h2u(__floats2half2_rn(v1.x, v1.y));
    o.w = h2u(__floats2half2_rn(v1.z, v1.w));
    __half* dst = g_hpk + (size_t)((slot >> 7) * 32 + ch) * ABLK_H + (slot & 127) * 40 + pos * 8;
    *(uint4*)dst = o;
}

// ---------------- combine + LN -> packed head A ------------------------------
__global__ void combine_ln_kernel(const float* __restrict__ gamma,
                                  const float* __restrict__ beta) {
    int t = blockIdx.x, tid = threadIdx.x;
    int s0 = g_slot[2 * t], s1 = g_slot[2 * t + 1];
    float w0 = g_w[2 * t], w1 = g_w[2 * t + 1];

    float4 a = ((const float4*)(g_y + (size_t)s0 * DMODEL))[tid];
    float4 b = ((const float4*)(g_y + (size_t)s1 * DMODEL))[tid];
    float4 c;
    c.x = w0 * a.x + w1 * b.x;  c.y = w0 * a.y + w1 * b.y;
    c.z = w0 * a.z + w1 * b.z;  c.w = w0 * a.w + w1 * b.w;

    float sum = c.x + c.y + c.z + c.w;
    float ssq = c.x*c.x + c.y*c.y + c.z*c.z + c.w*c.w;
    for (int o = 16; o > 0; o >>= 1) {
        sum += __shfl_xor_sync(0xffffffffu, sum, o);
        ssq += __shfl_xor_sync(0xffffffffu, ssq, o);
    }
    __shared__ float rs[8], rq[8];
    __shared__ float s_mu, s_rstd;
    int warp = tid >> 5, lane = tid & 31;
    if (lane == 0) { rs[warp] = sum; rq[warp] = ssq; }
    __syncthreads();
    if (tid == 0) {
        float S = 0.f, Q = 0.f;
#pragma unroll
        for (int w = 0; w < 8; w++) { S += rs[w]; Q += rq[w]; }
        float mu = S / (float)DMODEL;
        float var = Q / (float)DMODEL - mu * mu;
        s_mu = mu;
        s_rstd = rsqrtf(var + LN_EPS);
    }
    __syncthreads();
    float mu = s_mu, rstd = s_rstd;
    float4 g4 = ((const float4*)gamma)[tid];
    float4 b4 = ((const float4*)beta)[tid];
    uint2 o;
    o.x = h2u(__floats2half2_rn((c.x - mu) * rstd * g4.x + b4.x,
                                (c.y - mu) * rstd * g4.y + b4.y));
    o.y = h2u(__floats2half2_rn((c.z - mu) * rstd * g4.z + b4.z,
                                (c.w - mu) * rstd * g4.w + b4.w));
    int d0 = tid * 4;
    int ch = d0 >> 5, c2 = d0 & 31;
    __half* dst = g_xpk + (size_t)((t >> 7) * 32 + ch) * ABLK_H + (t & 127) * 40 + c2;
    *(uint2*)dst = o;
}

// ---------------- grouped fp16 GEMM (FFN1/FFN2), 64-deep stages --------------
template <int K, int N, bool RELU, int OUT>
__global__ void __launch_bounds__(512, 1)
bgemm(const __half* __restrict__ Apk, const __half* __restrict__ Bpk,
      const float* __restrict__ biasAll, void* __restrict__ Cout) {
    extern __shared__ __align__(128) char smc[];
    const int NCH = K / KCH;
    const int NC2 = K / (2 * KCH);
    const int NSTRIPE = N / NT;

    int e = blockIdx.z;
    int rowOff = g_off[e];
    int cnt = g_cnt[e];
    int mTile = blockIdx.y;
    int nTile = blockIdx.x;
    int rowBlock = mTile * MT;
    if (rowBlock >= cnt) return;
    int colBlock = nTile * NT;
    int gmTile = (rowOff >> 7) + mTile;

    const __half* Ablk = Apk + (size_t)gmTile * NCH * ABLK_H;
    const __half* Bblk = Bpk + (size_t)(e * NSTRIPE + nTile) * NCH * BBLK_H;
    const float* bias = biasAll + (size_t)e * N;

    int tid = threadIdx.x;
    int wid = tid >> 5, lane = tid & 31;
    int wm = wid >> 3, wn = wid & 7;
    int wmOff = wm * 64, wnOff = wn * 32;
    int g = lane >> 2, tg = lane & 3;
    int b3 = lane >> 3, r8 = lane & 7;
    int aRow = (b3 & 1) * 8 + r8;
    int aKu  = b3 >> 1;
    int bK   = (b3 & 1) * 8 + r8;
    int bNu  = (b3 >> 1) + (wnOff >> 3);

    uint32_t smb = smem_u32(smc);
    uint32_t mbF = smb + MBOFF;
    uint32_t mbE = smb + MBOFF + 64;

    if (tid == 0) {
#pragma unroll
        for (int s = 0; s < NSTG; s++) {
            MBAR_INIT(mbF + s * 8, 1);
            MBAR_INIT(mbE + s * 8, 16);
        }
    }
    __syncthreads();

    auto issue = [&](int c2) {
        int s = c2 & (NSTG - 1);
        uint32_t stg = smb + (uint32_t)s * STG2;
        uint32_t mb = mbF + s * 8;
        MBAR_EXPECT_TX(mb, STG2);
        bulk_ld(stg, Ablk + (size_t)(2 * c2) * ABLK_H, 2 * ABLK_B, mb);
        bulk_ld(stg + 2 * ABLK_B, Bblk + (size_t)(2 * c2) * BBLK_H, 2 * BBLK_B, mb);
    };

    if (tid == 0) {
#pragma unroll
        for (int c0 = 0; c0 < NSTG; c0++) issue(c0);
    }

    float acc[4][4][4];
#pragma unroll
    for (int i = 0; i < 4; i++)
#pragma unroll
        for (int j = 0; j < 4; j++)
#pragma unroll
            for (int q = 0; q < 4; q++) acc[i][j][q] = 0.f;

    uint32_t af[2][4][4];
    uint32_t bf[2][4][2];

    for (int c2 = 0; c2 < NC2; c2++) {
        int s = c2 & (NSTG - 1);
        int par = (c2 >> 2) & 1;
        MBAR_WAIT(mbF + s * 8, par);

        uint32_t sbase = smb + (uint32_t)s * STG2;
        {
            uint32_t ab = sbase;
            uint32_t bb = sbase + 2 * ABLK_B;
#pragma unroll
            for (int ks = 0; ks < 2; ks++) {
#pragma unroll
                for (int mb = 0; mb < 4; mb++)
                    ldsm4(af[0][mb], ab + (uint32_t)((wmOff + mb * 16 + aRow) * 5 + ks * 2 + aKu) * 16);
#pragma unroll
                for (int p = 0; p < 2; p++) {
                    uint32_t rr[4];
                    ldsm4t(rr, bb + (uint32_t)((ks * 16 + bK) * 33 + bNu + p * 2) * 16);
                    bf[0][2 * p][0] = rr[0]; bf[0][2 * p][1] = rr[1];
                    bf[0][2 * p + 1][0] = rr[2]; bf[0][2 * p + 1][1] = rr[3];
                }
#pragma unroll
                for (int mb = 0; mb < 4; mb++)
#pragma unroll
                    for (int nb = 0; nb < 4; nb++)
                        mma_f16(acc[mb][nb], af[0][mb], bf[0][nb]);
            }
        }
        {
            uint32_t ab = sbase + ABLK_B;
            uint32_t bb = sbase + 2 * ABLK_B + BBLK_B;
#pragma unroll
            for (int ks = 0; ks < 2; ks++) {
#pragma unroll
                for (int mb = 0; mb < 4; mb++)
                    ldsm4(af[1][mb], ab + (uint32_t)((wmOff + mb * 16 + aRow) * 5 + ks * 2 + aKu) * 16);
#pragma unroll
                for (int p = 0; p < 2; p++) {
                    uint32_t rr[4];
                    ldsm4t(rr, bb + (uint32_t)((ks * 16 + bK) * 33 + bNu + p * 2) * 16);
                    bf[1][2 * p][0] = rr[0]; bf[1][2 * p][1] = rr[1];
                    bf[1][2 * p + 1][0] = rr[2]; bf[1][2 * p + 1][1] = rr[3];
                }
                if (ks == 1) {
                    __syncwarp();
                    if (lane == 0) MBAR_ARRIVE(mbE + s * 8);
                }
#pragma unroll
                for (int mb = 0; mb < 4; mb++)
#pragma unroll
                    for (int nb = 0; nb < 4; nb++)
                        mma_f16(acc[mb][nb], af[1][mb], bf[1][nb]);
            }
        }
        if (tid == 0 && c2 + NSTG < NC2) {
            MBAR_WAIT(mbE + s * 8, par);
            issue(c2 + NSTG);
        }
    }

    // epilogue
#pragma unroll
    for (int nb = 0; nb < 4; nb++) {
        int col = colBlock + wnOff + nb * 8 + tg * 2;
        float2 bv = *(const float2*)(bias + col);
#pragma unroll
        for (int mb = 0; mb < 4; mb++) {
            int mr = wmOff + mb * 16 + g;
#pragma unroll
            for (int h = 0; h < 2; h++) {
                int rr2 = mr + h * 8;
                if (rowBlock + rr2 < cnt) {
                    float ox = acc[mb][nb][2 * h]     + bv.x;
                    float oy = acc[mb][nb][2 * h + 1] + bv.y;
                    if (RELU) { ox = fmaxf(ox, 0.f); oy = fmaxf(oy, 0.f); }
                    if (OUT == 1) {
                        int R = rowOff + rowBlock + rr2;
                        __half* dst = (__half*)Cout +
                            (size_t)((R >> 7) * (N / 32) + (col >> 5)) * ABLK_H +
                            (R & 127) * 40 + (col & 31);
                        *(__half2*)dst = __floats2half2_rn(ox, oy);
                    } else {
                        size_t ro = (size_t)(rowOff + rowBlock + rr2) * N + col;
                        *(float2*)((float*)Cout + ro) = make_float2(ox, oy);
                    }
                }
            }
        }
    }
}

// ---------------- persistent head GEMM: 152 CTAs, continuous pipeline -------
#define H_NCH   (DMODEL / KCH)        // 32
#define H_NC2   (DMODEL / (2 * KCH))  // 16
#define H_TM    16
#define H_TN    125
#define H_NTILES (H_TM * H_TN)        // 2000

__global__ void __launch_bounds__(512, 1)
hgemm_persist(const __half* __restrict__ Apk, const __half* __restrict__ Bpk,
              const float* __restrict__ bias, float* __restrict__ out) {
    extern __shared__ __align__(128) char smc[];
    int bid = blockIdx.x;
    int nCTA = gridDim.x;

    int nMy = (bid < H_NTILES) ? ((H_NTILES - 1 - bid) / nCTA + 1) : 0;
    int totalChunks = nMy * H_NC2;
    if (nMy == 0) return;

    int tid = threadIdx.x;
    int wid = tid >> 5, lane = tid & 31;
    int wm = wid >> 3, wn = wid & 7;
    int wmOff = wm * 64, wnOff = wn * 32;
    int g = lane >> 2, tg = lane & 3;
    int b3 = lane >> 3, r8 = lane & 7;
    int aRow = (b3 & 1) * 8 + r8;
    int aKu  = b3 >> 1;
    int bK   = (b3 & 1) * 8 + r8;
    int bNu  = (b3 >> 1) + (wnOff >> 3);

    uint32_t smb = smem_u32(smc);
    uint32_t mbF = smb + MBOFF;
    uint32_t mbE = smb + MBOFF + 64;

    if (tid == 0) {
#pragma unroll
        for (int s = 0; s < NSTG; s++) {
            MBAR_INIT(mbF + s * 8, 1);
            MBAR_INIT(mbE + s * 8, 16);
        }
    }
    __syncthreads();

    // gc -> (tileSeq, c2); tile = bid + tileSeq*nCTA; tile = n*16 + m
    auto issue = [&](int gc) {
        int s = gc & (NSTG - 1);
        int tileSeq = gc / H_NC2;
        int c2 = gc - tileSeq * H_NC2;
        int tile = bid + tileSeq * nCTA;
        int m = tile & (H_TM - 1);
        int n = tile >> 4;
        const __half* Ab = Apk + ((size_t)m * H_NCH + 2 * c2) * ABLK_H;
        const __half* Bb = Bpk + ((size_t)n * H_NCH + 2 * c2) * BBLK_H;
        uint32_t stg = smb + (uint32_t)s * STG2;
        uint32_t mb = mbF + s * 8;
        MBAR_EXPECT_TX(mb, STG2);
        bulk_ld(stg, Ab, 2 * ABLK_B, mb);
        bulk_ld(stg + 2 * ABLK_B, Bb, 2 * BBLK_B, mb);
    };

    if (tid == 0) {
        int pre = totalChunks < NSTG ? totalChunks : NSTG;
        for (int c0 = 0; c0 < pre; c0++) issue(c0);
    }

    uint32_t af[2][4][4];
    uint32_t bf[2][4][2];
    int gc = 0;

    for (int tile = bid; tile < H_NTILES; tile += nCTA) {
        int m = tile & (H_TM - 1);
        int n = tile >> 4;

        float acc[4][4][4];
#pragma unroll
        for (int i = 0; i < 4; i++)
#pragma unroll
            for (int j = 0; j < 4; j++)
#pragma unroll
                for (int q = 0; q < 4; q++) acc[i][j][q] = 0.f;

        for (int c2 = 0; c2 < H_NC2; c2++, gc++) {
            int s = gc & (NSTG - 1);
            int par = (gc >> 2) & 1;
            MBAR_WAIT(mbF + s * 8, par);

            uint32_t sbase = smb + (uint32_t)s * STG2;
            {
                uint32_t ab = sbase;
                uint32_t bb = sbase + 2 * ABLK_B;
#pragma unroll
                for (int ks = 0; ks < 2; ks++) {
#pragma unroll
                    for (int mb = 0; mb < 4; mb++)
                        ldsm4(af[0][mb], ab + (uint32_t)((wmOff + mb * 16 + aRow) * 5 + ks * 2 + aKu) * 16);
#pragma unroll
                    for (int p = 0; p < 2; p++) {
                        uint32_t rr[4];
                        ldsm4t(rr, bb + (uint32_t)((ks * 16 + bK) * 33 + bNu + p * 2) * 16);
                        bf[0][2 * p][0] = rr[0]; bf[0][2 * p][1] = rr[1];
                        bf[0][2 * p + 1][0] = rr[2]; bf[0][2 * p + 1][1] = rr[3];
                    }
#pragma unroll
                    for (int mb = 0; mb < 4; mb++)
#pragma unroll
                        for (int nb = 0; nb < 4; nb++)
                            mma_f16(acc[mb][nb], af[0][mb], bf[0][nb]);
                }
            }
            {
                uint32_t ab = sbase + ABLK_B;
                uint32_t bb = sbase + 2 * ABLK_B + BBLK_B;
#pragma unroll
                for (int ks = 0; ks < 2; ks++) {
#pragma unroll
                    for (int mb = 0; mb < 4; mb++)
                        ldsm4(af[1][mb], ab + (uint32_t)((wmOff + mb * 16 + aRow) * 5 + ks * 2 + aKu) * 16);
#pragma unroll
                    for (int p = 0; p < 2; p++) {
                        uint32_t rr[4];
                        ldsm4t(rr, bb + (uint32_t)((ks * 16 + bK) * 33 + bNu + p * 2) * 16);
                        bf[1][2 * p][0] = rr[0]; bf[1][2 * p][1] = rr[1];
                        bf[1][2 * p + 1][0] = rr[2]; bf[1][2 * p + 1][1] = rr[3];
                    }
                    if (ks == 1) {
                        __syncwarp();
                        if (lane == 0) MBAR_ARRIVE(mbE + s * 8);
                    }
#pragma unroll
                    for (int mb = 0; mb < 4; mb++)
#pragma unroll
                        for (int nb = 0; nb < 4; nb++)
                            mma_f16(acc[mb][nb], af[1][mb], bf[1][nb]);
                }
            }
            // producer: refill this stage with chunk gc+NSTG (may be next tile)
            if (tid == 0 && gc + NSTG < totalChunks) {
                MBAR_WAIT(mbE + s * 8, par);
                issue(gc + NSTG);
            }
        }

        // epilogue (all head rows valid; M=2048 exact)
        int rowBase = m * MT;
        int colBase = n * NT;
#pragma unroll
        for (int nb = 0; nb < 4; nb++) {
            int col = colBase + wnOff + nb * 8 + tg * 2;
            float2 bv = *(const float2*)(bias + col);
#pragma unroll
            for (int mb = 0; mb < 4; mb++) {
                int mr = rowBase + wmOff + mb * 16 + g;
#pragma unroll
                for (int h = 0; h < 2; h++) {
                    float ox = acc[mb][nb][2 * h]     + bv.x;
                    float oy = acc[mb][nb][2 * h + 1] + bv.y;
                    *(float2*)(out + (size_t)(mr + h * 8) * VOCABSZ + col) =
                        make_float2(ox, oy);
                }
            }
        }
    }
}

// ---------------- launch ----------------------------------------------------
extern "C" void kernel_launch(void* const* d_in, const int* in_sizes, int n_in,
                              void* d_out, int out_size) {
    const int*   x     = (const int*)  d_in[0];
    const float* embed = (const float*)d_in[1];
    const float* Wg    = (const float*)d_in[2];
    const float* bg    = (const float*)d_in[3];
    const float* W1    = (const float*)d_in[4];
    const float* b1    = (const float*)d_in[5];
    const float* W2    = (const float*)d_in[6];
    const float* b2    = (const float*)d_in[7];
    const float* gamma = (const float*)d_in[8];
    const float* beta  = (const float*)d_in[9];
    const float* Wh    = (const float*)d_in[10];
    const float* bh    = (const float*)d_in[11];
    float* out = (float*)d_out;

    __half *p_hpk, *p_apk, *p_xpk, *p_Whp, *p_W1p, *p_W2p;
    float *p_y;
    cudaGetSymbolAddress((void**)&p_hpk, g_hpk);
    cudaGetSymbolAddress((void**)&p_apk, g_apk);
    cudaGetSymbolAddress((void**)&p_xpk, g_xpk);
    cudaGetSymbolAddress((void**)&p_Whp, g_Whp);
    cudaGetSymbolAddress((void**)&p_W1p, g_W1p);
    cudaGetSymbolAddress((void**)&p_W2p, g_W2p);
    cudaGetSymbolAddress((void**)&p_y,   g_y);

    cudaFuncSetAttribute((const void*)bgemm<DMODEL, HIDDEN, true, 1>,
                         cudaFuncAttributeMaxDynamicSharedMemorySize, SMEM_SZ);
    cudaFuncSetAttribute((const void*)bgemm<HIDDEN, DMODEL, false, 0>,
                         cudaFuncAttributeMaxDynamicSharedMemorySize, SMEM_SZ);
    cudaFuncSetAttribute((const void*)hgemm_persist,
                         cudaFuncAttributeMaxDynamicSharedMemorySize, SMEM_SZ);

    // fused: weight pack + gate
    prep_kernel<<<WBLOCKS + TOKENS, 256>>>(x, embed, Wg, bg, Wh, W1, W2);
    scan_assign_kernel<<<1, 1024>>>();
    pack_h_kernel<<<(NSLOTPAD * 128 + 255) / 256, 256>>>(x, embed);

    // FFN1: per-expert [cnt,1024] x [1024,2048], ReLU, packed-half out
    bgemm<DMODEL, HIDDEN, true, 1>
        <<<dim3(HIDDEN / NT, 16, NEXP), 512, SMEM_SZ>>>(p_hpk, p_W1p, b1, p_apk);
    // FFN2: per-expert [cnt,2048] x [2048,1024], fp32 out
    bgemm<HIDDEN, DMODEL, false, 0>
        <<<dim3(DMODEL / NT, 16, NEXP), 512, SMEM_SZ>>>(p_apk, p_W2p, b2, p_y);

    combine_ln_kernel<<<TOKENS, 256>>>(gamma, beta);

    // Head: persistent, 152 CTAs, pipeline flows across tiles
    hgemm_persist<<<NSM, 512, SMEM_SZ>>>(p_xpk, p_Whp, bh, out);
}